// round 12
// baseline (speedup 1.0000x reference)
#include <cuda_runtime.h>
#include <cuda_fp16.h>
#include <math.h>

#define T    8192
#define DM   256
#define DI   512
#define S    16
#define NC   64           // chunks
#define L    128          // T/NC
#define CHB  8            // channels per scan block

typedef __half h16;

// ---------------- scratch (static device memory; no allocs) ----------------
__device__ float g_xz  [T * 1024];
__device__ float g_xc  [T * DI];
__device__ h16   g_in2 [T * DM];         // input fp16, K=256
__device__ h16   g_xc2 [T * DI];         // xc fp16, K=512
__device__ float g_dbl [T * 48];
__device__ h16   g_y22 [T * DI];         // gated y fp16, K=512
__device__ float g_h   [T * DM];
__device__ h16   g_h2  [T * DM];         // h fp16, K=256
__device__ h16   g_ff12[T * DI];         // relu(ff1) fp16, K=512
__device__ h16   g_Win2 [1024 * DM];     // weights fp16
__device__ h16   g_Wx2  [64 * DI];       // padded 48->64 rows
__device__ h16   g_Wc2  [DM * DI];
__device__ h16   g_Wexp2[DI * DM];
__device__ h16   g_Wsq2 [DM * DI];
__device__ float g_P   [NC * DI * S];
__device__ float g_hl  [NC * DI * S];
__device__ float g_hin [NC * DI * S];

__device__ __forceinline__ void ldsm4(unsigned& r0, unsigned& r1,
                                      unsigned& r2, unsigned& r3, unsigned addr) {
    asm volatile("ldmatrix.sync.aligned.m8n8.x4.shared.b16 {%0,%1,%2,%3}, [%4];"
                 : "=r"(r0), "=r"(r1), "=r"(r2), "=r"(r3) : "r"(addr));
}

__device__ __forceinline__ void cp16(unsigned saddr, const void* gaddr) {
    asm volatile("cp.async.ca.shared.global [%0], [%1], 16;"
                 :: "r"(saddr), "l"(gaddr));
}

#define MMA16816(acc, a0, a1, a2, a3, b0, b1)                                   \
    asm volatile(                                                               \
        "mma.sync.aligned.m16n8k16.row.col.f32.f16.f16.f32 "                    \
        "{%0,%1,%2,%3},{%4,%5,%6,%7},{%8,%9},{%0,%1,%2,%3};"                    \
        : "+f"(acc[0]), "+f"(acc[1]), "+f"(acc[2]), "+f"(acc[3])                \
        : "r"(a0), "r"(a1), "r"(a2), "r"(a3), "r"(b0), "r"(b1))

// ---------------- fp16 tensor-core GEMM (64-wide K chunks, 3-stage) ---------
// C[M,N] = A[M,K] * B[N,K]^T (+bias). K multiple of 64.
// MODE 0: fp32 out. MODE 1: relu->fp16 out.
template<int BM, int BN, int WM, int WN, int MODE>
__global__ __launch_bounds__(256, 2)
void gemm_f16(const h16* __restrict__ A, const h16* __restrict__ B,
              void* __restrict__ Cv, int K, int Nld, int Nlog,
              const float* __restrict__ bias) {
    constexpr int MT = BM / WM / 16;
    constexpr int NT = BN / WN / 8;
    constexpr int SAW = 36;                 // words per 64-h16 row (8 h16 pad)
    constexpr int STG = (BM + BN) * SAW;    // words per stage
    extern __shared__ unsigned sm[];        // 3 stages
    const unsigned smemU = (unsigned)__cvta_generic_to_shared(sm);

    const int tid = threadIdx.x;
    const int w = tid >> 5, lane = tid & 31;
    const int g = lane >> 2, t4 = lane & 3;
    const int wm = w % WM, wn = w / WM;
    const int bm = blockIdx.y * BM, bn = blockIdx.x * BN;
    const int m0 = wm * (BM / WM), n0 = wn * (BN / WN);

    const int rA = (lane & 7) + ((lane & 8) ? 8 : 0);
    const int cA = (lane & 16) ? 4 : 0;
    const int rB = (lane & 7) + ((lane & 16) ? 8 : 0);
    const int cB = (lane & 8) ? 4 : 0;
    const unsigned aAddr = smemU + (unsigned)(((m0 + rA) * SAW + cA) * 4);
    const unsigned bAddr = smemU + (unsigned)((BM * SAW + (n0 + rB) * SAW + cB) * 4);

    const int ldr = tid >> 3;
    const int lcw = (tid & 7) * 4;
    const int lce = (tid & 7) * 8;

    float acc[MT][NT][4];
#pragma unroll
    for (int mi = 0; mi < MT; mi++)
#pragma unroll
        for (int ni = 0; ni < NT; ni++)
#pragma unroll
            for (int q = 0; q < 4; q++) acc[mi][ni][q] = 0.f;

    const int nch = K >> 6;

    auto issue = [&](int ch, int st) {
        const unsigned base = smemU + (unsigned)(st * STG * 4);
        const int ke = ch * 64 + lce;
#pragma unroll
        for (int r = ldr; r < BM; r += 32)
            cp16(base + (unsigned)((r * SAW + lcw) * 4),
                 A + (size_t)(bm + r) * K + ke);
#pragma unroll
        for (int r = ldr; r < BN; r += 32)
            cp16(base + (unsigned)((BM * SAW + r * SAW + lcw) * 4),
                 B + (size_t)(bn + r) * K + ke);
        asm volatile("cp.async.commit_group;" ::: "memory");
    };

    issue(0, 0);
    issue(1, 1);

    int st = 0;
    for (int i = 0; i < nch; i++) {
        if (i + 1 < nch)
            asm volatile("cp.async.wait_group 1;" ::: "memory");
        else
            asm volatile("cp.async.wait_group 0;" ::: "memory");
        __syncthreads();
        if (i + 2 < nch) {
            int st2 = st + 2; if (st2 >= 3) st2 -= 3;
            issue(i + 2, st2);
        }
        const unsigned so = (unsigned)(st * STG * 4);
#pragma unroll
        for (int kt = 0; kt < 4; kt++) {
            unsigned af[MT][4];
#pragma unroll
            for (int mi = 0; mi < MT; mi++)
                ldsm4(af[mi][0], af[mi][1], af[mi][2], af[mi][3],
                      aAddr + so + (unsigned)(mi * 16 * SAW * 4 + kt * 32));
            unsigned bfr[NT][2];
#pragma unroll
            for (int p = 0; p < NT / 2; p++) {
                unsigned r0, r1, r2, r3;
                ldsm4(r0, r1, r2, r3,
                      bAddr + so + (unsigned)(p * 16 * SAW * 4 + kt * 32));
                bfr[2 * p][0] = r0; bfr[2 * p][1] = r1;
                bfr[2 * p + 1][0] = r2; bfr[2 * p + 1][1] = r3;
            }
#pragma unroll
            for (int mi = 0; mi < MT; mi++)
#pragma unroll
                for (int ni = 0; ni < NT; ni++)
                    MMA16816(acc[mi][ni], af[mi][0], af[mi][1], af[mi][2], af[mi][3],
                             bfr[ni][0], bfr[ni][1]);
        }
        if (++st >= 3) st = 0;
    }

    // epilogue
#pragma unroll
    for (int mi = 0; mi < MT; mi++) {
        int r0 = bm + m0 + mi * 16 + g;
        int r1 = r0 + 8;
#pragma unroll
        for (int ni = 0; ni < NT; ni++) {
            int c = bn + n0 + ni * 8 + 2 * t4;
            if (c >= Nlog) continue;
            float b0 = bias ? bias[c] : 0.f;
            float b1 = bias ? bias[c + 1] : 0.f;
            float v00 = acc[mi][ni][0] + b0, v01 = acc[mi][ni][1] + b1;
            float v10 = acc[mi][ni][2] + b0, v11 = acc[mi][ni][3] + b1;
            if (MODE == 0) {
                float* C = (float*)Cv;
                *reinterpret_cast<float2*>(C + (size_t)r0 * Nld + c) = make_float2(v00, v01);
                *reinterpret_cast<float2*>(C + (size_t)r1 * Nld + c) = make_float2(v10, v11);
            } else {
                h16* C2 = (h16*)Cv;
                v00 = fmaxf(v00, 0.f); v01 = fmaxf(v01, 0.f);
                v10 = fmaxf(v10, 0.f); v11 = fmaxf(v11, 0.f);
                *reinterpret_cast<__half2*>(C2 + (size_t)r0 * Nld + c) =
                    __halves2half2(__float2half(v00), __float2half(v01));
                *reinterpret_cast<__half2*>(C2 + (size_t)r1 * Nld + c) =
                    __halves2half2(__float2half(v10), __float2half(v11));
            }
        }
    }
}

// ---------------- GEMM with fused LayerNorm epilogue -------------------------
// BM=64, BN=256 (full row). out32 = LN(A@B^T + bias + res) * gam + bet.
__global__ __launch_bounds__(256, 1)
void gemm_ln(const h16* __restrict__ A, const h16* __restrict__ B, int K,
             const float* __restrict__ bias, const float* __restrict__ res,
             const float* __restrict__ gam, const float* __restrict__ bet,
             float* __restrict__ out32, h16* __restrict__ out16) {
    constexpr int BM = 64, BN = 256, WM = 2;
    constexpr int MT = 2, NT = 8;
    constexpr int SAW = 36;
    constexpr int STG = (BM + BN) * SAW;
    extern __shared__ unsigned sm[];
    const unsigned smemU = (unsigned)__cvta_generic_to_shared(sm);

    const int tid = threadIdx.x;
    const int w = tid >> 5, lane = tid & 31;
    const int g = lane >> 2, t4 = lane & 3;
    const int wm = w % WM, wn = w / WM;
    const int bm = blockIdx.x * BM;
    const int m0 = wm * 32, n0 = wn * 64;

    const int rA = (lane & 7) + ((lane & 8) ? 8 : 0);
    const int cA = (lane & 16) ? 4 : 0;
    const int rB = (lane & 7) + ((lane & 16) ? 8 : 0);
    const int cB = (lane & 8) ? 4 : 0;
    const unsigned aAddr = smemU + (unsigned)(((m0 + rA) * SAW + cA) * 4);
    const unsigned bAddr = smemU + (unsigned)((BM * SAW + (n0 + rB) * SAW + cB) * 4);

    const int ldr = tid >> 3;
    const int lcw = (tid & 7) * 4;
    const int lce = (tid & 7) * 8;

    float acc[MT][NT][4];
#pragma unroll
    for (int mi = 0; mi < MT; mi++)
#pragma unroll
        for (int ni = 0; ni < NT; ni++)
#pragma unroll
            for (int q = 0; q < 4; q++) acc[mi][ni][q] = 0.f;

    const int nch = K >> 6;

    auto issue = [&](int ch, int st) {
        const unsigned base = smemU + (unsigned)(st * STG * 4);
        const int ke = ch * 64 + lce;
#pragma unroll
        for (int r = ldr; r < BM; r += 32)
            cp16(base + (unsigned)((r * SAW + lcw) * 4),
                 A + (size_t)(bm + r) * K + ke);
#pragma unroll
        for (int r = ldr; r < BN; r += 32)
            cp16(base + (unsigned)((BM * SAW + r * SAW + lcw) * 4),
                 B + (size_t)r * K + ke);
        asm volatile("cp.async.commit_group;" ::: "memory");
    };

    issue(0, 0);
    issue(1, 1);

    int st = 0;
    for (int i = 0; i < nch; i++) {
        if (i + 1 < nch)
            asm volatile("cp.async.wait_group 1;" ::: "memory");
        else
            asm volatile("cp.async.wait_group 0;" ::: "memory");
        __syncthreads();
        if (i + 2 < nch) {
            int st2 = st + 2; if (st2 >= 3) st2 -= 3;
            issue(i + 2, st2);
        }
        const unsigned so = (unsigned)(st * STG * 4);
#pragma unroll
        for (int kt = 0; kt < 4; kt++) {
            unsigned af[MT][4];
#pragma unroll
            for (int mi = 0; mi < MT; mi++)
                ldsm4(af[mi][0], af[mi][1], af[mi][2], af[mi][3],
                      aAddr + so + (unsigned)(mi * 16 * SAW * 4 + kt * 32));
            unsigned bfr[NT][2];
#pragma unroll
            for (int p = 0; p < NT / 2; p++) {
                unsigned r0, r1, r2, r3;
                ldsm4(r0, r1, r2, r3,
                      bAddr + so + (unsigned)(p * 16 * SAW * 4 + kt * 32));
                bfr[2 * p][0] = r0; bfr[2 * p][1] = r1;
                bfr[2 * p + 1][0] = r2; bfr[2 * p + 1][1] = r3;
            }
#pragma unroll
            for (int mi = 0; mi < MT; mi++)
#pragma unroll
                for (int ni = 0; ni < NT; ni++)
                    MMA16816(acc[mi][ni], af[mi][0], af[mi][1], af[mi][2], af[mi][3],
                             bfr[ni][0], bfr[ni][1]);
        }
        if (++st >= 3) st = 0;
    }

    // --- fused LN epilogue ---
    float s1[MT][2], s2[MT][2];
#pragma unroll
    for (int mi = 0; mi < MT; mi++) {
        int r0 = bm + m0 + mi * 16 + g;
        int r1 = r0 + 8;
        s1[mi][0] = s1[mi][1] = s2[mi][0] = s2[mi][1] = 0.f;
#pragma unroll
        for (int ni = 0; ni < NT; ni++) {
            int c = n0 + ni * 8 + 2 * t4;
            float b0 = bias[c], b1 = bias[c + 1];
            float2 e0 = *reinterpret_cast<const float2*>(res + (size_t)r0 * DM + c);
            float2 e1 = *reinterpret_cast<const float2*>(res + (size_t)r1 * DM + c);
            acc[mi][ni][0] += b0 + e0.x;
            acc[mi][ni][1] += b1 + e0.y;
            acc[mi][ni][2] += b0 + e1.x;
            acc[mi][ni][3] += b1 + e1.y;
            s1[mi][0] += acc[mi][ni][0] + acc[mi][ni][1];
            s2[mi][0] += acc[mi][ni][0] * acc[mi][ni][0] + acc[mi][ni][1] * acc[mi][ni][1];
            s1[mi][1] += acc[mi][ni][2] + acc[mi][ni][3];
            s2[mi][1] += acc[mi][ni][2] * acc[mi][ni][2] + acc[mi][ni][3] * acc[mi][ni][3];
        }
    }
#pragma unroll
    for (int mi = 0; mi < MT; mi++)
#pragma unroll
        for (int q = 0; q < 2; q++) {
            s1[mi][q] += __shfl_xor_sync(0xffffffffu, s1[mi][q], 1);
            s1[mi][q] += __shfl_xor_sync(0xffffffffu, s1[mi][q], 2);
            s2[mi][q] += __shfl_xor_sync(0xffffffffu, s2[mi][q], 1);
            s2[mi][q] += __shfl_xor_sync(0xffffffffu, s2[mi][q], 2);
        }
    float* sred = (float*)sm;
    __syncthreads();
    if (t4 == 0) {
#pragma unroll
        for (int mi = 0; mi < MT; mi++) {
            int lr = m0 + mi * 16 + g;
            sred[(lr) * 8 + wn]           = s1[mi][0];
            sred[(lr) * 8 + 4 + wn]       = s2[mi][0];
            sred[(lr + 8) * 8 + wn]       = s1[mi][1];
            sred[(lr + 8) * 8 + 4 + wn]   = s2[mi][1];
        }
    }
    __syncthreads();
#pragma unroll
    for (int mi = 0; mi < MT; mi++) {
#pragma unroll
        for (int q = 0; q < 2; q++) {
            int lr = m0 + mi * 16 + g + q * 8;
            float t1 = sred[lr * 8 + 0] + sred[lr * 8 + 1] + sred[lr * 8 + 2] + sred[lr * 8 + 3];
            float t2 = sred[lr * 8 + 4] + sred[lr * 8 + 5] + sred[lr * 8 + 6] + sred[lr * 8 + 7];
            float m = t1 * (1.f / DM);
            float var = t2 * (1.f / DM) - m * m;
            float rstd = rsqrtf(var + 1e-5f);
            int row = bm + lr;
#pragma unroll
            for (int ni = 0; ni < NT; ni++) {
                int c = n0 + ni * 8 + 2 * t4;
                float v0 = (acc[mi][ni][q * 2 + 0] - m) * rstd * gam[c] + bet[c];
                float v1 = (acc[mi][ni][q * 2 + 1] - m) * rstd * gam[c + 1] + bet[c + 1];
                *reinterpret_cast<float2*>(out32 + (size_t)row * DM + c) = make_float2(v0, v1);
                if (out16)
                    *reinterpret_cast<__half2*>(out16 + (size_t)row * DM + c) =
                        __halves2half2(__float2half(v0), __float2half(v1));
            }
        }
    }
}

// ---------------- mega-prep: all conversions + Wc + output tail --------------
__global__ void prep_kernel(const float* __restrict__ input,
                            const float* __restrict__ Win,
                            const float* __restrict__ Wx,
                            const float* __restrict__ Wexp,
                            const float* __restrict__ Wsq,
                            const float* __restrict__ Wlin,
                            const float* __restrict__ Wout,
                            float* __restrict__ out_tail) {
    const int N0 = T * DM;              // in2 + out tail
    const int N1 = 1024 * 256;          // Win2
    const int N2 = 64 * 512;            // Wx2 (padded)
    const int N3 = 512 * 256;           // Wexp2
    const int N4 = 256 * 512;           // Wsq2
    const int N5 = 256 * 512;           // Wc2 = Wlin @ Wout
    const int TOT = N0 + N1 + N2 + N3 + N4 + N5;
    for (int idx = blockIdx.x * 256 + threadIdx.x; idx < TOT; idx += gridDim.x * 256) {
        int j = idx;
        if (j < N0) {
            float v = input[j];
            g_in2[j] = __float2half(v);
            if (out_tail) out_tail[j] = v;
            continue;
        }
        j -= N0;
        if (j < N1) { g_Win2[j] = __float2half(Win[j]); continue; }
        j -= N1;
        if (j < N2) {
            int n = j >> 9, k = j & 511;
            g_Wx2[j] = __float2half((n < 48) ? Wx[n * 512 + k] : 0.f);
            continue;
        }
        j -= N2;
        if (j < N3) { g_Wexp2[j] = __float2half(Wexp[j]); continue; }
        j -= N3;
        if (j < N4) { g_Wsq2[j] = __float2half(Wsq[j]); continue; }
        j -= N4;
        {   // Wc2[i][n] = sum_k Wlin[i][k] * Wout[k][n]
            int i = j >> 9, n = j & 511;
            float s = 0.f;
#pragma unroll 4
            for (int k = 0; k < DM; k++)
                s += Wlin[i * DM + k] * Wout[k * DI + n];
            g_Wc2[j] = __float2half(s);
        }
    }
}

// ---------------- depthwise causal conv1d (k=4) + SiLU, fp32 + fp16 out ------
__global__ void conv_silu_kernel(const float* __restrict__ cw,
                                 const float* __restrict__ cb) {
    int idx = blockIdx.x * 256 + threadIdx.x;     // t*512 + d
    int t = idx >> 9;
    int d = idx & 511;
    float acc = cb[d];
#pragma unroll
    for (int k = 0; k < 4; k++) {
        int tt = t - 3 + k;
        if (tt >= 0) acc += g_xz[tt * 1024 + d] * cw[d * 4 + k];
    }
    float sig = 1.f / (1.f + __expf(-acc));
    float v = acc * sig;
    g_xc[idx] = v;
    g_xc2[idx] = __float2half(v);
}

// ---------------- scan pass 1 (fused dt projection) --------------------------
__global__ void scan1_kernel(const float* __restrict__ A_log,
                             const float* __restrict__ Wdt,
                             const float* __restrict__ bdt) {
    __shared__ float xc_s[L][CHB];
    __shared__ alignas(16) float db_s[L][32];     // dbl[:, 0:32] (dtraw|B)
    __shared__ float dt_s[L][CHB];
    __shared__ float sW[CHB][16];
    __shared__ float sb[CHB];
    const int c = blockIdx.x, dg = blockIdx.y;
    const int t0 = c * L, d0 = dg * CHB;
    const int tid = threadIdx.x;

    if (tid < CHB * 16) sW[tid >> 4][tid & 15] = Wdt[(d0 + (tid >> 4)) * 16 + (tid & 15)];
    if (tid < CHB) sb[tid] = bdt[d0 + tid];
    for (int idx = tid; idx < L * CHB; idx += 128) {
        int t = idx >> 3, j = idx & 7;
        xc_s[t][j] = g_xc[(t0 + t) * DI + d0 + j];
    }
    for (int idx = tid; idx < L * 8; idx += 128) {
        int t = idx >> 3, q = idx & 7;
        *reinterpret_cast<float4*>(&db_s[t][q * 4]) =
            *reinterpret_cast<const float4*>(&g_dbl[(t0 + t) * 48 + q * 4]);
    }
    __syncthreads();

    // dt = softplus(dbl[:, :16] @ Wdt^T + b)
    for (int idx = tid; idx < L * CHB; idx += 128) {
        int t = idx >> 3, j = idx & 7;
        float s = sb[j];
#pragma unroll
        for (int k = 0; k < 16; k++) s += db_s[t][k] * sW[j][k];
        dt_s[t][j] = fmaxf(s, 0.f) + __logf(1.f + __expf(-fabsf(s)));
    }
    __syncthreads();

    const int w = tid >> 5, lane = tid & 31;
    const int j = w * 2 + (lane >> 4);
    const int s = lane & 15;
    const int d = d0 + j;
    const float Av = -__expf(A_log[d * S + s]);
    float h = 0.f, P = 1.f;
#pragma unroll 4
    for (int t = 0; t < L; t++) {
        float dtv = dt_s[t][j];
        float e = __expf(dtv * Av);
        h = e * h + (dtv * xc_s[t][j]) * db_s[t][16 + s];
        P *= e;
    }
    int o = (c * DI + d) * S + s;
    g_P[o] = P;
    g_hl[o] = h;
}

// ---------------- scan pass 2: sequential chunk combine ----------------------
__global__ void scan2_kernel() {
    int id = blockIdx.x * 256 + threadIdx.x;      // 0 .. 8191 = d*16+s
    float h = 0.f;
#pragma unroll 8
    for (int c = 0; c < NC; c++) {
        int o = c * DI * S + id;
        g_hin[o] = h;
        h = g_P[o] * h + g_hl[o];
    }
}

// ---------------- scan pass 3 (fused dt) + gating, fp16 out ------------------
__global__ void scan3_kernel(const float* __restrict__ A_log,
                             const float* __restrict__ Wdt,
                             const float* __restrict__ bdt,
                             const float* __restrict__ Dp) {
    __shared__ float xc_s[L][CHB];
    __shared__ alignas(16) float db_s[L][48];     // dbl full row (dtraw|B|C)
    __shared__ float dt_s[L][CHB];
    __shared__ float y_s[L][CHB];
    __shared__ float sW[CHB][16];
    __shared__ float sb[CHB];
    const int c = blockIdx.x, dg = blockIdx.y;
    const int t0 = c * L, d0 = dg * CHB;
    const int tid = threadIdx.x;

    if (tid < CHB * 16) sW[tid >> 4][tid & 15] = Wdt[(d0 + (tid >> 4)) * 16 + (tid & 15)];
    if (tid < CHB) sb[tid] = bdt[d0 + tid];
    for (int idx = tid; idx < L * CHB; idx += 128) {
        int t = idx >> 3, j = idx & 7;
        xc_s[t][j] = g_xc[(t0 + t) * DI + d0 + j];
    }
    for (int idx = tid; idx < L * 12; idx += 128) {
        int t = idx / 12, q = idx % 12;
        *reinterpret_cast<float4*>(&db_s[t][q * 4]) =
            *reinterpret_cast<const float4*>(&g_dbl[(t0 + t) * 48 + q * 4]);
    }
    __syncthreads();

    for (int idx = tid; idx < L * CHB; idx += 128) {
        int t = idx >> 3, j = idx & 7;
        float s = sb[j];
#pragma unroll
        for (int k = 0; k < 16; k++) s += db_s[t][k] * sW[j][k];
        dt_s[t][j] = fmaxf(s, 0.f) + __logf(1.f + __expf(-fabsf(s)));
    }
    __syncthreads();

    const int w = tid >> 5, lane = tid & 31;
    const int j = w * 2 + (lane >> 4);
    const int s = lane & 15;
    const int d = d0 + j;
    const float Av = -__expf(A_log[d * S + s]);
    float h = g_hin[(c * DI + d) * S + s];
#pragma unroll 4
    for (int t = 0; t < L; t++) {
        float dtv = dt_s[t][j];
        float e = __expf(dtv * Av);
        h = e * h + (dtv * xc_s[t][j]) * db_s[t][16 + s];
        float yv = h * db_s[t][32 + s];
        yv += __shfl_xor_sync(0xffffffffu, yv, 8);
        yv += __shfl_xor_sync(0xffffffffu, yv, 4);
        yv += __shfl_xor_sync(0xffffffffu, yv, 2);
        yv += __shfl_xor_sync(0xffffffffu, yv, 1);
        if (s == 0) y_s[t][j] = yv;
    }
    __syncthreads();

    // fused epilogue: y2 = (y + Dp*xc) * silu(z) -> fp16
    for (int idx = tid; idx < L * CHB; idx += 128) {
        int t = idx >> 3, jj = idx & 7;
        int dd = d0 + jj, tt = t0 + t;
        float z = g_xz[tt * 1024 + DI + dd];
        float sig = 1.f / (1.f + __expf(-z));
        float v = (y_s[t][jj] + Dp[dd] * xc_s[t][jj]) * (z * sig);
        g_y22[tt * DI + dd] = __float2half(v);
    }
}

// ---------------------------------------------------------------------------
extern "C" void kernel_launch(void* const* d_in, const int* in_sizes, int n_in,
                              void* d_out, int out_size) {
    const float* input  = (const float*)d_in[0];
    const float* W_in   = (const float*)d_in[2];
    const float* conv_w = (const float*)d_in[3];
    const float* conv_b = (const float*)d_in[4];
    const float* W_x    = (const float*)d_in[5];
    const float* W_dt   = (const float*)d_in[6];
    const float* b_dt   = (const float*)d_in[7];
    const float* A_log  = (const float*)d_in[8];
    const float* Dp     = (const float*)d_in[9];
    const float* W_out  = (const float*)d_in[10];
    const float* W_lin  = (const float*)d_in[11];
    const float* b_lin  = (const float*)d_in[12];
    const float* ln1_g  = (const float*)d_in[13];
    const float* ln1_b  = (const float*)d_in[14];
    const float* W_exp  = (const float*)d_in[15];
    const float* b_exp  = (const float*)d_in[16];
    const float* W_sq   = (const float*)d_in[17];
    const float* b_sq   = (const float*)d_in[18];
    const float* ln2_g  = (const float*)d_in[19];
    const float* ln2_b  = (const float*)d_in[20];
    float* out = (float*)d_out;

    float *xz, *dbl, *h;
    h16 *in2, *xc2, *y22, *h2, *ff12, *Win2, *Wx2, *Wexp2, *Wsq2, *Wc2;
    cudaGetSymbolAddress((void**)&xz,   g_xz);
    cudaGetSymbolAddress((void**)&dbl,  g_dbl);
    cudaGetSymbolAddress((void**)&h,    g_h);
    cudaGetSymbolAddress((void**)&in2,  g_in2);
    cudaGetSymbolAddress((void**)&xc2,  g_xc2);
    cudaGetSymbolAddress((void**)&y22,  g_y22);
    cudaGetSymbolAddress((void**)&h2,   g_h2);
    cudaGetSymbolAddress((void**)&ff12, g_ff12);
    cudaGetSymbolAddress((void**)&Win2, g_Win2);
    cudaGetSymbolAddress((void**)&Wx2,  g_Wx2);
    cudaGetSymbolAddress((void**)&Wexp2,g_Wexp2);
    cudaGetSymbolAddress((void**)&Wsq2, g_Wsq2);
    cudaGetSymbolAddress((void**)&Wc2,  g_Wc2);

    const int SM_128_128 = 3 * (128 + 128) * 36 * 4;   // 110592
    const int SM_64_64   = 3 * (64 + 64) * 36 * 4;     // 55296
    const int SM_LN      = 3 * (64 + 256) * 36 * 4;    // 138240
    cudaFuncSetAttribute(gemm_f16<128,128,4,2,0>, cudaFuncAttributeMaxDynamicSharedMemorySize, SM_128_128);
    cudaFuncSetAttribute(gemm_f16<128,128,4,2,1>, cudaFuncAttributeMaxDynamicSharedMemorySize, SM_128_128);
    cudaFuncSetAttribute(gemm_f16<64,64,2,4,0>,   cudaFuncAttributeMaxDynamicSharedMemorySize, SM_64_64);
    cudaFuncSetAttribute(gemm_ln,                 cudaFuncAttributeMaxDynamicSharedMemorySize, SM_LN);

    float* out_tail = (out_size >= 2 * T * DM) ? (out + (size_t)T * DM) : nullptr;

    // 1: mega-prep (input->fp16, all weights, Wc, output tail)
    prep_kernel<<<2048, 256>>>(input, W_in, W_x, W_exp, W_sq, W_lin, W_out, out_tail);

    // 2 (G1): xz = x @ W_in^T  [8192,1024], K=256
    gemm_f16<128,128,4,2,0><<<dim3(8, 64), 256, SM_128_128>>>(
        in2, Win2, xz, 256, 1024, 1024, nullptr);

    // 3: conv + silu -> xc fp32 + xc2 fp16
    conv_silu_kernel<<<(T * DI) / 256, 256>>>(conv_w, conv_b);

    // 4 (G2, profiled slot): dbl = xc @ W_x^T  [8192,48], K=512
    gemm_f16<64,64,2,4,0><<<dim3(1, 128), 256, SM_64_64>>>(
        xc2, Wx2, dbl, 512, 48, 48, nullptr);

    // 5-7: chunked selective scan (dt fused) + gating -> y22 fp16
    scan1_kernel<<<dim3(NC, DI / CHB), 128>>>(A_log, W_dt, b_dt);
    scan2_kernel<<<(DI * S) / 256, 256>>>();
    scan3_kernel<<<dim3(NC, DI / CHB), 128>>>(A_log, W_dt, b_dt, Dp);

    // 8 (G4+LN1): h = LN(y2 @ Wc^T + b_lin + input), h2 fp16
    gemm_ln<<<T / 64, 256, SM_LN>>>(
        y22, Wc2, 512, b_lin, input, ln1_g, ln1_b, h, h2);

    // 9 (G5): ff1 = relu(h @ W_exp^T + b_exp) -> ff12 fp16  [8192,512], K=256
    gemm_f16<128,128,4,2,1><<<dim3(4, 64), 256, SM_128_128>>>(
        h2, Wexp2, ff12, 256, 512, 512, b_exp);

    // 10 (G6+LN2): out = LN(ff1 @ W_sq^T + b_sq + h)
    gemm_ln<<<T / 64, 256, SM_LN>>>(
        ff12, Wsq2, 512, b_sq, h, ln2_g, ln2_b, out, nullptr);
}

// round 13
// speedup vs baseline: 1.1321x; 1.1321x over previous
#include <cuda_runtime.h>
#include <cuda_fp16.h>
#include <math.h>

#define T    8192
#define DM   256
#define DI   512
#define S    16
#define NC   64           // chunks
#define L    128          // T/NC
#define CHB  8            // channels per scan block

typedef __half h16;

// ---------------- scratch (static device memory; no allocs) ----------------
__device__ float g_xz  [T * 1024];
__device__ float g_xc  [T * DI];
__device__ h16   g_in2 [T * DM];         // input fp16, K=256
__device__ h16   g_xc2 [T * DI];         // xc fp16, K=512
__device__ float g_dbl [T * 48];
__device__ float g_dt  [T * DI];
__device__ h16   g_y22 [T * DI];         // gated y fp16, K=512
__device__ float g_h   [T * DM];
__device__ h16   g_h2  [T * DM];         // h fp16, K=256
__device__ h16   g_ff12[T * DI];         // relu(ff1) fp16, K=512
__device__ h16   g_Win2 [1024 * DM];     // weights fp16
__device__ h16   g_Wx2  [64 * DI];       // padded 48->64 rows
__device__ h16   g_Wc2  [DM * DI];
__device__ h16   g_Wexp2[DI * DM];
__device__ h16   g_Wsq2 [DM * DI];
__device__ h16   g_Wlin2[DM * DM];
__device__ h16   g_WoutT[DI * DM];       // Wout^T: [n][k]
__device__ float g_P   [NC * DI * S];
__device__ float g_hl  [NC * DI * S];
__device__ float g_hin [NC * DI * S];

__device__ __forceinline__ void ldsm4(unsigned& r0, unsigned& r1,
                                      unsigned& r2, unsigned& r3, unsigned addr) {
    asm volatile("ldmatrix.sync.aligned.m8n8.x4.shared.b16 {%0,%1,%2,%3}, [%4];"
                 : "=r"(r0), "=r"(r1), "=r"(r2), "=r"(r3) : "r"(addr));
}

__device__ __forceinline__ void cp16(unsigned saddr, const void* gaddr) {
    asm volatile("cp.async.ca.shared.global [%0], [%1], 16;"
                 :: "r"(saddr), "l"(gaddr));
}

#define MMA16816(acc, a0, a1, a2, a3, b0, b1)                                   \
    asm volatile(                                                               \
        "mma.sync.aligned.m16n8k16.row.col.f32.f16.f16.f32 "                    \
        "{%0,%1,%2,%3},{%4,%5,%6,%7},{%8,%9},{%0,%1,%2,%3};"                    \
        : "+f"(acc[0]), "+f"(acc[1]), "+f"(acc[2]), "+f"(acc[3])                \
        : "r"(a0), "r"(a1), "r"(a2), "r"(a3), "r"(b0), "r"(b1))

// ---------------- fp16 tensor-core GEMM (64-wide K chunks, 3-stage) ---------
// C[M,N] = A[M,K] * B[N,K]^T (+bias). K multiple of 64.
// MODE 0: fp32 out. MODE 1: relu->fp16 out. MODE 2: fp16 out (no relu).
template<int BM, int BN, int WM, int WN, int MODE>
__global__ __launch_bounds__(256, 2)
void gemm_f16(const h16* __restrict__ A, const h16* __restrict__ B,
              void* __restrict__ Cv, int K, int Nld, int Nlog,
              const float* __restrict__ bias) {
    constexpr int MT = BM / WM / 16;
    constexpr int NT = BN / WN / 8;
    constexpr int SAW = 36;                 // words per 64-h16 row (8 h16 pad)
    constexpr int STG = (BM + BN) * SAW;    // words per stage
    extern __shared__ unsigned sm[];        // 3 stages
    const unsigned smemU = (unsigned)__cvta_generic_to_shared(sm);

    const int tid = threadIdx.x;
    const int w = tid >> 5, lane = tid & 31;
    const int g = lane >> 2, t4 = lane & 3;
    const int wm = w % WM, wn = w / WM;
    const int bm = blockIdx.y * BM, bn = blockIdx.x * BN;
    const int m0 = wm * (BM / WM), n0 = wn * (BN / WN);

    const int rA = (lane & 7) + ((lane & 8) ? 8 : 0);
    const int cA = (lane & 16) ? 4 : 0;
    const int rB = (lane & 7) + ((lane & 16) ? 8 : 0);
    const int cB = (lane & 8) ? 4 : 0;
    const unsigned aAddr = smemU + (unsigned)(((m0 + rA) * SAW + cA) * 4);
    const unsigned bAddr = smemU + (unsigned)((BM * SAW + (n0 + rB) * SAW + cB) * 4);

    const int ldr = tid >> 3;
    const int lcw = (tid & 7) * 4;
    const int lce = (tid & 7) * 8;

    float acc[MT][NT][4];
#pragma unroll
    for (int mi = 0; mi < MT; mi++)
#pragma unroll
        for (int ni = 0; ni < NT; ni++)
#pragma unroll
            for (int q = 0; q < 4; q++) acc[mi][ni][q] = 0.f;

    const int nch = K >> 6;

    auto issue = [&](int ch, int st) {
        const unsigned base = smemU + (unsigned)(st * STG * 4);
        const int ke = ch * 64 + lce;
#pragma unroll
        for (int r = ldr; r < BM; r += 32)
            cp16(base + (unsigned)((r * SAW + lcw) * 4),
                 A + (size_t)(bm + r) * K + ke);
#pragma unroll
        for (int r = ldr; r < BN; r += 32)
            cp16(base + (unsigned)((BM * SAW + r * SAW + lcw) * 4),
                 B + (size_t)(bn + r) * K + ke);
        asm volatile("cp.async.commit_group;" ::: "memory");
    };

    issue(0, 0);
    issue(1, 1);

    int st = 0;
    for (int i = 0; i < nch; i++) {
        if (i + 1 < nch)
            asm volatile("cp.async.wait_group 1;" ::: "memory");
        else
            asm volatile("cp.async.wait_group 0;" ::: "memory");
        __syncthreads();
        if (i + 2 < nch) {
            int st2 = st + 2; if (st2 >= 3) st2 -= 3;
            issue(i + 2, st2);
        }
        const unsigned so = (unsigned)(st * STG * 4);
#pragma unroll
        for (int kt = 0; kt < 4; kt++) {
            unsigned af[MT][4];
#pragma unroll
            for (int mi = 0; mi < MT; mi++)
                ldsm4(af[mi][0], af[mi][1], af[mi][2], af[mi][3],
                      aAddr + so + (unsigned)(mi * 16 * SAW * 4 + kt * 32));
            unsigned bfr[NT][2];
#pragma unroll
            for (int p = 0; p < NT / 2; p++) {
                unsigned r0, r1, r2, r3;
                ldsm4(r0, r1, r2, r3,
                      bAddr + so + (unsigned)(p * 16 * SAW * 4 + kt * 32));
                bfr[2 * p][0] = r0; bfr[2 * p][1] = r1;
                bfr[2 * p + 1][0] = r2; bfr[2 * p + 1][1] = r3;
            }
#pragma unroll
            for (int mi = 0; mi < MT; mi++)
#pragma unroll
                for (int ni = 0; ni < NT; ni++)
                    MMA16816(acc[mi][ni], af[mi][0], af[mi][1], af[mi][2], af[mi][3],
                             bfr[ni][0], bfr[ni][1]);
        }
        if (++st >= 3) st = 0;
    }

    // epilogue
#pragma unroll
    for (int mi = 0; mi < MT; mi++) {
        int r0 = bm + m0 + mi * 16 + g;
        int r1 = r0 + 8;
#pragma unroll
        for (int ni = 0; ni < NT; ni++) {
            int c = bn + n0 + ni * 8 + 2 * t4;
            if (c >= Nlog) continue;
            float b0 = bias ? bias[c] : 0.f;
            float b1 = bias ? bias[c + 1] : 0.f;
            float v00 = acc[mi][ni][0] + b0, v01 = acc[mi][ni][1] + b1;
            float v10 = acc[mi][ni][2] + b0, v11 = acc[mi][ni][3] + b1;
            if (MODE == 0) {
                float* C = (float*)Cv;
                *reinterpret_cast<float2*>(C + (size_t)r0 * Nld + c) = make_float2(v00, v01);
                *reinterpret_cast<float2*>(C + (size_t)r1 * Nld + c) = make_float2(v10, v11);
            } else {
                h16* C2 = (h16*)Cv;
                if (MODE == 1) {
                    v00 = fmaxf(v00, 0.f); v01 = fmaxf(v01, 0.f);
                    v10 = fmaxf(v10, 0.f); v11 = fmaxf(v11, 0.f);
                }
                *reinterpret_cast<__half2*>(C2 + (size_t)r0 * Nld + c) =
                    __halves2half2(__float2half(v00), __float2half(v01));
                *reinterpret_cast<__half2*>(C2 + (size_t)r1 * Nld + c) =
                    __halves2half2(__float2half(v10), __float2half(v11));
            }
        }
    }
}

// ---------------- GEMM with fused LayerNorm epilogue -------------------------
// BM=64, BN=256 (full row). out32 = LN(A@B^T + bias + res) * gam + bet.
__global__ __launch_bounds__(256, 1)
void gemm_ln(const h16* __restrict__ A, const h16* __restrict__ B, int K,
             const float* __restrict__ bias, const float* __restrict__ res,
             const float* __restrict__ gam, const float* __restrict__ bet,
             float* __restrict__ out32, h16* __restrict__ out16) {
    constexpr int BM = 64, BN = 256, WM = 2;
    constexpr int MT = 2, NT = 8;
    constexpr int SAW = 36;
    constexpr int STG = (BM + BN) * SAW;
    extern __shared__ unsigned sm[];
    const unsigned smemU = (unsigned)__cvta_generic_to_shared(sm);

    const int tid = threadIdx.x;
    const int w = tid >> 5, lane = tid & 31;
    const int g = lane >> 2, t4 = lane & 3;
    const int wm = w % WM, wn = w / WM;
    const int bm = blockIdx.x * BM;
    const int m0 = wm * 32, n0 = wn * 64;

    const int rA = (lane & 7) + ((lane & 8) ? 8 : 0);
    const int cA = (lane & 16) ? 4 : 0;
    const int rB = (lane & 7) + ((lane & 16) ? 8 : 0);
    const int cB = (lane & 8) ? 4 : 0;
    const unsigned aAddr = smemU + (unsigned)(((m0 + rA) * SAW + cA) * 4);
    const unsigned bAddr = smemU + (unsigned)((BM * SAW + (n0 + rB) * SAW + cB) * 4);

    const int ldr = tid >> 3;
    const int lcw = (tid & 7) * 4;
    const int lce = (tid & 7) * 8;

    float acc[MT][NT][4];
#pragma unroll
    for (int mi = 0; mi < MT; mi++)
#pragma unroll
        for (int ni = 0; ni < NT; ni++)
#pragma unroll
            for (int q = 0; q < 4; q++) acc[mi][ni][q] = 0.f;

    const int nch = K >> 6;

    auto issue = [&](int ch, int st) {
        const unsigned base = smemU + (unsigned)(st * STG * 4);
        const int ke = ch * 64 + lce;
#pragma unroll
        for (int r = ldr; r < BM; r += 32)
            cp16(base + (unsigned)((r * SAW + lcw) * 4),
                 A + (size_t)(bm + r) * K + ke);
#pragma unroll
        for (int r = ldr; r < BN; r += 32)
            cp16(base + (unsigned)((BM * SAW + r * SAW + lcw) * 4),
                 B + (size_t)r * K + ke);
        asm volatile("cp.async.commit_group;" ::: "memory");
    };

    issue(0, 0);
    issue(1, 1);

    int st = 0;
    for (int i = 0; i < nch; i++) {
        if (i + 1 < nch)
            asm volatile("cp.async.wait_group 1;" ::: "memory");
        else
            asm volatile("cp.async.wait_group 0;" ::: "memory");
        __syncthreads();
        if (i + 2 < nch) {
            int st2 = st + 2; if (st2 >= 3) st2 -= 3;
            issue(i + 2, st2);
        }
        const unsigned so = (unsigned)(st * STG * 4);
#pragma unroll
        for (int kt = 0; kt < 4; kt++) {
            unsigned af[MT][4];
#pragma unroll
            for (int mi = 0; mi < MT; mi++)
                ldsm4(af[mi][0], af[mi][1], af[mi][2], af[mi][3],
                      aAddr + so + (unsigned)(mi * 16 * SAW * 4 + kt * 32));
            unsigned bfr[NT][2];
#pragma unroll
            for (int p = 0; p < NT / 2; p++) {
                unsigned r0, r1, r2, r3;
                ldsm4(r0, r1, r2, r3,
                      bAddr + so + (unsigned)(p * 16 * SAW * 4 + kt * 32));
                bfr[2 * p][0] = r0; bfr[2 * p][1] = r1;
                bfr[2 * p + 1][0] = r2; bfr[2 * p + 1][1] = r3;
            }
#pragma unroll
            for (int mi = 0; mi < MT; mi++)
#pragma unroll
                for (int ni = 0; ni < NT; ni++)
                    MMA16816(acc[mi][ni], af[mi][0], af[mi][1], af[mi][2], af[mi][3],
                             bfr[ni][0], bfr[ni][1]);
        }
        if (++st >= 3) st = 0;
    }

    // --- fused LN epilogue ---
    float s1[MT][2], s2[MT][2];
#pragma unroll
    for (int mi = 0; mi < MT; mi++) {
        int r0 = bm + m0 + mi * 16 + g;
        int r1 = r0 + 8;
        s1[mi][0] = s1[mi][1] = s2[mi][0] = s2[mi][1] = 0.f;
#pragma unroll
        for (int ni = 0; ni < NT; ni++) {
            int c = n0 + ni * 8 + 2 * t4;
            float b0 = bias[c], b1 = bias[c + 1];
            float2 e0 = *reinterpret_cast<const float2*>(res + (size_t)r0 * DM + c);
            float2 e1 = *reinterpret_cast<const float2*>(res + (size_t)r1 * DM + c);
            acc[mi][ni][0] += b0 + e0.x;
            acc[mi][ni][1] += b1 + e0.y;
            acc[mi][ni][2] += b0 + e1.x;
            acc[mi][ni][3] += b1 + e1.y;
            s1[mi][0] += acc[mi][ni][0] + acc[mi][ni][1];
            s2[mi][0] += acc[mi][ni][0] * acc[mi][ni][0] + acc[mi][ni][1] * acc[mi][ni][1];
            s1[mi][1] += acc[mi][ni][2] + acc[mi][ni][3];
            s2[mi][1] += acc[mi][ni][2] * acc[mi][ni][2] + acc[mi][ni][3] * acc[mi][ni][3];
        }
    }
#pragma unroll
    for (int mi = 0; mi < MT; mi++)
#pragma unroll
        for (int q = 0; q < 2; q++) {
            s1[mi][q] += __shfl_xor_sync(0xffffffffu, s1[mi][q], 1);
            s1[mi][q] += __shfl_xor_sync(0xffffffffu, s1[mi][q], 2);
            s2[mi][q] += __shfl_xor_sync(0xffffffffu, s2[mi][q], 1);
            s2[mi][q] += __shfl_xor_sync(0xffffffffu, s2[mi][q], 2);
        }
    float* sred = (float*)sm;
    __syncthreads();
    if (t4 == 0) {
#pragma unroll
        for (int mi = 0; mi < MT; mi++) {
            int lr = m0 + mi * 16 + g;
            sred[(lr) * 8 + wn]           = s1[mi][0];
            sred[(lr) * 8 + 4 + wn]       = s2[mi][0];
            sred[(lr + 8) * 8 + wn]       = s1[mi][1];
            sred[(lr + 8) * 8 + 4 + wn]   = s2[mi][1];
        }
    }
    __syncthreads();
#pragma unroll
    for (int mi = 0; mi < MT; mi++) {
#pragma unroll
        for (int q = 0; q < 2; q++) {
            int lr = m0 + mi * 16 + g + q * 8;
            float t1 = sred[lr * 8 + 0] + sred[lr * 8 + 1] + sred[lr * 8 + 2] + sred[lr * 8 + 3];
            float t2 = sred[lr * 8 + 4] + sred[lr * 8 + 5] + sred[lr * 8 + 6] + sred[lr * 8 + 7];
            float m = t1 * (1.f / DM);
            float var = t2 * (1.f / DM) - m * m;
            float rstd = rsqrtf(var + 1e-5f);
            int row = bm + lr;
#pragma unroll
            for (int ni = 0; ni < NT; ni++) {
                int c = n0 + ni * 8 + 2 * t4;
                float v0 = (acc[mi][ni][q * 2 + 0] - m) * rstd * gam[c] + bet[c];
                float v1 = (acc[mi][ni][q * 2 + 1] - m) * rstd * gam[c + 1] + bet[c + 1];
                *reinterpret_cast<float2*>(out32 + (size_t)row * DM + c) = make_float2(v0, v1);
                if (out16)
                    *reinterpret_cast<__half2*>(out16 + (size_t)row * DM + c) =
                        __halves2half2(__float2half(v0), __float2half(v1));
            }
        }
    }
}

// ---------------- prep: input fp32 -> fp16, plus output-tail copy ------------
__global__ void prepA_kernel(const float* __restrict__ X, float* __restrict__ tail) {
    int idx = blockIdx.x * 256 + threadIdx.x;
    if (idx < T * DM) {
        float v = X[idx];
        g_in2[idx] = __float2half(v);
        if (tail) tail[idx] = v;
    }
}

// ---------------- prep: all weight conversions (grid-stride) -----------------
__global__ void prepW_kernel(const float* __restrict__ Win,
                             const float* __restrict__ Wx,
                             const float* __restrict__ Wexp,
                             const float* __restrict__ Wsq,
                             const float* __restrict__ Wlin,
                             const float* __restrict__ Wout) {
    const int N1 = 1024 * 256, N2 = 64 * 512, N3 = 512 * 256,
              N4 = 256 * 512, N5 = 256 * 256, N6 = 512 * 256;
    for (int idx = blockIdx.x * 256 + threadIdx.x;
         idx < N1 + N2 + N3 + N4 + N5 + N6; idx += gridDim.x * 256) {
        int j = idx;
        if (j < N1) { g_Win2[j] = __float2half(Win[j]); continue; }
        j -= N1;
        if (j < N2) {
            int n = j >> 9, k = j & 511;
            g_Wx2[j] = __float2half((n < 48) ? Wx[n * 512 + k] : 0.f);
            continue;
        }
        j -= N2;
        if (j < N3) { g_Wexp2[j] = __float2half(Wexp[j]); continue; }
        j -= N3;
        if (j < N4) { g_Wsq2[j] = __float2half(Wsq[j]); continue; }
        j -= N4;
        if (j < N5) { g_Wlin2[j] = __float2half(Wlin[j]); continue; }
        j -= N5;
        {   // WoutT[n][k] = Wout[k][n]
            int n = j >> 8, k = j & 255;
            g_WoutT[j] = __float2half(Wout[k * 512 + n]);
        }
    }
}

// ---------------- depthwise causal conv1d (k=4) + SiLU (register-carried) ----
// Each thread: fixed d, 8 consecutive t; 3-tap history carried in registers.
__global__ void conv_silu_kernel(const float* __restrict__ cw,
                                 const float* __restrict__ cb) {
    int idx = blockIdx.x * 256 + threadIdx.x;     // (t/8)*512 + d
    int d = idx & 511;
    int t0 = (idx >> 9) * 8;
    float w0 = cw[d * 4 + 0], w1 = cw[d * 4 + 1];
    float w2 = cw[d * 4 + 2], w3 = cw[d * 4 + 3];
    float b = cb[d];
    float xm3 = (t0 >= 3) ? g_xz[(t0 - 3) * 1024 + d] : 0.f;
    float xm2 = (t0 >= 2) ? g_xz[(t0 - 2) * 1024 + d] : 0.f;
    float xm1 = (t0 >= 1) ? g_xz[(t0 - 1) * 1024 + d] : 0.f;
#pragma unroll
    for (int q = 0; q < 8; q++) {
        int t = t0 + q;
        float x0 = g_xz[t * 1024 + d];
        float acc = b + w0 * xm3 + w1 * xm2 + w2 * xm1 + w3 * x0;
        xm3 = xm2; xm2 = xm1; xm1 = x0;
        float sig = 1.f / (1.f + __expf(-acc));
        float v = acc * sig;
        g_xc[t * 512 + d] = v;
        g_xc2[t * 512 + d] = __float2half(v);
    }
}

// ---------------- dt projection: softplus(dbl[:, :16] @ W_dt^T + b_dt) ------
__global__ void dtproj_kernel(const float* __restrict__ Wdt,
                              const float* __restrict__ bdt) {
    __shared__ float sWT[16][512];                // transposed: [k][d]
    __shared__ float sD[16][16];
    const int t0 = blockIdx.x * 16;
    const int tid = threadIdx.x;                  // 256
    for (int idx = tid; idx < 512 * 16; idx += 256)
        sWT[idx & 15][idx >> 4] = Wdt[idx];       // Wdt[d][k]
    for (int idx = tid; idx < 256; idx += 256) {
        int r = idx >> 4, k = idx & 15;
        sD[r][k] = g_dbl[(t0 + r) * 48 + k];
    }
    __syncthreads();
#pragma unroll
    for (int half = 0; half < 2; half++) {
        int d = tid + half * 256;
        float b = bdt[d];
        float wv[16];
#pragma unroll
        for (int k = 0; k < 16; k++) wv[k] = sWT[k][d];
#pragma unroll
        for (int r = 0; r < 16; r++) {
            float s = b;
#pragma unroll
            for (int k = 0; k < 16; k++) s += sD[r][k] * wv[k];
            float v = fmaxf(s, 0.f) + __logf(1.f + __expf(-fabsf(s)));
            g_dt[(t0 + r) * 512 + d] = v;
        }
    }
}

// ---------------- scan pass 1 ------------------------------------------------
__global__ void scan1_kernel(const float* __restrict__ A_log) {
    __shared__ float dt_s[L][CHB];
    __shared__ float xc_s[L][CHB];
    __shared__ float B_s[L][S];
    const int c = blockIdx.x, dg = blockIdx.y;
    const int t0 = c * L, d0 = dg * CHB;
    const int tid = threadIdx.x;

    for (int idx = tid; idx < L * CHB; idx += 128) {
        int t = idx >> 3, j = idx & 7;
        dt_s[t][j] = g_dt[(t0 + t) * DI + d0 + j];
        xc_s[t][j] = g_xc[(t0 + t) * DI + d0 + j];
    }
    for (int idx = tid; idx < L * S; idx += 128) {
        int t = idx >> 4, s = idx & 15;
        B_s[t][s] = g_dbl[(t0 + t) * 48 + 16 + s];
    }
    __syncthreads();

    const int w = tid >> 5, lane = tid & 31;
    const int j = w * 2 + (lane >> 4);
    const int s = lane & 15;
    const int d = d0 + j;
    const float Av = -__expf(A_log[d * S + s]);
    float h = 0.f, P = 1.f;
#pragma unroll 4
    for (int t = 0; t < L; t++) {
        float dtv = dt_s[t][j];
        float e = __expf(dtv * Av);
        h = e * h + (dtv * xc_s[t][j]) * B_s[t][s];
        P *= e;
    }
    int o = (c * DI + d) * S + s;
    g_P[o] = P;
    g_hl[o] = h;
}

// ---------------- scan pass 2: sequential chunk combine ----------------------
__global__ void scan2_kernel() {
    int id = blockIdx.x * 256 + threadIdx.x;      // 0 .. 8191 = d*16+s
    float h = 0.f;
#pragma unroll 8
    for (int c = 0; c < NC; c++) {
        int o = c * DI * S + id;
        g_hin[o] = h;
        h = g_P[o] * h + g_hl[o];
    }
}

// ---------------- scan pass 3: final scan + gating, fp16 out -----------------
__global__ void scan3_kernel(const float* __restrict__ A_log,
                             const float* __restrict__ Dp) {
    __shared__ float dt_s[L][CHB];
    __shared__ float xc_s[L][CHB];
    __shared__ float B_s[L][S];
    __shared__ float C_s[L][S];
    __shared__ float y_s[L][CHB];
    const int c = blockIdx.x, dg = blockIdx.y;
    const int t0 = c * L, d0 = dg * CHB;
    const int tid = threadIdx.x;

    for (int idx = tid; idx < L * CHB; idx += 128) {
        int t = idx >> 3, j = idx & 7;
        dt_s[t][j] = g_dt[(t0 + t) * DI + d0 + j];
        xc_s[t][j] = g_xc[(t0 + t) * DI + d0 + j];
    }
    for (int idx = tid; idx < L * S; idx += 128) {
        int t = idx >> 4, s = idx & 15;
        B_s[t][s] = g_dbl[(t0 + t) * 48 + 16 + s];
        C_s[t][s] = g_dbl[(t0 + t) * 48 + 32 + s];
    }
    __syncthreads();

    const int w = tid >> 5, lane = tid & 31;
    const int j = w * 2 + (lane >> 4);
    const int s = lane & 15;
    const int d = d0 + j;
    const float Av = -__expf(A_log[d * S + s]);
    float h = g_hin[(c * DI + d) * S + s];
#pragma unroll 4
    for (int t = 0; t < L; t++) {
        float dtv = dt_s[t][j];
        float e = __expf(dtv * Av);
        h = e * h + (dtv * xc_s[t][j]) * B_s[t][s];
        float yv = h * C_s[t][s];
        yv += __shfl_xor_sync(0xffffffffu, yv, 8);
        yv += __shfl_xor_sync(0xffffffffu, yv, 4);
        yv += __shfl_xor_sync(0xffffffffu, yv, 2);
        yv += __shfl_xor_sync(0xffffffffu, yv, 1);
        if (s == 0) y_s[t][j] = yv;
    }
    __syncthreads();

    // fused epilogue: y2 = (y + Dp*xc) * silu(z) -> fp16
    for (int idx = tid; idx < L * CHB; idx += 128) {
        int t = idx >> 3, jj = idx & 7;
        int dd = d0 + jj, tt = t0 + t;
        float z = g_xz[tt * 1024 + DI + dd];
        float sig = 1.f / (1.f + __expf(-z));
        float v = (y_s[t][jj] + Dp[dd] * xc_s[t][jj]) * (z * sig);
        g_y22[tt * DI + dd] = __float2half(v);
    }
}

// ---------------------------------------------------------------------------
extern "C" void kernel_launch(void* const* d_in, const int* in_sizes, int n_in,
                              void* d_out, int out_size) {
    const float* input  = (const float*)d_in[0];
    const float* W_in   = (const float*)d_in[2];
    const float* conv_w = (const float*)d_in[3];
    const float* conv_b = (const float*)d_in[4];
    const float* W_x    = (const float*)d_in[5];
    const float* W_dt   = (const float*)d_in[6];
    const float* b_dt   = (const float*)d_in[7];
    const float* A_log  = (const float*)d_in[8];
    const float* Dp     = (const float*)d_in[9];
    const float* W_out  = (const float*)d_in[10];
    const float* W_lin  = (const float*)d_in[11];
    const float* b_lin  = (const float*)d_in[12];
    const float* ln1_g  = (const float*)d_in[13];
    const float* ln1_b  = (const float*)d_in[14];
    const float* W_exp  = (const float*)d_in[15];
    const float* b_exp  = (const float*)d_in[16];
    const float* W_sq   = (const float*)d_in[17];
    const float* b_sq   = (const float*)d_in[18];
    const float* ln2_g  = (const float*)d_in[19];
    const float* ln2_b  = (const float*)d_in[20];
    float* out = (float*)d_out;

    float *xz, *dbl, *h;
    h16 *in2, *xc2, *y22, *h2, *ff12, *Win2, *Wx2, *Wexp2, *Wsq2, *Wc2, *Wlin2, *WoutT;
    cudaGetSymbolAddress((void**)&xz,   g_xz);
    cudaGetSymbolAddress((void**)&dbl,  g_dbl);
    cudaGetSymbolAddress((void**)&h,    g_h);
    cudaGetSymbolAddress((void**)&in2,  g_in2);
    cudaGetSymbolAddress((void**)&xc2,  g_xc2);
    cudaGetSymbolAddress((void**)&y22,  g_y22);
    cudaGetSymbolAddress((void**)&h2,   g_h2);
    cudaGetSymbolAddress((void**)&ff12, g_ff12);
    cudaGetSymbolAddress((void**)&Win2, g_Win2);
    cudaGetSymbolAddress((void**)&Wx2,  g_Wx2);
    cudaGetSymbolAddress((void**)&Wexp2,g_Wexp2);
    cudaGetSymbolAddress((void**)&Wsq2, g_Wsq2);
    cudaGetSymbolAddress((void**)&Wc2,  g_Wc2);
    cudaGetSymbolAddress((void**)&Wlin2,g_Wlin2);
    cudaGetSymbolAddress((void**)&WoutT,g_WoutT);

    const int SM_128_128 = 3 * (128 + 128) * 36 * 4;   // 110592
    const int SM_64_128  = 3 * (64 + 128) * 36 * 4;    // 82944
    const int SM_64_64   = 3 * (64 + 64) * 36 * 4;     // 55296
    const int SM_LN      = 3 * (64 + 256) * 36 * 4;    // 138240
    cudaFuncSetAttribute(gemm_f16<128,128,4,2,0>, cudaFuncAttributeMaxDynamicSharedMemorySize, SM_128_128);
    cudaFuncSetAttribute(gemm_f16<128,128,4,2,1>, cudaFuncAttributeMaxDynamicSharedMemorySize, SM_128_128);
    cudaFuncSetAttribute(gemm_f16<64,128,2,4,2>,  cudaFuncAttributeMaxDynamicSharedMemorySize, SM_64_128);
    cudaFuncSetAttribute(gemm_f16<64,64,2,4,0>,   cudaFuncAttributeMaxDynamicSharedMemorySize, SM_64_64);
    cudaFuncSetAttribute(gemm_ln,                 cudaFuncAttributeMaxDynamicSharedMemorySize, SM_LN);

    float* out_tail = (out_size >= 2 * T * DM) ? (out + (size_t)T * DM) : nullptr;

    // 1: input -> fp16 (+ output tail copy)
    prepA_kernel<<<(T * DM) / 256, 256>>>(input, out_tail);
    // 2: all weights -> fp16 (incl. Wout transpose)
    prepW_kernel<<<1024, 256>>>(W_in, W_x, W_exp, W_sq, W_lin, W_out);
    // 3 (G0): Wc = Wlin @ Wout  [256,512], K=256, fp16 out
    gemm_f16<64,128,2,4,2><<<dim3(4, 4), 256, SM_64_128>>>(
        Wlin2, WoutT, Wc2, 256, 512, 512, nullptr);

    // 4 (G1, profiled slot): xz = x @ W_in^T  [8192,1024], K=256
    gemm_f16<128,128,4,2,0><<<dim3(8, 64), 256, SM_128_128>>>(
        in2, Win2, xz, 256, 1024, 1024, nullptr);

    // 5: conv + silu -> xc fp32 + xc2 fp16 (register-carried)
    conv_silu_kernel<<<(T * DI / 8) / 256, 256>>>(conv_w, conv_b);

    // 6 (G2): dbl = xc @ W_x^T  [8192,48], K=512 (N padded to 64)
    gemm_f16<64,64,2,4,0><<<dim3(1, 128), 256, SM_64_64>>>(
        xc2, Wx2, dbl, 512, 48, 48, nullptr);

    // 7 (G3): dt = softplus(dbl[:, :16] @ W_dt^T + b_dt)
    dtproj_kernel<<<T / 16, 256>>>(W_dt, b_dt);

    // 8-10: chunked selective scan + gating -> y22 fp16
    scan1_kernel<<<dim3(NC, DI / CHB), 128>>>(A_log);
    scan2_kernel<<<(DI * S) / 256, 256>>>();
    scan3_kernel<<<dim3(NC, DI / CHB), 128>>>(A_log, Dp);

    // 11 (G4+LN1): h = LN(y2 @ Wc^T + b_lin + input), h2 fp16
    gemm_ln<<<T / 64, 256, SM_LN>>>(
        y22, Wc2, 512, b_lin, input, ln1_g, ln1_b, h, h2);

    // 12 (G5): ff1 = relu(h @ W_exp^T + b_exp) -> ff12 fp16  [8192,512], K=256
    gemm_f16<128,128,4,2,1><<<dim3(4, 64), 256, SM_128_128>>>(
        h2, Wexp2, ff12, 256, 512, 512, b_exp);

    // 13 (G6+LN2): out = LN(ff1 @ W_sq^T + b_sq + h)
    gemm_ln<<<T / 64, 256, SM_LN>>>(
        ff12, Wsq2, 512, b_sq, h, ln2_g, ln2_b, out, nullptr);
}

// round 14
// speedup vs baseline: 1.1688x; 1.0324x over previous
#include <cuda_runtime.h>
#include <cuda_fp16.h>
#include <math.h>

#define T    8192
#define DM   256
#define DI   512
#define S    16
#define NC   64           // chunks
#define L    128          // T/NC
#define CHB  8            // channels per scan block

typedef __half h16;

// ---------------- scratch (static device memory; no allocs) ----------------
__device__ float g_xz  [T * 1024];
__device__ float g_xc  [T * DI];
__device__ h16   g_in2 [T * DM];         // input fp16, K=256
__device__ h16   g_xc2 [T * DI];         // xc fp16, K=512
__device__ float g_dbl [T * 48];
__device__ float g_dt  [T * DI];
__device__ h16   g_y22 [T * DI];         // gated y fp16, K=512
__device__ float g_h   [T * DM];
__device__ h16   g_h2  [T * DM];         // h fp16, K=256
__device__ h16   g_ff12[T * DI];         // relu(ff1) fp16, K=512
__device__ h16   g_Win2 [1024 * DM];     // weights fp16
__device__ h16   g_Wx2  [64 * DI];       // padded 48->64 rows
__device__ h16   g_Wc2  [DM * DI];
__device__ h16   g_Wexp2[DI * DM];
__device__ h16   g_Wsq2 [DM * DI];
__device__ h16   g_Wlin2[DM * DM];
__device__ h16   g_WoutT[DI * DM];       // Wout^T: [n][k]
__device__ float g_P   [NC * DI * S];
__device__ float g_hl  [NC * DI * S];
__device__ float g_hin [NC * DI * S];

__device__ __forceinline__ void ldsm4(unsigned& r0, unsigned& r1,
                                      unsigned& r2, unsigned& r3, unsigned addr) {
    asm volatile("ldmatrix.sync.aligned.m8n8.x4.shared.b16 {%0,%1,%2,%3}, [%4];"
                 : "=r"(r0), "=r"(r1), "=r"(r2), "=r"(r3) : "r"(addr));
}

__device__ __forceinline__ void cp16(unsigned saddr, const void* gaddr) {
    asm volatile("cp.async.ca.shared.global [%0], [%1], 16;"
                 :: "r"(saddr), "l"(gaddr));
}

#define MMA16816(acc, a0, a1, a2, a3, b0, b1)                                   \
    asm volatile(                                                               \
        "mma.sync.aligned.m16n8k16.row.col.f32.f16.f16.f32 "                    \
        "{%0,%1,%2,%3},{%4,%5,%6,%7},{%8,%9},{%0,%1,%2,%3};"                    \
        : "+f"(acc[0]), "+f"(acc[1]), "+f"(acc[2]), "+f"(acc[3])                \
        : "r"(a0), "r"(a1), "r"(a2), "r"(a3), "r"(b0), "r"(b1))

// ---------------- fp16 tensor-core GEMM (64-wide K chunks, 3-stage) ---------
// C[M,N] = A[M,K] * B[N,K]^T (+bias). K multiple of 64.
// MODE 0: fp32 out. MODE 1: relu->fp16 out. MODE 2: fp16 out (no relu).
template<int BM, int BN, int WM, int WN, int MODE>
__global__ __launch_bounds__(256, 2)
void gemm_f16(const h16* __restrict__ A, const h16* __restrict__ B,
              void* __restrict__ Cv, int K, int Nld, int Nlog,
              const float* __restrict__ bias) {
    constexpr int MT = BM / WM / 16;
    constexpr int NT = BN / WN / 8;
    constexpr int SAW = 36;                 // words per 64-h16 row (8 h16 pad)
    constexpr int STG = (BM + BN) * SAW;    // words per stage
    extern __shared__ unsigned sm[];        // 3 stages
    const unsigned smemU = (unsigned)__cvta_generic_to_shared(sm);

    const int tid = threadIdx.x;
    const int w = tid >> 5, lane = tid & 31;
    const int g = lane >> 2, t4 = lane & 3;
    const int wm = w % WM, wn = w / WM;
    const int bm = blockIdx.y * BM, bn = blockIdx.x * BN;
    const int m0 = wm * (BM / WM), n0 = wn * (BN / WN);

    const int rA = (lane & 7) + ((lane & 8) ? 8 : 0);
    const int cA = (lane & 16) ? 4 : 0;
    const int rB = (lane & 7) + ((lane & 16) ? 8 : 0);
    const int cB = (lane & 8) ? 4 : 0;
    const unsigned aAddr = smemU + (unsigned)(((m0 + rA) * SAW + cA) * 4);
    const unsigned bAddr = smemU + (unsigned)((BM * SAW + (n0 + rB) * SAW + cB) * 4);

    const int ldr = tid >> 3;
    const int lcw = (tid & 7) * 4;
    const int lce = (tid & 7) * 8;

    float acc[MT][NT][4];
#pragma unroll
    for (int mi = 0; mi < MT; mi++)
#pragma unroll
        for (int ni = 0; ni < NT; ni++)
#pragma unroll
            for (int q = 0; q < 4; q++) acc[mi][ni][q] = 0.f;

    const int nch = K >> 6;

    auto issue = [&](int ch, int st) {
        const unsigned base = smemU + (unsigned)(st * STG * 4);
        const int ke = ch * 64 + lce;
#pragma unroll
        for (int r = ldr; r < BM; r += 32)
            cp16(base + (unsigned)((r * SAW + lcw) * 4),
                 A + (size_t)(bm + r) * K + ke);
#pragma unroll
        for (int r = ldr; r < BN; r += 32)
            cp16(base + (unsigned)((BM * SAW + r * SAW + lcw) * 4),
                 B + (size_t)(bn + r) * K + ke);
        asm volatile("cp.async.commit_group;" ::: "memory");
    };

    issue(0, 0);
    issue(1, 1);

    int st = 0;
    for (int i = 0; i < nch; i++) {
        if (i + 1 < nch)
            asm volatile("cp.async.wait_group 1;" ::: "memory");
        else
            asm volatile("cp.async.wait_group 0;" ::: "memory");
        __syncthreads();
        if (i + 2 < nch) {
            int st2 = st + 2; if (st2 >= 3) st2 -= 3;
            issue(i + 2, st2);
        }
        const unsigned so = (unsigned)(st * STG * 4);
#pragma unroll
        for (int kt = 0; kt < 4; kt++) {
            unsigned af[MT][4];
#pragma unroll
            for (int mi = 0; mi < MT; mi++)
                ldsm4(af[mi][0], af[mi][1], af[mi][2], af[mi][3],
                      aAddr + so + (unsigned)(mi * 16 * SAW * 4 + kt * 32));
            unsigned bfr[NT][2];
#pragma unroll
            for (int p = 0; p < NT / 2; p++) {
                unsigned r0, r1, r2, r3;
                ldsm4(r0, r1, r2, r3,
                      bAddr + so + (unsigned)(p * 16 * SAW * 4 + kt * 32));
                bfr[2 * p][0] = r0; bfr[2 * p][1] = r1;
                bfr[2 * p + 1][0] = r2; bfr[2 * p + 1][1] = r3;
            }
#pragma unroll
            for (int mi = 0; mi < MT; mi++)
#pragma unroll
                for (int ni = 0; ni < NT; ni++)
                    MMA16816(acc[mi][ni], af[mi][0], af[mi][1], af[mi][2], af[mi][3],
                             bfr[ni][0], bfr[ni][1]);
        }
        if (++st >= 3) st = 0;
    }

    // epilogue
#pragma unroll
    for (int mi = 0; mi < MT; mi++) {
        int r0 = bm + m0 + mi * 16 + g;
        int r1 = r0 + 8;
#pragma unroll
        for (int ni = 0; ni < NT; ni++) {
            int c = bn + n0 + ni * 8 + 2 * t4;
            if (c >= Nlog) continue;
            float b0 = bias ? bias[c] : 0.f;
            float b1 = bias ? bias[c + 1] : 0.f;
            float v00 = acc[mi][ni][0] + b0, v01 = acc[mi][ni][1] + b1;
            float v10 = acc[mi][ni][2] + b0, v11 = acc[mi][ni][3] + b1;
            if (MODE == 0) {
                float* C = (float*)Cv;
                *reinterpret_cast<float2*>(C + (size_t)r0 * Nld + c) = make_float2(v00, v01);
                *reinterpret_cast<float2*>(C + (size_t)r1 * Nld + c) = make_float2(v10, v11);
            } else {
                h16* C2 = (h16*)Cv;
                if (MODE == 1) {
                    v00 = fmaxf(v00, 0.f); v01 = fmaxf(v01, 0.f);
                    v10 = fmaxf(v10, 0.f); v11 = fmaxf(v11, 0.f);
                }
                *reinterpret_cast<__half2*>(C2 + (size_t)r0 * Nld + c) =
                    __halves2half2(__float2half(v00), __float2half(v01));
                *reinterpret_cast<__half2*>(C2 + (size_t)r1 * Nld + c) =
                    __halves2half2(__float2half(v10), __float2half(v11));
            }
        }
    }
}

// ---------------- G2 + fused dt projection -----------------------------------
// BM=64, BN=64 (N=48 logical). Writes dbl fp32, then computes
// dt = softplus(dbl[:, :16] @ Wdt^T + b_dt) for its 64 rows, all 512 channels.
__global__ __launch_bounds__(256, 2)
void gemm_dt(const h16* __restrict__ A, const h16* __restrict__ B, int K,
             float* __restrict__ dblOut,
             const float* __restrict__ Wdt, const float* __restrict__ bdt) {
    constexpr int BM = 64, BN = 64, WM = 2;
    constexpr int MT = 2, NT = 2;
    constexpr int SAW = 36;
    constexpr int STG = (BM + BN) * SAW;
    extern __shared__ unsigned sm[];
    const unsigned smemU = (unsigned)__cvta_generic_to_shared(sm);

    const int tid = threadIdx.x;
    const int w = tid >> 5, lane = tid & 31;
    const int g = lane >> 2, t4 = lane & 3;
    const int wm = w % WM, wn = w / WM;
    const int bm = blockIdx.y * BM;
    const int m0 = wm * 32, n0 = wn * 16;

    const int rA = (lane & 7) + ((lane & 8) ? 8 : 0);
    const int cA = (lane & 16) ? 4 : 0;
    const int rB = (lane & 7) + ((lane & 16) ? 8 : 0);
    const int cB = (lane & 8) ? 4 : 0;
    const unsigned aAddr = smemU + (unsigned)(((m0 + rA) * SAW + cA) * 4);
    const unsigned bAddr = smemU + (unsigned)((BM * SAW + (n0 + rB) * SAW + cB) * 4);

    const int ldr = tid >> 3;
    const int lcw = (tid & 7) * 4;
    const int lce = (tid & 7) * 8;

    float acc[MT][NT][4];
#pragma unroll
    for (int mi = 0; mi < MT; mi++)
#pragma unroll
        for (int ni = 0; ni < NT; ni++)
#pragma unroll
            for (int q = 0; q < 4; q++) acc[mi][ni][q] = 0.f;

    const int nch = K >> 6;

    auto issue = [&](int ch, int st) {
        const unsigned base = smemU + (unsigned)(st * STG * 4);
        const int ke = ch * 64 + lce;
#pragma unroll
        for (int r = ldr; r < BM; r += 32)
            cp16(base + (unsigned)((r * SAW + lcw) * 4),
                 A + (size_t)(bm + r) * K + ke);
#pragma unroll
        for (int r = ldr; r < BN; r += 32)
            cp16(base + (unsigned)((BM * SAW + r * SAW + lcw) * 4),
                 B + (size_t)r * K + ke);
        asm volatile("cp.async.commit_group;" ::: "memory");
    };

    issue(0, 0);
    issue(1, 1);

    int st = 0;
    for (int i = 0; i < nch; i++) {
        if (i + 1 < nch)
            asm volatile("cp.async.wait_group 1;" ::: "memory");
        else
            asm volatile("cp.async.wait_group 0;" ::: "memory");
        __syncthreads();
        if (i + 2 < nch) {
            int st2 = st + 2; if (st2 >= 3) st2 -= 3;
            issue(i + 2, st2);
        }
        const unsigned so = (unsigned)(st * STG * 4);
#pragma unroll
        for (int kt = 0; kt < 4; kt++) {
            unsigned af[MT][4];
#pragma unroll
            for (int mi = 0; mi < MT; mi++)
                ldsm4(af[mi][0], af[mi][1], af[mi][2], af[mi][3],
                      aAddr + so + (unsigned)(mi * 16 * SAW * 4 + kt * 32));
            unsigned bfr[NT][2];
            {
                unsigned r0, r1, r2, r3;
                ldsm4(r0, r1, r2, r3,
                      bAddr + so + (unsigned)(kt * 32));
                bfr[0][0] = r0; bfr[0][1] = r1;
                bfr[1][0] = r2; bfr[1][1] = r3;
            }
#pragma unroll
            for (int mi = 0; mi < MT; mi++)
#pragma unroll
                for (int ni = 0; ni < NT; ni++)
                    MMA16816(acc[mi][ni], af[mi][0], af[mi][1], af[mi][2], af[mi][3],
                             bfr[ni][0], bfr[ni][1]);
        }
        if (++st >= 3) st = 0;
    }

    // write dbl (cols < 48) + stage cols 0..15 into smem for dt
    float* sdt = (float*)sm;                      // [64][17] floats, staging free now
    __syncthreads();
#pragma unroll
    for (int mi = 0; mi < MT; mi++) {
        int lr0 = m0 + mi * 16 + g;
        int lr1 = lr0 + 8;
        int r0 = bm + lr0, r1 = bm + lr1;
#pragma unroll
        for (int ni = 0; ni < NT; ni++) {
            int c = n0 + ni * 8 + 2 * t4;
            if (c < 48) {
                *reinterpret_cast<float2*>(dblOut + (size_t)r0 * 48 + c) =
                    make_float2(acc[mi][ni][0], acc[mi][ni][1]);
                *reinterpret_cast<float2*>(dblOut + (size_t)r1 * 48 + c) =
                    make_float2(acc[mi][ni][2], acc[mi][ni][3]);
            }
            if (c < 16) {                          // only wn==0 warps
                sdt[lr0 * 17 + c]     = acc[mi][ni][0];
                sdt[lr0 * 17 + c + 1] = acc[mi][ni][1];
                sdt[lr1 * 17 + c]     = acc[mi][ni][2];
                sdt[lr1 * 17 + c + 1] = acc[mi][ni][3];
            }
        }
    }
    __syncthreads();

    // dt = softplus(sdt @ Wdt^T + b) for rows [bm, bm+64), all 512 channels
#pragma unroll
    for (int half = 0; half < 2; half++) {
        int d = tid + half * 256;
        float wv[16];
#pragma unroll
        for (int k = 0; k < 16; k++) wv[k] = Wdt[d * 16 + k];
        float b = bdt[d];
#pragma unroll 4
        for (int r = 0; r < 64; r++) {
            float s = b;
#pragma unroll
            for (int k = 0; k < 16; k++) s += sdt[r * 17 + k] * wv[k];
            float v = fmaxf(s, 0.f) + __logf(1.f + __expf(-fabsf(s)));
            g_dt[(size_t)(bm + r) * 512 + d] = v;
        }
    }
}

// ---------------- GEMM with fused LayerNorm epilogue -------------------------
// BM=64, BN=256 (full row). out32 = LN(A@B^T + bias + res) * gam + bet.
__global__ __launch_bounds__(256, 1)
void gemm_ln(const h16* __restrict__ A, const h16* __restrict__ B, int K,
             const float* __restrict__ bias, const float* __restrict__ res,
             const float* __restrict__ gam, const float* __restrict__ bet,
             float* __restrict__ out32, h16* __restrict__ out16) {
    constexpr int BM = 64, BN = 256, WM = 2;
    constexpr int MT = 2, NT = 8;
    constexpr int SAW = 36;
    constexpr int STG = (BM + BN) * SAW;
    extern __shared__ unsigned sm[];
    const unsigned smemU = (unsigned)__cvta_generic_to_shared(sm);

    const int tid = threadIdx.x;
    const int w = tid >> 5, lane = tid & 31;
    const int g = lane >> 2, t4 = lane & 3;
    const int wm = w % WM, wn = w / WM;
    const int bm = blockIdx.x * BM;
    const int m0 = wm * 32, n0 = wn * 64;

    const int rA = (lane & 7) + ((lane & 8) ? 8 : 0);
    const int cA = (lane & 16) ? 4 : 0;
    const int rB = (lane & 7) + ((lane & 16) ? 8 : 0);
    const int cB = (lane & 8) ? 4 : 0;
    const unsigned aAddr = smemU + (unsigned)(((m0 + rA) * SAW + cA) * 4);
    const unsigned bAddr = smemU + (unsigned)((BM * SAW + (n0 + rB) * SAW + cB) * 4);

    const int ldr = tid >> 3;
    const int lcw = (tid & 7) * 4;
    const int lce = (tid & 7) * 8;

    float acc[MT][NT][4];
#pragma unroll
    for (int mi = 0; mi < MT; mi++)
#pragma unroll
        for (int ni = 0; ni < NT; ni++)
#pragma unroll
            for (int q = 0; q < 4; q++) acc[mi][ni][q] = 0.f;

    const int nch = K >> 6;

    auto issue = [&](int ch, int st) {
        const unsigned base = smemU + (unsigned)(st * STG * 4);
        const int ke = ch * 64 + lce;
#pragma unroll
        for (int r = ldr; r < BM; r += 32)
            cp16(base + (unsigned)((r * SAW + lcw) * 4),
                 A + (size_t)(bm + r) * K + ke);
#pragma unroll
        for (int r = ldr; r < BN; r += 32)
            cp16(base + (unsigned)((BM * SAW + r * SAW + lcw) * 4),
                 B + (size_t)r * K + ke);
        asm volatile("cp.async.commit_group;" ::: "memory");
    };

    issue(0, 0);
    issue(1, 1);

    int st = 0;
    for (int i = 0; i < nch; i++) {
        if (i + 1 < nch)
            asm volatile("cp.async.wait_group 1;" ::: "memory");
        else
            asm volatile("cp.async.wait_group 0;" ::: "memory");
        __syncthreads();
        if (i + 2 < nch) {
            int st2 = st + 2; if (st2 >= 3) st2 -= 3;
            issue(i + 2, st2);
        }
        const unsigned so = (unsigned)(st * STG * 4);
#pragma unroll
        for (int kt = 0; kt < 4; kt++) {
            unsigned af[MT][4];
#pragma unroll
            for (int mi = 0; mi < MT; mi++)
                ldsm4(af[mi][0], af[mi][1], af[mi][2], af[mi][3],
                      aAddr + so + (unsigned)(mi * 16 * SAW * 4 + kt * 32));
            unsigned bfr[NT][2];
#pragma unroll
            for (int p = 0; p < NT / 2; p++) {
                unsigned r0, r1, r2, r3;
                ldsm4(r0, r1, r2, r3,
                      bAddr + so + (unsigned)(p * 16 * SAW * 4 + kt * 32));
                bfr[2 * p][0] = r0; bfr[2 * p][1] = r1;
                bfr[2 * p + 1][0] = r2; bfr[2 * p + 1][1] = r3;
            }
#pragma unroll
            for (int mi = 0; mi < MT; mi++)
#pragma unroll
                for (int ni = 0; ni < NT; ni++)
                    MMA16816(acc[mi][ni], af[mi][0], af[mi][1], af[mi][2], af[mi][3],
                             bfr[ni][0], bfr[ni][1]);
        }
        if (++st >= 3) st = 0;
    }

    // --- fused LN epilogue ---
    float s1[MT][2], s2[MT][2];
#pragma unroll
    for (int mi = 0; mi < MT; mi++) {
        int r0 = bm + m0 + mi * 16 + g;
        int r1 = r0 + 8;
        s1[mi][0] = s1[mi][1] = s2[mi][0] = s2[mi][1] = 0.f;
#pragma unroll
        for (int ni = 0; ni < NT; ni++) {
            int c = n0 + ni * 8 + 2 * t4;
            float b0 = bias[c], b1 = bias[c + 1];
            float2 e0 = *reinterpret_cast<const float2*>(res + (size_t)r0 * DM + c);
            float2 e1 = *reinterpret_cast<const float2*>(res + (size_t)r1 * DM + c);
            acc[mi][ni][0] += b0 + e0.x;
            acc[mi][ni][1] += b1 + e0.y;
            acc[mi][ni][2] += b0 + e1.x;
            acc[mi][ni][3] += b1 + e1.y;
            s1[mi][0] += acc[mi][ni][0] + acc[mi][ni][1];
            s2[mi][0] += acc[mi][ni][0] * acc[mi][ni][0] + acc[mi][ni][1] * acc[mi][ni][1];
            s1[mi][1] += acc[mi][ni][2] + acc[mi][ni][3];
            s2[mi][1] += acc[mi][ni][2] * acc[mi][ni][2] + acc[mi][ni][3] * acc[mi][ni][3];
        }
    }
#pragma unroll
    for (int mi = 0; mi < MT; mi++)
#pragma unroll
        for (int q = 0; q < 2; q++) {
            s1[mi][q] += __shfl_xor_sync(0xffffffffu, s1[mi][q], 1);
            s1[mi][q] += __shfl_xor_sync(0xffffffffu, s1[mi][q], 2);
            s2[mi][q] += __shfl_xor_sync(0xffffffffu, s2[mi][q], 1);
            s2[mi][q] += __shfl_xor_sync(0xffffffffu, s2[mi][q], 2);
        }
    float* sred = (float*)sm;
    __syncthreads();
    if (t4 == 0) {
#pragma unroll
        for (int mi = 0; mi < MT; mi++) {
            int lr = m0 + mi * 16 + g;
            sred[(lr) * 8 + wn]           = s1[mi][0];
            sred[(lr) * 8 + 4 + wn]       = s2[mi][0];
            sred[(lr + 8) * 8 + wn]       = s1[mi][1];
            sred[(lr + 8) * 8 + 4 + wn]   = s2[mi][1];
        }
    }
    __syncthreads();
#pragma unroll
    for (int mi = 0; mi < MT; mi++) {
#pragma unroll
        for (int q = 0; q < 2; q++) {
            int lr = m0 + mi * 16 + g + q * 8;
            float t1 = sred[lr * 8 + 0] + sred[lr * 8 + 1] + sred[lr * 8 + 2] + sred[lr * 8 + 3];
            float t2 = sred[lr * 8 + 4] + sred[lr * 8 + 5] + sred[lr * 8 + 6] + sred[lr * 8 + 7];
            float m = t1 * (1.f / DM);
            float var = t2 * (1.f / DM) - m * m;
            float rstd = rsqrtf(var + 1e-5f);
            int row = bm + lr;
#pragma unroll
            for (int ni = 0; ni < NT; ni++) {
                int c = n0 + ni * 8 + 2 * t4;
                float v0 = (acc[mi][ni][q * 2 + 0] - m) * rstd * gam[c] + bet[c];
                float v1 = (acc[mi][ni][q * 2 + 1] - m) * rstd * gam[c + 1] + bet[c + 1];
                *reinterpret_cast<float2*>(out32 + (size_t)row * DM + c) = make_float2(v0, v1);
                if (out16)
                    *reinterpret_cast<__half2*>(out16 + (size_t)row * DM + c) =
                        __halves2half2(__float2half(v0), __float2half(v1));
            }
        }
    }
}

// ---------------- merged prep: input + all weight conversions ---------------
__global__ void prep_kernel(const float* __restrict__ X, float* __restrict__ tail,
                            const float* __restrict__ Win,
                            const float* __restrict__ Wx,
                            const float* __restrict__ Wexp,
                            const float* __restrict__ Wsq,
                            const float* __restrict__ Wlin,
                            const float* __restrict__ Wout) {
    const int N0 = T * DM;
    const int N1 = 1024 * 256, N2 = 64 * 512, N3 = 512 * 256,
              N4 = 256 * 512, N5 = 256 * 256, N6 = 512 * 256;
    const int TOT = N0 + N1 + N2 + N3 + N4 + N5 + N6;
    for (int idx = blockIdx.x * 256 + threadIdx.x; idx < TOT; idx += gridDim.x * 256) {
        int j = idx;
        if (j < N0) {
            float v = X[j];
            g_in2[j] = __float2half(v);
            if (tail) tail[j] = v;
            continue;
        }
        j -= N0;
        if (j < N1) { g_Win2[j] = __float2half(Win[j]); continue; }
        j -= N1;
        if (j < N2) {
            int n = j >> 9, k = j & 511;
            g_Wx2[j] = __float2half((n < 48) ? Wx[n * 512 + k] : 0.f);
            continue;
        }
        j -= N2;
        if (j < N3) { g_Wexp2[j] = __float2half(Wexp[j]); continue; }
        j -= N3;
        if (j < N4) { g_Wsq2[j] = __float2half(Wsq[j]); continue; }
        j -= N4;
        if (j < N5) { g_Wlin2[j] = __float2half(Wlin[j]); continue; }
        j -= N5;
        {   // WoutT[n][k] = Wout[k][n]
            int n = j >> 8, k = j & 255;
            g_WoutT[j] = __float2half(Wout[k * 512 + n]);
        }
    }
}

// ---------------- depthwise causal conv1d (k=4) + SiLU (register-carried) ----
__global__ void conv_silu_kernel(const float* __restrict__ cw,
                                 const float* __restrict__ cb) {
    int idx = blockIdx.x * 256 + threadIdx.x;     // (t/8)*512 + d
    int d = idx & 511;
    int t0 = (idx >> 9) * 8;
    float w0 = cw[d * 4 + 0], w1 = cw[d * 4 + 1];
    float w2 = cw[d * 4 + 2], w3 = cw[d * 4 + 3];
    float b = cb[d];
    float xm3 = (t0 >= 3) ? g_xz[(t0 - 3) * 1024 + d] : 0.f;
    float xm2 = (t0 >= 2) ? g_xz[(t0 - 2) * 1024 + d] : 0.f;
    float xm1 = (t0 >= 1) ? g_xz[(t0 - 1) * 1024 + d] : 0.f;
#pragma unroll
    for (int q = 0; q < 8; q++) {
        int t = t0 + q;
        float x0 = g_xz[t * 1024 + d];
        float acc = b + w0 * xm3 + w1 * xm2 + w2 * xm1 + w3 * x0;
        xm3 = xm2; xm2 = xm1; xm1 = x0;
        float sig = 1.f / (1.f + __expf(-acc));
        float v = acc * sig;
        g_xc[t * 512 + d] = v;
        g_xc2[t * 512 + d] = __float2half(v);
    }
}

// ---------------- scan pass 1 ------------------------------------------------
__global__ void scan1_kernel(const float* __restrict__ A_log) {
    __shared__ float dt_s[L][CHB];
    __shared__ float xc_s[L][CHB];
    __shared__ float B_s[L][S];
    const int c = blockIdx.x, dg = blockIdx.y;
    const int t0 = c * L, d0 = dg * CHB;
    const int tid = threadIdx.x;

    for (int idx = tid; idx < L * CHB; idx += 128) {
        int t = idx >> 3, j = idx & 7;
        dt_s[t][j] = g_dt[(t0 + t) * DI + d0 + j];
        xc_s[t][j] = g_xc[(t0 + t) * DI + d0 + j];
    }
    for (int idx = tid; idx < L * S; idx += 128) {
        int t = idx >> 4, s = idx & 15;
        B_s[t][s] = g_dbl[(t0 + t) * 48 + 16 + s];
    }
    __syncthreads();

    const int w = tid >> 5, lane = tid & 31;
    const int j = w * 2 + (lane >> 4);
    const int s = lane & 15;
    const int d = d0 + j;
    const float Av = -__expf(A_log[d * S + s]);
    float h = 0.f, P = 1.f;
#pragma unroll 4
    for (int t = 0; t < L; t++) {
        float dtv = dt_s[t][j];
        float e = __expf(dtv * Av);
        h = e * h + (dtv * xc_s[t][j]) * B_s[t][s];
        P *= e;
    }
    int o = (c * DI + d) * S + s;
    g_P[o] = P;
    g_hl[o] = h;
}

// ---------------- scan pass 2: sequential chunk combine ----------------------
__global__ void scan2_kernel() {
    int id = blockIdx.x * 256 + threadIdx.x;      // 0 .. 8191 = d*16+s
    float h = 0.f;
#pragma unroll 8
    for (int c = 0; c < NC; c++) {
        int o = c * DI * S + id;
        g_hin[o] = h;
        h = g_P[o] * h + g_hl[o];
    }
}

// ---------------- scan pass 3: final scan + gating, fp16 out -----------------
__global__ void scan3_kernel(const float* __restrict__ A_log,
                             const float* __restrict__ Dp) {
    __shared__ float dt_s[L][CHB];
    __shared__ float xc_s[L][CHB];
    __shared__ float B_s[L][S];
    __shared__ float C_s[L][S];
    __shared__ float y_s[L][CHB];
    const int c = blockIdx.x, dg = blockIdx.y;
    const int t0 = c * L, d0 = dg * CHB;
    const int tid = threadIdx.x;

    for (int idx = tid; idx < L * CHB; idx += 128) {
        int t = idx >> 3, j = idx & 7;
        dt_s[t][j] = g_dt[(t0 + t) * DI + d0 + j];
        xc_s[t][j] = g_xc[(t0 + t) * DI + d0 + j];
    }
    for (int idx = tid; idx < L * S; idx += 128) {
        int t = idx >> 4, s = idx & 15;
        B_s[t][s] = g_dbl[(t0 + t) * 48 + 16 + s];
        C_s[t][s] = g_dbl[(t0 + t) * 48 + 32 + s];
    }
    __syncthreads();

    const int w = tid >> 5, lane = tid & 31;
    const int j = w * 2 + (lane >> 4);
    const int s = lane & 15;
    const int d = d0 + j;
    const float Av = -__expf(A_log[d * S + s]);
    float h = g_hin[(c * DI + d) * S + s];
#pragma unroll 4
    for (int t = 0; t < L; t++) {
        float dtv = dt_s[t][j];
        float e = __expf(dtv * Av);
        h = e * h + (dtv * xc_s[t][j]) * B_s[t][s];
        float yv = h * C_s[t][s];
        yv += __shfl_xor_sync(0xffffffffu, yv, 8);
        yv += __shfl_xor_sync(0xffffffffu, yv, 4);
        yv += __shfl_xor_sync(0xffffffffu, yv, 2);
        yv += __shfl_xor_sync(0xffffffffu, yv, 1);
        if (s == 0) y_s[t][j] = yv;
    }
    __syncthreads();

    // fused epilogue: y2 = (y + Dp*xc) * silu(z) -> fp16
    for (int idx = tid; idx < L * CHB; idx += 128) {
        int t = idx >> 3, jj = idx & 7;
        int dd = d0 + jj, tt = t0 + t;
        float z = g_xz[tt * 1024 + DI + dd];
        float sig = 1.f / (1.f + __expf(-z));
        float v = (y_s[t][jj] + Dp[dd] * xc_s[t][jj]) * (z * sig);
        g_y22[tt * DI + dd] = __float2half(v);
    }
}

// ---------------------------------------------------------------------------
extern "C" void kernel_launch(void* const* d_in, const int* in_sizes, int n_in,
                              void* d_out, int out_size) {
    const float* input  = (const float*)d_in[0];
    const float* W_in   = (const float*)d_in[2];
    const float* conv_w = (const float*)d_in[3];
    const float* conv_b = (const float*)d_in[4];
    const float* W_x    = (const float*)d_in[5];
    const float* W_dt   = (const float*)d_in[6];
    const float* b_dt   = (const float*)d_in[7];
    const float* A_log  = (const float*)d_in[8];
    const float* Dp     = (const float*)d_in[9];
    const float* W_out  = (const float*)d_in[10];
    const float* W_lin  = (const float*)d_in[11];
    const float* b_lin  = (const float*)d_in[12];
    const float* ln1_g  = (const float*)d_in[13];
    const float* ln1_b  = (const float*)d_in[14];
    const float* W_exp  = (const float*)d_in[15];
    const float* b_exp  = (const float*)d_in[16];
    const float* W_sq   = (const float*)d_in[17];
    const float* b_sq   = (const float*)d_in[18];
    const float* ln2_g  = (const float*)d_in[19];
    const float* ln2_b  = (const float*)d_in[20];
    float* out = (float*)d_out;

    float *xz, *dbl, *h;
    h16 *in2, *xc2, *y22, *h2, *ff12, *Win2, *Wx2, *Wexp2, *Wsq2, *Wc2, *Wlin2, *WoutT;
    cudaGetSymbolAddress((void**)&xz,   g_xz);
    cudaGetSymbolAddress((void**)&dbl,  g_dbl);
    cudaGetSymbolAddress((void**)&h,    g_h);
    cudaGetSymbolAddress((void**)&in2,  g_in2);
    cudaGetSymbolAddress((void**)&xc2,  g_xc2);
    cudaGetSymbolAddress((void**)&y22,  g_y22);
    cudaGetSymbolAddress((void**)&h2,   g_h2);
    cudaGetSymbolAddress((void**)&ff12, g_ff12);
    cudaGetSymbolAddress((void**)&Win2, g_Win2);
    cudaGetSymbolAddress((void**)&Wx2,  g_Wx2);
    cudaGetSymbolAddress((void**)&Wexp2,g_Wexp2);
    cudaGetSymbolAddress((void**)&Wsq2, g_Wsq2);
    cudaGetSymbolAddress((void**)&Wc2,  g_Wc2);
    cudaGetSymbolAddress((void**)&Wlin2,g_Wlin2);
    cudaGetSymbolAddress((void**)&WoutT,g_WoutT);

    const int SM_128_128 = 3 * (128 + 128) * 36 * 4;   // 110592
    const int SM_64_128  = 3 * (64 + 128) * 36 * 4;    // 82944
    const int SM_64_64   = 3 * (64 + 64) * 36 * 4;     // 55296
    const int SM_LN      = 3 * (64 + 256) * 36 * 4;    // 138240
    cudaFuncSetAttribute(gemm_f16<128,128,4,2,0>, cudaFuncAttributeMaxDynamicSharedMemorySize, SM_128_128);
    cudaFuncSetAttribute(gemm_f16<128,128,4,2,1>, cudaFuncAttributeMaxDynamicSharedMemorySize, SM_128_128);
    cudaFuncSetAttribute(gemm_f16<64,128,2,4,2>,  cudaFuncAttributeMaxDynamicSharedMemorySize, SM_64_128);
    cudaFuncSetAttribute(gemm_dt,                 cudaFuncAttributeMaxDynamicSharedMemorySize, SM_64_64);
    cudaFuncSetAttribute(gemm_ln,                 cudaFuncAttributeMaxDynamicSharedMemorySize, SM_LN);

    float* out_tail = (out_size >= 2 * T * DM) ? (out + (size_t)T * DM) : nullptr;

    // 1: merged prep (input + all weights)
    prep_kernel<<<2048, 256>>>(input, out_tail, W_in, W_x, W_exp, W_sq, W_lin, W_out);

    // 2 (G0): Wc = Wlin @ Wout  [256,512], K=256, fp16 out
    gemm_f16<64,128,2,4,2><<<dim3(4, 4), 256, SM_64_128>>>(
        Wlin2, WoutT, Wc2, 256, 512, 512, nullptr);

    // 3 (G1): xz = x @ W_in^T  [8192,1024], K=256
    gemm_f16<128,128,4,2,0><<<dim3(8, 64), 256, SM_128_128>>>(
        in2, Win2, xz, 256, 1024, 1024, nullptr);

    // 4: conv + silu -> xc fp32 + xc2 fp16 (register-carried)
    conv_silu_kernel<<<(T * DI / 8) / 256, 256>>>(conv_w, conv_b);

    // 5 (G2+dt): dbl = xc @ W_x^T, dt = softplus(dbl16 @ Wdt^T + b)
    gemm_dt<<<dim3(1, 128), 256, SM_64_64>>>(xc2, Wx2, 512, dbl, W_dt, b_dt);

    // 6-8: chunked selective scan + gating -> y22 fp16
    scan1_kernel<<<dim3(NC, DI / CHB), 128>>>(A_log);
    scan2_kernel<<<(DI * S) / 256, 256>>>();
    scan3_kernel<<<dim3(NC, DI / CHB), 128>>>(A_log, Dp);

    // 9 (G4+LN1): h = LN(y2 @ Wc^T + b_lin + input), h2 fp16
    gemm_ln<<<T / 64, 256, SM_LN>>>(
        y22, Wc2, 512, b_lin, input, ln1_g, ln1_b, h, h2);

    // 10 (G5): ff1 = relu(h @ W_exp^T + b_exp) -> ff12 fp16  [8192,512], K=256
    gemm_f16<128,128,4,2,1><<<dim3(4, 64), 256, SM_128_128>>>(
        h2, Wexp2, ff12, 256, 512, 512, b_exp);

    // 11 (G6+LN2): out = LN(ff1 @ W_sq^T + b_sq + h)
    gemm_ln<<<T / 64, 256, SM_LN>>>(
        ff12, Wsq2, 512, b_sq, h, ln2_g, ln2_b, out, nullptr);
}

// round 15
// speedup vs baseline: 1.1956x; 1.0230x over previous
#include <cuda_runtime.h>
#include <cuda_fp16.h>
#include <math.h>

#define T    8192
#define DM   256
#define DI   512
#define S    16
#define NC   64           // chunks
#define L    128          // T/NC
#define CHB  8            // channels per scan block

typedef __half h16;

// ---------------- scratch (static device memory; no allocs) ----------------
__device__ float g_xz  [T * 1024];
__device__ h16   g_in2 [T * DM];         // input fp16, K=256
__device__ h16   g_xc2 [T * DI];         // xc fp16 (conv+silu output)
__device__ float g_dbl [T * 48];
__device__ float g_dt  [T * DI];
__device__ h16   g_y22 [T * DI];         // gated y fp16, K=512
__device__ float g_h   [T * DM];
__device__ h16   g_h2  [T * DM];         // h fp16, K=256
__device__ h16   g_ff12[T * DI];         // relu(ff1) fp16, K=512
__device__ h16   g_Win2 [1024 * DM];     // weights fp16
__device__ h16   g_Wx2  [64 * DI];       // padded 48->64 rows
__device__ h16   g_Wc2  [DM * DI];
__device__ h16   g_Wexp2[DI * DM];
__device__ h16   g_Wsq2 [DM * DI];
__device__ h16   g_Wlin2[DM * DM];
__device__ h16   g_WoutT[DI * DM];       // Wout^T: [n][k]
__device__ float g_P   [NC * DI * S];
__device__ float g_hl  [NC * DI * S];
__device__ float g_hin [NC * DI * S];

__device__ __forceinline__ void ldsm4(unsigned& r0, unsigned& r1,
                                      unsigned& r2, unsigned& r3, unsigned addr) {
    asm volatile("ldmatrix.sync.aligned.m8n8.x4.shared.b16 {%0,%1,%2,%3}, [%4];"
                 : "=r"(r0), "=r"(r1), "=r"(r2), "=r"(r3) : "r"(addr));
}

__device__ __forceinline__ void cp16(unsigned saddr, const void* gaddr) {
    asm volatile("cp.async.ca.shared.global [%0], [%1], 16;"
                 :: "r"(saddr), "l"(gaddr));
}

#define MMA16816(acc, a0, a1, a2, a3, b0, b1)                                   \
    asm volatile(                                                               \
        "mma.sync.aligned.m16n8k16.row.col.f32.f16.f16.f32 "                    \
        "{%0,%1,%2,%3},{%4,%5,%6,%7},{%8,%9},{%0,%1,%2,%3};"                    \
        : "+f"(acc[0]), "+f"(acc[1]), "+f"(acc[2]), "+f"(acc[3])                \
        : "r"(a0), "r"(a1), "r"(a2), "r"(a3), "r"(b0), "r"(b1))

// ---------------- fp16 tensor-core GEMM (64-wide K chunks, 3-stage) ---------
// C[M,N] = A[M,K] * B[N,K]^T (+bias). K multiple of 64.
// MODE 0: fp32 out. MODE 1: relu->fp16 out. MODE 2: fp16 out (no relu).
template<int BM, int BN, int WM, int WN, int MODE>
__global__ __launch_bounds__(256, 2)
void gemm_f16(const h16* __restrict__ A, const h16* __restrict__ B,
              void* __restrict__ Cv, int K, int Nld, int Nlog,
              const float* __restrict__ bias) {
    constexpr int MT = BM / WM / 16;
    constexpr int NT = BN / WN / 8;
    constexpr int SAW = 36;                 // words per 64-h16 row (8 h16 pad)
    constexpr int STG = (BM + BN) * SAW;    // words per stage
    extern __shared__ unsigned sm[];        // 3 stages
    const unsigned smemU = (unsigned)__cvta_generic_to_shared(sm);

    const int tid = threadIdx.x;
    const int w = tid >> 5, lane = tid & 31;
    const int g = lane >> 2, t4 = lane & 3;
    const int wm = w % WM, wn = w / WM;
    const int bm = blockIdx.y * BM, bn = blockIdx.x * BN;
    const int m0 = wm * (BM / WM), n0 = wn * (BN / WN);

    const int rA = (lane & 7) + ((lane & 8) ? 8 : 0);
    const int cA = (lane & 16) ? 4 : 0;
    const int rB = (lane & 7) + ((lane & 16) ? 8 : 0);
    const int cB = (lane & 8) ? 4 : 0;
    const unsigned aAddr = smemU + (unsigned)(((m0 + rA) * SAW + cA) * 4);
    const unsigned bAddr = smemU + (unsigned)((BM * SAW + (n0 + rB) * SAW + cB) * 4);

    const int ldr = tid >> 3;
    const int lcw = (tid & 7) * 4;
    const int lce = (tid & 7) * 8;

    float acc[MT][NT][4];
#pragma unroll
    for (int mi = 0; mi < MT; mi++)
#pragma unroll
        for (int ni = 0; ni < NT; ni++)
#pragma unroll
            for (int q = 0; q < 4; q++) acc[mi][ni][q] = 0.f;

    const int nch = K >> 6;

    auto issue = [&](int ch, int st) {
        const unsigned base = smemU + (unsigned)(st * STG * 4);
        const int ke = ch * 64 + lce;
#pragma unroll
        for (int r = ldr; r < BM; r += 32)
            cp16(base + (unsigned)((r * SAW + lcw) * 4),
                 A + (size_t)(bm + r) * K + ke);
#pragma unroll
        for (int r = ldr; r < BN; r += 32)
            cp16(base + (unsigned)((BM * SAW + r * SAW + lcw) * 4),
                 B + (size_t)(bn + r) * K + ke);
        asm volatile("cp.async.commit_group;" ::: "memory");
    };

    issue(0, 0);
    issue(1, 1);

    int st = 0;
    for (int i = 0; i < nch; i++) {
        if (i + 1 < nch)
            asm volatile("cp.async.wait_group 1;" ::: "memory");
        else
            asm volatile("cp.async.wait_group 0;" ::: "memory");
        __syncthreads();
        if (i + 2 < nch) {
            int st2 = st + 2; if (st2 >= 3) st2 -= 3;
            issue(i + 2, st2);
        }
        const unsigned so = (unsigned)(st * STG * 4);
#pragma unroll
        for (int kt = 0; kt < 4; kt++) {
            unsigned af[MT][4];
#pragma unroll
            for (int mi = 0; mi < MT; mi++)
                ldsm4(af[mi][0], af[mi][1], af[mi][2], af[mi][3],
                      aAddr + so + (unsigned)(mi * 16 * SAW * 4 + kt * 32));
            unsigned bfr[NT][2];
#pragma unroll
            for (int p = 0; p < NT / 2; p++) {
                unsigned r0, r1, r2, r3;
                ldsm4(r0, r1, r2, r3,
                      bAddr + so + (unsigned)(p * 16 * SAW * 4 + kt * 32));
                bfr[2 * p][0] = r0; bfr[2 * p][1] = r1;
                bfr[2 * p + 1][0] = r2; bfr[2 * p + 1][1] = r3;
            }
#pragma unroll
            for (int mi = 0; mi < MT; mi++)
#pragma unroll
                for (int ni = 0; ni < NT; ni++)
                    MMA16816(acc[mi][ni], af[mi][0], af[mi][1], af[mi][2], af[mi][3],
                             bfr[ni][0], bfr[ni][1]);
        }
        if (++st >= 3) st = 0;
    }

    // epilogue
#pragma unroll
    for (int mi = 0; mi < MT; mi++) {
        int r0 = bm + m0 + mi * 16 + g;
        int r1 = r0 + 8;
#pragma unroll
        for (int ni = 0; ni < NT; ni++) {
            int c = bn + n0 + ni * 8 + 2 * t4;
            if (c >= Nlog) continue;
            float b0 = bias ? bias[c] : 0.f;
            float b1 = bias ? bias[c + 1] : 0.f;
            float v00 = acc[mi][ni][0] + b0, v01 = acc[mi][ni][1] + b1;
            float v10 = acc[mi][ni][2] + b0, v11 = acc[mi][ni][3] + b1;
            if (MODE == 0) {
                float* C = (float*)Cv;
                *reinterpret_cast<float2*>(C + (size_t)r0 * Nld + c) = make_float2(v00, v01);
                *reinterpret_cast<float2*>(C + (size_t)r1 * Nld + c) = make_float2(v10, v11);
            } else {
                h16* C2 = (h16*)Cv;
                if (MODE == 1) {
                    v00 = fmaxf(v00, 0.f); v01 = fmaxf(v01, 0.f);
                    v10 = fmaxf(v10, 0.f); v11 = fmaxf(v11, 0.f);
                }
                *reinterpret_cast<__half2*>(C2 + (size_t)r0 * Nld + c) =
                    __halves2half2(__float2half(v00), __float2half(v01));
                *reinterpret_cast<__half2*>(C2 + (size_t)r1 * Nld + c) =
                    __halves2half2(__float2half(v10), __float2half(v11));
            }
        }
    }
}

// ---------------- G2 + fused dt projection -----------------------------------
__global__ __launch_bounds__(256, 2)
void gemm_dt(const h16* __restrict__ A, const h16* __restrict__ B, int K,
             float* __restrict__ dblOut,
             const float* __restrict__ Wdt, const float* __restrict__ bdt) {
    constexpr int BM = 64, BN = 64, WM = 2;
    constexpr int MT = 2, NT = 2;
    constexpr int SAW = 36;
    constexpr int STG = (BM + BN) * SAW;
    extern __shared__ unsigned sm[];
    const unsigned smemU = (unsigned)__cvta_generic_to_shared(sm);

    const int tid = threadIdx.x;
    const int w = tid >> 5, lane = tid & 31;
    const int g = lane >> 2, t4 = lane & 3;
    const int wm = w % WM, wn = w / WM;
    const int bm = blockIdx.y * BM;
    const int m0 = wm * 32, n0 = wn * 16;

    const int rA = (lane & 7) + ((lane & 8) ? 8 : 0);
    const int cA = (lane & 16) ? 4 : 0;
    const int rB = (lane & 7) + ((lane & 16) ? 8 : 0);
    const int cB = (lane & 8) ? 4 : 0;
    const unsigned aAddr = smemU + (unsigned)(((m0 + rA) * SAW + cA) * 4);
    const unsigned bAddr = smemU + (unsigned)((BM * SAW + (n0 + rB) * SAW + cB) * 4);

    const int ldr = tid >> 3;
    const int lcw = (tid & 7) * 4;
    const int lce = (tid & 7) * 8;

    float acc[MT][NT][4];
#pragma unroll
    for (int mi = 0; mi < MT; mi++)
#pragma unroll
        for (int ni = 0; ni < NT; ni++)
#pragma unroll
            for (int q = 0; q < 4; q++) acc[mi][ni][q] = 0.f;

    const int nch = K >> 6;

    auto issue = [&](int ch, int st) {
        const unsigned base = smemU + (unsigned)(st * STG * 4);
        const int ke = ch * 64 + lce;
#pragma unroll
        for (int r = ldr; r < BM; r += 32)
            cp16(base + (unsigned)((r * SAW + lcw) * 4),
                 A + (size_t)(bm + r) * K + ke);
#pragma unroll
        for (int r = ldr; r < BN; r += 32)
            cp16(base + (unsigned)((BM * SAW + r * SAW + lcw) * 4),
                 B + (size_t)r * K + ke);
        asm volatile("cp.async.commit_group;" ::: "memory");
    };

    issue(0, 0);
    issue(1, 1);

    int st = 0;
    for (int i = 0; i < nch; i++) {
        if (i + 1 < nch)
            asm volatile("cp.async.wait_group 1;" ::: "memory");
        else
            asm volatile("cp.async.wait_group 0;" ::: "memory");
        __syncthreads();
        if (i + 2 < nch) {
            int st2 = st + 2; if (st2 >= 3) st2 -= 3;
            issue(i + 2, st2);
        }
        const unsigned so = (unsigned)(st * STG * 4);
#pragma unroll
        for (int kt = 0; kt < 4; kt++) {
            unsigned af[MT][4];
#pragma unroll
            for (int mi = 0; mi < MT; mi++)
                ldsm4(af[mi][0], af[mi][1], af[mi][2], af[mi][3],
                      aAddr + so + (unsigned)(mi * 16 * SAW * 4 + kt * 32));
            unsigned bfr[NT][2];
            {
                unsigned r0, r1, r2, r3;
                ldsm4(r0, r1, r2, r3,
                      bAddr + so + (unsigned)(kt * 32));
                bfr[0][0] = r0; bfr[0][1] = r1;
                bfr[1][0] = r2; bfr[1][1] = r3;
            }
#pragma unroll
            for (int mi = 0; mi < MT; mi++)
#pragma unroll
                for (int ni = 0; ni < NT; ni++)
                    MMA16816(acc[mi][ni], af[mi][0], af[mi][1], af[mi][2], af[mi][3],
                             bfr[ni][0], bfr[ni][1]);
        }
        if (++st >= 3) st = 0;
    }

    float* sdt = (float*)sm;                      // [64][17] floats
    __syncthreads();
#pragma unroll
    for (int mi = 0; mi < MT; mi++) {
        int lr0 = m0 + mi * 16 + g;
        int lr1 = lr0 + 8;
        int r0 = bm + lr0, r1 = bm + lr1;
#pragma unroll
        for (int ni = 0; ni < NT; ni++) {
            int c = n0 + ni * 8 + 2 * t4;
            if (c < 48) {
                *reinterpret_cast<float2*>(dblOut + (size_t)r0 * 48 + c) =
                    make_float2(acc[mi][ni][0], acc[mi][ni][1]);
                *reinterpret_cast<float2*>(dblOut + (size_t)r1 * 48 + c) =
                    make_float2(acc[mi][ni][2], acc[mi][ni][3]);
            }
            if (c < 16) {
                sdt[lr0 * 17 + c]     = acc[mi][ni][0];
                sdt[lr0 * 17 + c + 1] = acc[mi][ni][1];
                sdt[lr1 * 17 + c]     = acc[mi][ni][2];
                sdt[lr1 * 17 + c + 1] = acc[mi][ni][3];
            }
        }
    }
    __syncthreads();

#pragma unroll
    for (int half = 0; half < 2; half++) {
        int d = tid + half * 256;
        float wv[16];
#pragma unroll
        for (int k = 0; k < 16; k++) wv[k] = Wdt[d * 16 + k];
        float b = bdt[d];
#pragma unroll 4
        for (int r = 0; r < 64; r++) {
            float s = b;
#pragma unroll
            for (int k = 0; k < 16; k++) s += sdt[r * 17 + k] * wv[k];
            float v = fmaxf(s, 0.f) + __logf(1.f + __expf(-fabsf(s)));
            g_dt[(size_t)(bm + r) * 512 + d] = v;
        }
    }
}

// ---------------- GEMM with fused LayerNorm epilogue (2-stage, occ 2) --------
__global__ __launch_bounds__(256, 2)
void gemm_ln(const h16* __restrict__ A, const h16* __restrict__ B, int K,
             const float* __restrict__ bias, const float* __restrict__ res,
             const float* __restrict__ gam, const float* __restrict__ bet,
             float* __restrict__ out32, h16* __restrict__ out16) {
    constexpr int BM = 64, BN = 256, WM = 2;
    constexpr int MT = 2, NT = 8;
    constexpr int SAW = 36;
    constexpr int STG = (BM + BN) * SAW;
    extern __shared__ unsigned sm[];              // 2 stages
    const unsigned smemU = (unsigned)__cvta_generic_to_shared(sm);

    const int tid = threadIdx.x;
    const int w = tid >> 5, lane = tid & 31;
    const int g = lane >> 2, t4 = lane & 3;
    const int wm = w % WM, wn = w / WM;
    const int bm = blockIdx.x * BM;
    const int m0 = wm * 32, n0 = wn * 64;

    const int rA = (lane & 7) + ((lane & 8) ? 8 : 0);
    const int cA = (lane & 16) ? 4 : 0;
    const int rB = (lane & 7) + ((lane & 16) ? 8 : 0);
    const int cB = (lane & 8) ? 4 : 0;
    const unsigned aAddr = smemU + (unsigned)(((m0 + rA) * SAW + cA) * 4);
    const unsigned bAddr = smemU + (unsigned)((BM * SAW + (n0 + rB) * SAW + cB) * 4);

    const int ldr = tid >> 3;
    const int lcw = (tid & 7) * 4;
    const int lce = (tid & 7) * 8;

    float acc[MT][NT][4];
#pragma unroll
    for (int mi = 0; mi < MT; mi++)
#pragma unroll
        for (int ni = 0; ni < NT; ni++)
#pragma unroll
            for (int q = 0; q < 4; q++) acc[mi][ni][q] = 0.f;

    const int nch = K >> 6;

    auto issue = [&](int ch, int st) {
        const unsigned base = smemU + (unsigned)(st * STG * 4);
        const int ke = ch * 64 + lce;
#pragma unroll
        for (int r = ldr; r < BM; r += 32)
            cp16(base + (unsigned)((r * SAW + lcw) * 4),
                 A + (size_t)(bm + r) * K + ke);
#pragma unroll
        for (int r = ldr; r < BN; r += 32)
            cp16(base + (unsigned)((BM * SAW + r * SAW + lcw) * 4),
                 B + (size_t)r * K + ke);
        asm volatile("cp.async.commit_group;" ::: "memory");
    };

    issue(0, 0);

    for (int i = 0; i < nch; i++) {
        if (i + 1 < nch) {
            issue(i + 1, (i + 1) & 1);
            asm volatile("cp.async.wait_group 1;" ::: "memory");
        } else {
            asm volatile("cp.async.wait_group 0;" ::: "memory");
        }
        __syncthreads();
        const unsigned so = (unsigned)((i & 1) * STG * 4);
#pragma unroll
        for (int kt = 0; kt < 4; kt++) {
            unsigned af[MT][4];
#pragma unroll
            for (int mi = 0; mi < MT; mi++)
                ldsm4(af[mi][0], af[mi][1], af[mi][2], af[mi][3],
                      aAddr + so + (unsigned)(mi * 16 * SAW * 4 + kt * 32));
            unsigned bfr[NT][2];
#pragma unroll
            for (int p = 0; p < NT / 2; p++) {
                unsigned r0, r1, r2, r3;
                ldsm4(r0, r1, r2, r3,
                      bAddr + so + (unsigned)(p * 16 * SAW * 4 + kt * 32));
                bfr[2 * p][0] = r0; bfr[2 * p][1] = r1;
                bfr[2 * p + 1][0] = r2; bfr[2 * p + 1][1] = r3;
            }
#pragma unroll
            for (int mi = 0; mi < MT; mi++)
#pragma unroll
                for (int ni = 0; ni < NT; ni++)
                    MMA16816(acc[mi][ni], af[mi][0], af[mi][1], af[mi][2], af[mi][3],
                             bfr[ni][0], bfr[ni][1]);
        }
        __syncthreads();                           // buffer reuse guard (2-stage)
    }

    // --- fused LN epilogue ---
    float s1[MT][2], s2[MT][2];
#pragma unroll
    for (int mi = 0; mi < MT; mi++) {
        int r0 = bm + m0 + mi * 16 + g;
        int r1 = r0 + 8;
        s1[mi][0] = s1[mi][1] = s2[mi][0] = s2[mi][1] = 0.f;
#pragma unroll
        for (int ni = 0; ni < NT; ni++) {
            int c = n0 + ni * 8 + 2 * t4;
            float b0 = bias[c], b1 = bias[c + 1];
            float2 e0 = *reinterpret_cast<const float2*>(res + (size_t)r0 * DM + c);
            float2 e1 = *reinterpret_cast<const float2*>(res + (size_t)r1 * DM + c);
            acc[mi][ni][0] += b0 + e0.x;
            acc[mi][ni][1] += b1 + e0.y;
            acc[mi][ni][2] += b0 + e1.x;
            acc[mi][ni][3] += b1 + e1.y;
            s1[mi][0] += acc[mi][ni][0] + acc[mi][ni][1];
            s2[mi][0] += acc[mi][ni][0] * acc[mi][ni][0] + acc[mi][ni][1] * acc[mi][ni][1];
            s1[mi][1] += acc[mi][ni][2] + acc[mi][ni][3];
            s2[mi][1] += acc[mi][ni][2] * acc[mi][ni][2] + acc[mi][ni][3] * acc[mi][ni][3];
        }
    }
#pragma unroll
    for (int mi = 0; mi < MT; mi++)
#pragma unroll
        for (int q = 0; q < 2; q++) {
            s1[mi][q] += __shfl_xor_sync(0xffffffffu, s1[mi][q], 1);
            s1[mi][q] += __shfl_xor_sync(0xffffffffu, s1[mi][q], 2);
            s2[mi][q] += __shfl_xor_sync(0xffffffffu, s2[mi][q], 1);
            s2[mi][q] += __shfl_xor_sync(0xffffffffu, s2[mi][q], 2);
        }
    float* sred = (float*)sm;
    __syncthreads();
    if (t4 == 0) {
#pragma unroll
        for (int mi = 0; mi < MT; mi++) {
            int lr = m0 + mi * 16 + g;
            sred[(lr) * 8 + wn]           = s1[mi][0];
            sred[(lr) * 8 + 4 + wn]       = s2[mi][0];
            sred[(lr + 8) * 8 + wn]       = s1[mi][1];
            sred[(lr + 8) * 8 + 4 + wn]   = s2[mi][1];
        }
    }
    __syncthreads();
#pragma unroll
    for (int mi = 0; mi < MT; mi++) {
#pragma unroll
        for (int q = 0; q < 2; q++) {
            int lr = m0 + mi * 16 + g + q * 8;
            float t1 = sred[lr * 8 + 0] + sred[lr * 8 + 1] + sred[lr * 8 + 2] + sred[lr * 8 + 3];
            float t2 = sred[lr * 8 + 4] + sred[lr * 8 + 5] + sred[lr * 8 + 6] + sred[lr * 8 + 7];
            float m = t1 * (1.f / DM);
            float var = t2 * (1.f / DM) - m * m;
            float rstd = rsqrtf(var + 1e-5f);
            int row = bm + lr;
#pragma unroll
            for (int ni = 0; ni < NT; ni++) {
                int c = n0 + ni * 8 + 2 * t4;
                float v0 = (acc[mi][ni][q * 2 + 0] - m) * rstd * gam[c] + bet[c];
                float v1 = (acc[mi][ni][q * 2 + 1] - m) * rstd * gam[c + 1] + bet[c + 1];
                *reinterpret_cast<float2*>(out32 + (size_t)row * DM + c) = make_float2(v0, v1);
                if (out16)
                    *reinterpret_cast<__half2*>(out16 + (size_t)row * DM + c) =
                        __halves2half2(__float2half(v0), __float2half(v1));
            }
        }
    }
}

// ---------------- merged prep: input + all weight conversions ---------------
__global__ void prep_kernel(const float* __restrict__ X, float* __restrict__ tail,
                            const float* __restrict__ Win,
                            const float* __restrict__ Wx,
                            const float* __restrict__ Wexp,
                            const float* __restrict__ Wsq,
                            const float* __restrict__ Wlin,
                            const float* __restrict__ Wout) {
    const int N0 = T * DM;
    const int N1 = 1024 * 256, N2 = 64 * 512, N3 = 512 * 256,
              N4 = 256 * 512, N5 = 256 * 256, N6 = 512 * 256;
    const int TOT = N0 + N1 + N2 + N3 + N4 + N5 + N6;
    for (int idx = blockIdx.x * 256 + threadIdx.x; idx < TOT; idx += gridDim.x * 256) {
        int j = idx;
        if (j < N0) {
            float v = X[j];
            g_in2[j] = __float2half(v);
            if (tail) tail[j] = v;
            continue;
        }
        j -= N0;
        if (j < N1) { g_Win2[j] = __float2half(Win[j]); continue; }
        j -= N1;
        if (j < N2) {
            int n = j >> 9, k = j & 511;
            g_Wx2[j] = __float2half((n < 48) ? Wx[n * 512 + k] : 0.f);
            continue;
        }
        j -= N2;
        if (j < N3) { g_Wexp2[j] = __float2half(Wexp[j]); continue; }
        j -= N3;
        if (j < N4) { g_Wsq2[j] = __float2half(Wsq[j]); continue; }
        j -= N4;
        if (j < N5) { g_Wlin2[j] = __float2half(Wlin[j]); continue; }
        j -= N5;
        {
            int n = j >> 8, k = j & 255;
            g_WoutT[j] = __float2half(Wout[k * 512 + n]);
        }
    }
}

// ---------------- depthwise causal conv1d (k=4) + SiLU (register-carried) ----
__global__ void conv_silu_kernel(const float* __restrict__ cw,
                                 const float* __restrict__ cb) {
    int idx = blockIdx.x * 256 + threadIdx.x;     // (t/8)*512 + d
    int d = idx & 511;
    int t0 = (idx >> 9) * 8;
    float w0 = cw[d * 4 + 0], w1 = cw[d * 4 + 1];
    float w2 = cw[d * 4 + 2], w3 = cw[d * 4 + 3];
    float b = cb[d];
    float xm3 = (t0 >= 3) ? g_xz[(t0 - 3) * 1024 + d] : 0.f;
    float xm2 = (t0 >= 2) ? g_xz[(t0 - 2) * 1024 + d] : 0.f;
    float xm1 = (t0 >= 1) ? g_xz[(t0 - 1) * 1024 + d] : 0.f;
#pragma unroll
    for (int q = 0; q < 8; q++) {
        int t = t0 + q;
        float x0 = g_xz[t * 1024 + d];
        float acc = b + w0 * xm3 + w1 * xm2 + w2 * xm1 + w3 * x0;
        xm3 = xm2; xm2 = xm1; xm1 = x0;
        float sig = 1.f / (1.f + __expf(-acc));
        g_xc2[t * 512 + d] = __float2half(acc * sig);
    }
}

// ---------------- scan pass 1 (xc from fp16) ---------------------------------
__global__ void scan1_kernel(const float* __restrict__ A_log) {
    __shared__ float dt_s[L][CHB];
    __shared__ float xc_s[L][CHB];
    __shared__ float B_s[L][S];
    const int c = blockIdx.x, dg = blockIdx.y;
    const int t0 = c * L, d0 = dg * CHB;
    const int tid = threadIdx.x;

    for (int idx = tid; idx < L * CHB; idx += 128) {
        int t = idx >> 3, j = idx & 7;
        dt_s[t][j] = g_dt[(t0 + t) * DI + d0 + j];
        xc_s[t][j] = __half2float(g_xc2[(t0 + t) * DI + d0 + j]);
    }
    for (int idx = tid; idx < L * S; idx += 128) {
        int t = idx >> 4, s = idx & 15;
        B_s[t][s] = g_dbl[(t0 + t) * 48 + 16 + s];
    }
    __syncthreads();

    const int w = tid >> 5, lane = tid & 31;
    const int j = w * 2 + (lane >> 4);
    const int s = lane & 15;
    const int d = d0 + j;
    const float Av = -__expf(A_log[d * S + s]);
    float h = 0.f, P = 1.f;
#pragma unroll 4
    for (int t = 0; t < L; t++) {
        float dtv = dt_s[t][j];
        float e = __expf(dtv * Av);
        h = e * h + (dtv * xc_s[t][j]) * B_s[t][s];
        P *= e;
    }
    int o = (c * DI + d) * S + s;
    g_P[o] = P;
    g_hl[o] = h;
}

// ---------------- scan pass 2: sequential chunk combine ----------------------
__global__ void scan2_kernel() {
    int id = blockIdx.x * 256 + threadIdx.x;      // 0 .. 8191 = d*16+s
    float h = 0.f;
#pragma unroll 8
    for (int c = 0; c < NC; c++) {
        int o = c * DI * S + id;
        g_hin[o] = h;
        h = g_P[o] * h + g_hl[o];
    }
}

// ---------------- scan pass 3: final scan + gating, fp16 out -----------------
__global__ void scan3_kernel(const float* __restrict__ A_log,
                             const float* __restrict__ Dp) {
    __shared__ float dt_s[L][CHB];
    __shared__ float xc_s[L][CHB];
    __shared__ float B_s[L][S];
    __shared__ float C_s[L][S];
    __shared__ float y_s[L][CHB];
    const int c = blockIdx.x, dg = blockIdx.y;
    const int t0 = c * L, d0 = dg * CHB;
    const int tid = threadIdx.x;

    for (int idx = tid; idx < L * CHB; idx += 128) {
        int t = idx >> 3, j = idx & 7;
        dt_s[t][j] = g_dt[(t0 + t) * DI + d0 + j];
        xc_s[t][j] = __half2float(g_xc2[(t0 + t) * DI + d0 + j]);
    }
    for (int idx = tid; idx < L * S; idx += 128) {
        int t = idx >> 4, s = idx & 15;
        B_s[t][s] = g_dbl[(t0 + t) * 48 + 16 + s];
        C_s[t][s] = g_dbl[(t0 + t) * 48 + 32 + s];
    }
    __syncthreads();

    const int w = tid >> 5, lane = tid & 31;
    const int j = w * 2 + (lane >> 4);
    const int s = lane & 15;
    const int d = d0 + j;
    const float Av = -__expf(A_log[d * S + s]);
    float h = g_hin[(c * DI + d) * S + s];
#pragma unroll 4
    for (int t = 0; t < L; t++) {
        float dtv = dt_s[t][j];
        float e = __expf(dtv * Av);
        h = e * h + (dtv * xc_s[t][j]) * B_s[t][s];
        float yv = h * C_s[t][s];
        yv += __shfl_xor_sync(0xffffffffu, yv, 8);
        yv += __shfl_xor_sync(0xffffffffu, yv, 4);
        yv += __shfl_xor_sync(0xffffffffu, yv, 2);
        yv += __shfl_xor_sync(0xffffffffu, yv, 1);
        if (s == 0) y_s[t][j] = yv;
    }
    __syncthreads();

    for (int idx = tid; idx < L * CHB; idx += 128) {
        int t = idx >> 3, jj = idx & 7;
        int dd = d0 + jj, tt = t0 + t;
        float z = g_xz[tt * 1024 + DI + dd];
        float sig = 1.f / (1.f + __expf(-z));
        float v = (y_s[t][jj] + Dp[dd] * xc_s[t][jj]) * (z * sig);
        g_y22[tt * DI + dd] = __float2half(v);
    }
}

// ---------------------------------------------------------------------------
extern "C" void kernel_launch(void* const* d_in, const int* in_sizes, int n_in,
                              void* d_out, int out_size) {
    const float* input  = (const float*)d_in[0];
    const float* W_in   = (const float*)d_in[2];
    const float* conv_w = (const float*)d_in[3];
    const float* conv_b = (const float*)d_in[4];
    const float* W_x    = (const float*)d_in[5];
    const float* W_dt   = (const float*)d_in[6];
    const float* b_dt   = (const float*)d_in[7];
    const float* A_log  = (const float*)d_in[8];
    const float* Dp     = (const float*)d_in[9];
    const float* W_out  = (const float*)d_in[10];
    const float* W_lin  = (const float*)d_in[11];
    const float* b_lin  = (const float*)d_in[12];
    const float* ln1_g  = (const float*)d_in[13];
    const float* ln1_b  = (const float*)d_in[14];
    const float* W_exp  = (const float*)d_in[15];
    const float* b_exp  = (const float*)d_in[16];
    const float* W_sq   = (const float*)d_in[17];
    const float* b_sq   = (const float*)d_in[18];
    const float* ln2_g  = (const float*)d_in[19];
    const float* ln2_b  = (const float*)d_in[20];
    float* out = (float*)d_out;

    float *xz, *dbl, *h;
    h16 *in2, *xc2, *y22, *h2, *ff12, *Win2, *Wx2, *Wexp2, *Wsq2, *Wc2, *Wlin2, *WoutT;
    cudaGetSymbolAddress((void**)&xz,   g_xz);
    cudaGetSymbolAddress((void**)&dbl,  g_dbl);
    cudaGetSymbolAddress((void**)&h,    g_h);
    cudaGetSymbolAddress((void**)&in2,  g_in2);
    cudaGetSymbolAddress((void**)&xc2,  g_xc2);
    cudaGetSymbolAddress((void**)&y22,  g_y22);
    cudaGetSymbolAddress((void**)&h2,   g_h2);
    cudaGetSymbolAddress((void**)&ff12, g_ff12);
    cudaGetSymbolAddress((void**)&Win2, g_Win2);
    cudaGetSymbolAddress((void**)&Wx2,  g_Wx2);
    cudaGetSymbolAddress((void**)&Wexp2,g_Wexp2);
    cudaGetSymbolAddress((void**)&Wsq2, g_Wsq2);
    cudaGetSymbolAddress((void**)&Wc2,  g_Wc2);
    cudaGetSymbolAddress((void**)&Wlin2,g_Wlin2);
    cudaGetSymbolAddress((void**)&WoutT,g_WoutT);

    const int SM_128_128 = 3 * (128 + 128) * 36 * 4;   // 110592
    const int SM_64_128  = 3 * (64 + 128) * 36 * 4;    // 82944
    const int SM_64_64   = 3 * (64 + 64) * 36 * 4;     // 55296
    const int SM_LN      = 2 * (64 + 256) * 36 * 4;    // 92160 (2-stage)
    cudaFuncSetAttribute(gemm_f16<128,128,4,2,0>, cudaFuncAttributeMaxDynamicSharedMemorySize, SM_128_128);
    cudaFuncSetAttribute(gemm_f16<128,128,4,2,1>, cudaFuncAttributeMaxDynamicSharedMemorySize, SM_128_128);
    cudaFuncSetAttribute(gemm_f16<64,128,2,4,2>,  cudaFuncAttributeMaxDynamicSharedMemorySize, SM_64_128);
    cudaFuncSetAttribute(gemm_dt,                 cudaFuncAttributeMaxDynamicSharedMemorySize, SM_64_64);
    cudaFuncSetAttribute(gemm_ln,                 cudaFuncAttributeMaxDynamicSharedMemorySize, SM_LN);

    float* out_tail = (out_size >= 2 * T * DM) ? (out + (size_t)T * DM) : nullptr;

    // 1: merged prep (input + all weights)
    prep_kernel<<<2048, 256>>>(input, out_tail, W_in, W_x, W_exp, W_sq, W_lin, W_out);

    // 2 (G0): Wc = Wlin @ Wout  [256,512], K=256, fp16 out
    gemm_f16<64,128,2,4,2><<<dim3(4, 4), 256, SM_64_128>>>(
        Wlin2, WoutT, Wc2, 256, 512, 512, nullptr);

    // 3 (G1): xz = x @ W_in^T  [8192,1024], K=256
    gemm_f16<128,128,4,2,0><<<dim3(8, 64), 256, SM_128_128>>>(
        in2, Win2, xz, 256, 1024, 1024, nullptr);

    // 4: conv + silu -> xc2 fp16 only
    conv_silu_kernel<<<(T * DI / 8) / 256, 256>>>(conv_w, conv_b);

    // 5 (G2+dt): dbl = xc @ W_x^T, dt = softplus(dbl16 @ Wdt^T + b)
    gemm_dt<<<dim3(1, 128), 256, SM_64_64>>>(xc2, Wx2, 512, dbl, W_dt, b_dt);

    // 6-8: chunked selective scan + gating -> y22 fp16
    scan1_kernel<<<dim3(NC, DI / CHB), 128>>>(A_log);
    scan2_kernel<<<(DI * S) / 256, 256>>>();
    scan3_kernel<<<dim3(NC, DI / CHB), 128>>>(A_log, Dp);

    // 9 (G4+LN1): h = LN(y2 @ Wc^T + b_lin + input), h2 fp16
    gemm_ln<<<T / 64, 256, SM_LN>>>(
        y22, Wc2, 512, b_lin, input, ln1_g, ln1_b, h, h2);

    // 10 (G5): ff1 = relu(h @ W_exp^T + b_exp) -> ff12 fp16  [8192,512], K=256
    gemm_f16<128,128,4,2,1><<<dim3(4, 64), 256, SM_128_128>>>(
        h2, Wexp2, ff12, 256, 512, 512, b_exp);

    // 11 (G6+LN2): out = LN(ff1 @ W_sq^T + b_sq + h)
    gemm_ln<<<T / 64, 256, SM_LN>>>(
        ff12, Wsq2, 512, b_sq, h, ln2_g, ln2_b, out, nullptr);
}

// round 16
// speedup vs baseline: 1.2051x; 1.0079x over previous
#include <cuda_runtime.h>
#include <cuda_fp16.h>
#include <math.h>

#define T    8192
#define DM   256
#define DI   512
#define S    16
#define NC   64           // chunks
#define L    128          // T/NC
#define CHB  8            // channels per scan block

typedef __half h16;

// ---------------- scratch (static device memory; no allocs) ----------------
__device__ h16   g_xz2 [T * 1024];       // in-proj output, fp16
__device__ h16   g_in2 [T * DM];         // input fp16, K=256
__device__ h16   g_xc2 [T * DI];         // xc fp16 (conv+silu output)
__device__ float g_dbl [T * 48];
__device__ float g_dt  [T * DI];
__device__ h16   g_y22 [T * DI];         // gated y fp16, K=512
__device__ float g_h   [T * DM];
__device__ h16   g_h2  [T * DM];         // h fp16, K=256
__device__ h16   g_ff12[T * DI];         // relu(ff1) fp16, K=512
__device__ h16   g_Win2 [1024 * DM];     // weights fp16
__device__ h16   g_Wx2  [64 * DI];       // padded 48->64 rows
__device__ h16   g_Wc2  [DM * DI];
__device__ h16   g_Wexp2[DI * DM];
__device__ h16   g_Wsq2 [DM * DI];
__device__ h16   g_Wlin2[DM * DM];
__device__ h16   g_WoutT[DI * DM];       // Wout^T: [n][k]
__device__ float g_P   [NC * DI * S];
__device__ float g_hl  [NC * DI * S];
__device__ float g_hin [NC * DI * S];

__device__ __forceinline__ void ldsm4(unsigned& r0, unsigned& r1,
                                      unsigned& r2, unsigned& r3, unsigned addr) {
    asm volatile("ldmatrix.sync.aligned.m8n8.x4.shared.b16 {%0,%1,%2,%3}, [%4];"
                 : "=r"(r0), "=r"(r1), "=r"(r2), "=r"(r3) : "r"(addr));
}

__device__ __forceinline__ void cp16(unsigned saddr, const void* gaddr) {
    asm volatile("cp.async.ca.shared.global [%0], [%1], 16;"
                 :: "r"(saddr), "l"(gaddr));
}

#define MMA16816(acc, a0, a1, a2, a3, b0, b1)                                   \
    asm volatile(                                                               \
        "mma.sync.aligned.m16n8k16.row.col.f32.f16.f16.f32 "                    \
        "{%0,%1,%2,%3},{%4,%5,%6,%7},{%8,%9},{%0,%1,%2,%3};"                    \
        : "+f"(acc[0]), "+f"(acc[1]), "+f"(acc[2]), "+f"(acc[3])                \
        : "r"(a0), "r"(a1), "r"(a2), "r"(a3), "r"(b0), "r"(b1))

// ---------------- fp16 tensor-core GEMM (64-wide K chunks, 3-stage) ---------
// C[M,N] = A[M,K] * B[N,K]^T (+bias). K multiple of 64.
// MODE 0: fp32 out. MODE 1: relu->fp16 out. MODE 2: fp16 out (no relu).
template<int BM, int BN, int WM, int WN, int MODE>
__global__ __launch_bounds__(256, 2)
void gemm_f16(const h16* __restrict__ A, const h16* __restrict__ B,
              void* __restrict__ Cv, int K, int Nld, int Nlog,
              const float* __restrict__ bias) {
    constexpr int MT = BM / WM / 16;
    constexpr int NT = BN / WN / 8;
    constexpr int SAW = 36;                 // words per 64-h16 row (8 h16 pad)
    constexpr int STG = (BM + BN) * SAW;    // words per stage
    extern __shared__ unsigned sm[];        // 3 stages
    const unsigned smemU = (unsigned)__cvta_generic_to_shared(sm);

    const int tid = threadIdx.x;
    const int w = tid >> 5, lane = tid & 31;
    const int g = lane >> 2, t4 = lane & 3;
    const int wm = w % WM, wn = w / WM;
    const int bm = blockIdx.y * BM, bn = blockIdx.x * BN;
    const int m0 = wm * (BM / WM), n0 = wn * (BN / WN);

    const int rA = (lane & 7) + ((lane & 8) ? 8 : 0);
    const int cA = (lane & 16) ? 4 : 0;
    const int rB = (lane & 7) + ((lane & 16) ? 8 : 0);
    const int cB = (lane & 8) ? 4 : 0;
    const unsigned aAddr = smemU + (unsigned)(((m0 + rA) * SAW + cA) * 4);
    const unsigned bAddr = smemU + (unsigned)((BM * SAW + (n0 + rB) * SAW + cB) * 4);

    const int ldr = tid >> 3;
    const int lcw = (tid & 7) * 4;
    const int lce = (tid & 7) * 8;

    float acc[MT][NT][4];
#pragma unroll
    for (int mi = 0; mi < MT; mi++)
#pragma unroll
        for (int ni = 0; ni < NT; ni++)
#pragma unroll
            for (int q = 0; q < 4; q++) acc[mi][ni][q] = 0.f;

    const int nch = K >> 6;

    auto issue = [&](int ch, int st) {
        const unsigned base = smemU + (unsigned)(st * STG * 4);
        const int ke = ch * 64 + lce;
#pragma unroll
        for (int r = ldr; r < BM; r += 32)
            cp16(base + (unsigned)((r * SAW + lcw) * 4),
                 A + (size_t)(bm + r) * K + ke);
#pragma unroll
        for (int r = ldr; r < BN; r += 32)
            cp16(base + (unsigned)((BM * SAW + r * SAW + lcw) * 4),
                 B + (size_t)(bn + r) * K + ke);
        asm volatile("cp.async.commit_group;" ::: "memory");
    };

    issue(0, 0);
    issue(1, 1);

    int st = 0;
    for (int i = 0; i < nch; i++) {
        if (i + 1 < nch)
            asm volatile("cp.async.wait_group 1;" ::: "memory");
        else
            asm volatile("cp.async.wait_group 0;" ::: "memory");
        __syncthreads();
        if (i + 2 < nch) {
            int st2 = st + 2; if (st2 >= 3) st2 -= 3;
            issue(i + 2, st2);
        }
        const unsigned so = (unsigned)(st * STG * 4);
#pragma unroll
        for (int kt = 0; kt < 4; kt++) {
            unsigned af[MT][4];
#pragma unroll
            for (int mi = 0; mi < MT; mi++)
                ldsm4(af[mi][0], af[mi][1], af[mi][2], af[mi][3],
                      aAddr + so + (unsigned)(mi * 16 * SAW * 4 + kt * 32));
            unsigned bfr[NT][2];
#pragma unroll
            for (int p = 0; p < NT / 2; p++) {
                unsigned r0, r1, r2, r3;
                ldsm4(r0, r1, r2, r3,
                      bAddr + so + (unsigned)(p * 16 * SAW * 4 + kt * 32));
                bfr[2 * p][0] = r0; bfr[2 * p][1] = r1;
                bfr[2 * p + 1][0] = r2; bfr[2 * p + 1][1] = r3;
            }
#pragma unroll
            for (int mi = 0; mi < MT; mi++)
#pragma unroll
                for (int ni = 0; ni < NT; ni++)
                    MMA16816(acc[mi][ni], af[mi][0], af[mi][1], af[mi][2], af[mi][3],
                             bfr[ni][0], bfr[ni][1]);
        }
        if (++st >= 3) st = 0;
    }

    // epilogue
#pragma unroll
    for (int mi = 0; mi < MT; mi++) {
        int r0 = bm + m0 + mi * 16 + g;
        int r1 = r0 + 8;
#pragma unroll
        for (int ni = 0; ni < NT; ni++) {
            int c = bn + n0 + ni * 8 + 2 * t4;
            if (c >= Nlog) continue;
            float b0 = bias ? bias[c] : 0.f;
            float b1 = bias ? bias[c + 1] : 0.f;
            float v00 = acc[mi][ni][0] + b0, v01 = acc[mi][ni][1] + b1;
            float v10 = acc[mi][ni][2] + b0, v11 = acc[mi][ni][3] + b1;
            if (MODE == 0) {
                float* C = (float*)Cv;
                *reinterpret_cast<float2*>(C + (size_t)r0 * Nld + c) = make_float2(v00, v01);
                *reinterpret_cast<float2*>(C + (size_t)r1 * Nld + c) = make_float2(v10, v11);
            } else {
                h16* C2 = (h16*)Cv;
                if (MODE == 1) {
                    v00 = fmaxf(v00, 0.f); v01 = fmaxf(v01, 0.f);
                    v10 = fmaxf(v10, 0.f); v11 = fmaxf(v11, 0.f);
                }
                *reinterpret_cast<__half2*>(C2 + (size_t)r0 * Nld + c) =
                    __halves2half2(__float2half(v00), __float2half(v01));
                *reinterpret_cast<__half2*>(C2 + (size_t)r1 * Nld + c) =
                    __halves2half2(__float2half(v10), __float2half(v11));
            }
        }
    }
}

// ---------------- G2 + fused dt projection -----------------------------------
__global__ __launch_bounds__(256, 2)
void gemm_dt(const h16* __restrict__ A, const h16* __restrict__ B, int K,
             float* __restrict__ dblOut,
             const float* __restrict__ Wdt, const float* __restrict__ bdt) {
    constexpr int BM = 64, BN = 64, WM = 2;
    constexpr int MT = 2, NT = 2;
    constexpr int SAW = 36;
    constexpr int STG = (BM + BN) * SAW;
    extern __shared__ unsigned sm[];
    const unsigned smemU = (unsigned)__cvta_generic_to_shared(sm);

    const int tid = threadIdx.x;
    const int w = tid >> 5, lane = tid & 31;
    const int g = lane >> 2, t4 = lane & 3;
    const int wm = w % WM, wn = w / WM;
    const int bm = blockIdx.y * BM;
    const int m0 = wm * 32, n0 = wn * 16;

    const int rA = (lane & 7) + ((lane & 8) ? 8 : 0);
    const int cA = (lane & 16) ? 4 : 0;
    const int rB = (lane & 7) + ((lane & 16) ? 8 : 0);
    const int cB = (lane & 8) ? 4 : 0;
    const unsigned aAddr = smemU + (unsigned)(((m0 + rA) * SAW + cA) * 4);
    const unsigned bAddr = smemU + (unsigned)((BM * SAW + (n0 + rB) * SAW + cB) * 4);

    const int ldr = tid >> 3;
    const int lcw = (tid & 7) * 4;
    const int lce = (tid & 7) * 8;

    float acc[MT][NT][4];
#pragma unroll
    for (int mi = 0; mi < MT; mi++)
#pragma unroll
        for (int ni = 0; ni < NT; ni++)
#pragma unroll
            for (int q = 0; q < 4; q++) acc[mi][ni][q] = 0.f;

    const int nch = K >> 6;

    auto issue = [&](int ch, int st) {
        const unsigned base = smemU + (unsigned)(st * STG * 4);
        const int ke = ch * 64 + lce;
#pragma unroll
        for (int r = ldr; r < BM; r += 32)
            cp16(base + (unsigned)((r * SAW + lcw) * 4),
                 A + (size_t)(bm + r) * K + ke);
#pragma unroll
        for (int r = ldr; r < BN; r += 32)
            cp16(base + (unsigned)((BM * SAW + r * SAW + lcw) * 4),
                 B + (size_t)r * K + ke);
        asm volatile("cp.async.commit_group;" ::: "memory");
    };

    issue(0, 0);
    issue(1, 1);

    int st = 0;
    for (int i = 0; i < nch; i++) {
        if (i + 1 < nch)
            asm volatile("cp.async.wait_group 1;" ::: "memory");
        else
            asm volatile("cp.async.wait_group 0;" ::: "memory");
        __syncthreads();
        if (i + 2 < nch) {
            int st2 = st + 2; if (st2 >= 3) st2 -= 3;
            issue(i + 2, st2);
        }
        const unsigned so = (unsigned)(st * STG * 4);
#pragma unroll
        for (int kt = 0; kt < 4; kt++) {
            unsigned af[MT][4];
#pragma unroll
            for (int mi = 0; mi < MT; mi++)
                ldsm4(af[mi][0], af[mi][1], af[mi][2], af[mi][3],
                      aAddr + so + (unsigned)(mi * 16 * SAW * 4 + kt * 32));
            unsigned bfr[NT][2];
            {
                unsigned r0, r1, r2, r3;
                ldsm4(r0, r1, r2, r3,
                      bAddr + so + (unsigned)(kt * 32));
                bfr[0][0] = r0; bfr[0][1] = r1;
                bfr[1][0] = r2; bfr[1][1] = r3;
            }
#pragma unroll
            for (int mi = 0; mi < MT; mi++)
#pragma unroll
                for (int ni = 0; ni < NT; ni++)
                    MMA16816(acc[mi][ni], af[mi][0], af[mi][1], af[mi][2], af[mi][3],
                             bfr[ni][0], bfr[ni][1]);
        }
        if (++st >= 3) st = 0;
    }

    float* sdt = (float*)sm;                      // [64][17] floats
    __syncthreads();
#pragma unroll
    for (int mi = 0; mi < MT; mi++) {
        int lr0 = m0 + mi * 16 + g;
        int lr1 = lr0 + 8;
        int r0 = bm + lr0, r1 = bm + lr1;
#pragma unroll
        for (int ni = 0; ni < NT; ni++) {
            int c = n0 + ni * 8 + 2 * t4;
            if (c < 48) {
                *reinterpret_cast<float2*>(dblOut + (size_t)r0 * 48 + c) =
                    make_float2(acc[mi][ni][0], acc[mi][ni][1]);
                *reinterpret_cast<float2*>(dblOut + (size_t)r1 * 48 + c) =
                    make_float2(acc[mi][ni][2], acc[mi][ni][3]);
            }
            if (c < 16) {
                sdt[lr0 * 17 + c]     = acc[mi][ni][0];
                sdt[lr0 * 17 + c + 1] = acc[mi][ni][1];
                sdt[lr1 * 17 + c]     = acc[mi][ni][2];
                sdt[lr1 * 17 + c + 1] = acc[mi][ni][3];
            }
        }
    }
    __syncthreads();

#pragma unroll
    for (int half = 0; half < 2; half++) {
        int d = tid + half * 256;
        float wv[16];
#pragma unroll
        for (int k = 0; k < 16; k++) wv[k] = Wdt[d * 16 + k];
        float b = bdt[d];
#pragma unroll 4
        for (int r = 0; r < 64; r++) {
            float s = b;
#pragma unroll
            for (int k = 0; k < 16; k++) s += sdt[r * 17 + k] * wv[k];
            float v = fmaxf(s, 0.f) + __logf(1.f + __expf(-fabsf(s)));
            g_dt[(size_t)(bm + r) * 512 + d] = v;
        }
    }
}

// ---------------- GEMM with fused LayerNorm epilogue (2-stage, occ 2) --------
__global__ __launch_bounds__(256, 2)
void gemm_ln(const h16* __restrict__ A, const h16* __restrict__ B, int K,
             const float* __restrict__ bias, const float* __restrict__ res,
             const float* __restrict__ gam, const float* __restrict__ bet,
             float* __restrict__ out32, h16* __restrict__ out16) {
    constexpr int BM = 64, BN = 256, WM = 2;
    constexpr int MT = 2, NT = 8;
    constexpr int SAW = 36;
    constexpr int STG = (BM + BN) * SAW;
    extern __shared__ unsigned sm[];              // 2 stages
    const unsigned smemU = (unsigned)__cvta_generic_to_shared(sm);

    const int tid = threadIdx.x;
    const int w = tid >> 5, lane = tid & 31;
    const int g = lane >> 2, t4 = lane & 3;
    const int wm = w % WM, wn = w / WM;
    const int bm = blockIdx.x * BM;
    const int m0 = wm * 32, n0 = wn * 64;

    const int rA = (lane & 7) + ((lane & 8) ? 8 : 0);
    const int cA = (lane & 16) ? 4 : 0;
    const int rB = (lane & 7) + ((lane & 16) ? 8 : 0);
    const int cB = (lane & 8) ? 4 : 0;
    const unsigned aAddr = smemU + (unsigned)(((m0 + rA) * SAW + cA) * 4);
    const unsigned bAddr = smemU + (unsigned)((BM * SAW + (n0 + rB) * SAW + cB) * 4);

    const int ldr = tid >> 3;
    const int lcw = (tid & 7) * 4;
    const int lce = (tid & 7) * 8;

    float acc[MT][NT][4];
#pragma unroll
    for (int mi = 0; mi < MT; mi++)
#pragma unroll
        for (int ni = 0; ni < NT; ni++)
#pragma unroll
            for (int q = 0; q < 4; q++) acc[mi][ni][q] = 0.f;

    const int nch = K >> 6;

    auto issue = [&](int ch, int st) {
        const unsigned base = smemU + (unsigned)(st * STG * 4);
        const int ke = ch * 64 + lce;
#pragma unroll
        for (int r = ldr; r < BM; r += 32)
            cp16(base + (unsigned)((r * SAW + lcw) * 4),
                 A + (size_t)(bm + r) * K + ke);
#pragma unroll
        for (int r = ldr; r < BN; r += 32)
            cp16(base + (unsigned)((BM * SAW + r * SAW + lcw) * 4),
                 B + (size_t)r * K + ke);
        asm volatile("cp.async.commit_group;" ::: "memory");
    };

    issue(0, 0);

    for (int i = 0; i < nch; i++) {
        if (i + 1 < nch) {
            issue(i + 1, (i + 1) & 1);
            asm volatile("cp.async.wait_group 1;" ::: "memory");
        } else {
            asm volatile("cp.async.wait_group 0;" ::: "memory");
        }
        __syncthreads();
        const unsigned so = (unsigned)((i & 1) * STG * 4);
#pragma unroll
        for (int kt = 0; kt < 4; kt++) {
            unsigned af[MT][4];
#pragma unroll
            for (int mi = 0; mi < MT; mi++)
                ldsm4(af[mi][0], af[mi][1], af[mi][2], af[mi][3],
                      aAddr + so + (unsigned)(mi * 16 * SAW * 4 + kt * 32));
            unsigned bfr[NT][2];
#pragma unroll
            for (int p = 0; p < NT / 2; p++) {
                unsigned r0, r1, r2, r3;
                ldsm4(r0, r1, r2, r3,
                      bAddr + so + (unsigned)(p * 16 * SAW * 4 + kt * 32));
                bfr[2 * p][0] = r0; bfr[2 * p][1] = r1;
                bfr[2 * p + 1][0] = r2; bfr[2 * p + 1][1] = r3;
            }
#pragma unroll
            for (int mi = 0; mi < MT; mi++)
#pragma unroll
                for (int ni = 0; ni < NT; ni++)
                    MMA16816(acc[mi][ni], af[mi][0], af[mi][1], af[mi][2], af[mi][3],
                             bfr[ni][0], bfr[ni][1]);
        }
        __syncthreads();                           // buffer reuse guard (2-stage)
    }

    // --- fused LN epilogue ---
    float s1[MT][2], s2[MT][2];
#pragma unroll
    for (int mi = 0; mi < MT; mi++) {
        int r0 = bm + m0 + mi * 16 + g;
        int r1 = r0 + 8;
        s1[mi][0] = s1[mi][1] = s2[mi][0] = s2[mi][1] = 0.f;
#pragma unroll
        for (int ni = 0; ni < NT; ni++) {
            int c = n0 + ni * 8 + 2 * t4;
            float b0 = bias[c], b1 = bias[c + 1];
            float2 e0 = *reinterpret_cast<const float2*>(res + (size_t)r0 * DM + c);
            float2 e1 = *reinterpret_cast<const float2*>(res + (size_t)r1 * DM + c);
            acc[mi][ni][0] += b0 + e0.x;
            acc[mi][ni][1] += b1 + e0.y;
            acc[mi][ni][2] += b0 + e1.x;
            acc[mi][ni][3] += b1 + e1.y;
            s1[mi][0] += acc[mi][ni][0] + acc[mi][ni][1];
            s2[mi][0] += acc[mi][ni][0] * acc[mi][ni][0] + acc[mi][ni][1] * acc[mi][ni][1];
            s1[mi][1] += acc[mi][ni][2] + acc[mi][ni][3];
            s2[mi][1] += acc[mi][ni][2] * acc[mi][ni][2] + acc[mi][ni][3] * acc[mi][ni][3];
        }
    }
#pragma unroll
    for (int mi = 0; mi < MT; mi++)
#pragma unroll
        for (int q = 0; q < 2; q++) {
            s1[mi][q] += __shfl_xor_sync(0xffffffffu, s1[mi][q], 1);
            s1[mi][q] += __shfl_xor_sync(0xffffffffu, s1[mi][q], 2);
            s2[mi][q] += __shfl_xor_sync(0xffffffffu, s2[mi][q], 1);
            s2[mi][q] += __shfl_xor_sync(0xffffffffu, s2[mi][q], 2);
        }
    float* sred = (float*)sm;
    __syncthreads();
    if (t4 == 0) {
#pragma unroll
        for (int mi = 0; mi < MT; mi++) {
            int lr = m0 + mi * 16 + g;
            sred[(lr) * 8 + wn]           = s1[mi][0];
            sred[(lr) * 8 + 4 + wn]       = s2[mi][0];
            sred[(lr + 8) * 8 + wn]       = s1[mi][1];
            sred[(lr + 8) * 8 + 4 + wn]   = s2[mi][1];
        }
    }
    __syncthreads();
#pragma unroll
    for (int mi = 0; mi < MT; mi++) {
#pragma unroll
        for (int q = 0; q < 2; q++) {
            int lr = m0 + mi * 16 + g + q * 8;
            float t1 = sred[lr * 8 + 0] + sred[lr * 8 + 1] + sred[lr * 8 + 2] + sred[lr * 8 + 3];
            float t2 = sred[lr * 8 + 4] + sred[lr * 8 + 5] + sred[lr * 8 + 6] + sred[lr * 8 + 7];
            float m = t1 * (1.f / DM);
            float var = t2 * (1.f / DM) - m * m;
            float rstd = rsqrtf(var + 1e-5f);
            int row = bm + lr;
#pragma unroll
            for (int ni = 0; ni < NT; ni++) {
                int c = n0 + ni * 8 + 2 * t4;
                float v0 = (acc[mi][ni][q * 2 + 0] - m) * rstd * gam[c] + bet[c];
                float v1 = (acc[mi][ni][q * 2 + 1] - m) * rstd * gam[c + 1] + bet[c + 1];
                *reinterpret_cast<float2*>(out32 + (size_t)row * DM + c) = make_float2(v0, v1);
                if (out16)
                    *reinterpret_cast<__half2*>(out16 + (size_t)row * DM + c) =
                        __halves2half2(__float2half(v0), __float2half(v1));
            }
        }
    }
}

// ---------------- merged prep: input + all weight conversions ---------------
__global__ void prep_kernel(const float* __restrict__ X, float* __restrict__ tail,
                            const float* __restrict__ Win,
                            const float* __restrict__ Wx,
                            const float* __restrict__ Wexp,
                            const float* __restrict__ Wsq,
                            const float* __restrict__ Wlin,
                            const float* __restrict__ Wout) {
    const int N0 = T * DM;
    const int N1 = 1024 * 256, N2 = 64 * 512, N3 = 512 * 256,
              N4 = 256 * 512, N5 = 256 * 256, N6 = 512 * 256;
    const int TOT = N0 + N1 + N2 + N3 + N4 + N5 + N6;
    for (int idx = blockIdx.x * 256 + threadIdx.x; idx < TOT; idx += gridDim.x * 256) {
        int j = idx;
        if (j < N0) {
            float v = X[j];
            g_in2[j] = __float2half(v);
            if (tail) tail[j] = v;
            continue;
        }
        j -= N0;
        if (j < N1) { g_Win2[j] = __float2half(Win[j]); continue; }
        j -= N1;
        if (j < N2) {
            int n = j >> 9, k = j & 511;
            g_Wx2[j] = __float2half((n < 48) ? Wx[n * 512 + k] : 0.f);
            continue;
        }
        j -= N2;
        if (j < N3) { g_Wexp2[j] = __float2half(Wexp[j]); continue; }
        j -= N3;
        if (j < N4) { g_Wsq2[j] = __float2half(Wsq[j]); continue; }
        j -= N4;
        if (j < N5) { g_Wlin2[j] = __float2half(Wlin[j]); continue; }
        j -= N5;
        {
            int n = j >> 8, k = j & 255;
            g_WoutT[j] = __float2half(Wout[k * 512 + n]);
        }
    }
}

// ---------------- depthwise causal conv1d (k=4) + SiLU (fp16 in/out) ---------
// Each thread: 2 adjacent d, 8 consecutive t; history carried in registers.
__global__ void conv_silu_kernel(const float* __restrict__ cw,
                                 const float* __restrict__ cb) {
    int idx = blockIdx.x * 256 + threadIdx.x;     // (t/8)*256 + d2
    int d = (idx & 255) * 2;
    int t0 = (idx >> 8) * 8;
    float w0a = cw[d * 4 + 0], w1a = cw[d * 4 + 1], w2a = cw[d * 4 + 2], w3a = cw[d * 4 + 3];
    float w0b = cw[d * 4 + 4], w1b = cw[d * 4 + 5], w2b = cw[d * 4 + 6], w3b = cw[d * 4 + 7];
    float ba = cb[d], bb = cb[d + 1];
    float2 xm3 = make_float2(0.f, 0.f), xm2 = xm3, xm1 = xm3;
    if (t0 >= 3) xm3 = __half22float2(*reinterpret_cast<const __half2*>(g_xz2 + (t0 - 3) * 1024 + d));
    if (t0 >= 2) xm2 = __half22float2(*reinterpret_cast<const __half2*>(g_xz2 + (t0 - 2) * 1024 + d));
    if (t0 >= 1) xm1 = __half22float2(*reinterpret_cast<const __half2*>(g_xz2 + (t0 - 1) * 1024 + d));
#pragma unroll
    for (int q = 0; q < 8; q++) {
        int t = t0 + q;
        float2 x0 = __half22float2(*reinterpret_cast<const __half2*>(g_xz2 + t * 1024 + d));
        float accA = ba + w0a * xm3.x + w1a * xm2.x + w2a * xm1.x + w3a * x0.x;
        float accB = bb + w0b * xm3.y + w1b * xm2.y + w2b * xm1.y + w3b * x0.y;
        xm3 = xm2; xm2 = xm1; xm1 = x0;
        float va = accA / (1.f + __expf(-accA));
        float vb = accB / (1.f + __expf(-accB));
        *reinterpret_cast<__half2*>(g_xc2 + t * 512 + d) =
            __halves2half2(__float2half(va), __float2half(vb));
    }
}

// ---------------- scan pass 1 (xc from fp16) ---------------------------------
__global__ void scan1_kernel(const float* __restrict__ A_log) {
    __shared__ float dt_s[L][CHB];
    __shared__ float xc_s[L][CHB];
    __shared__ float B_s[L][S];
    const int c = blockIdx.x, dg = blockIdx.y;
    const int t0 = c * L, d0 = dg * CHB;
    const int tid = threadIdx.x;

    for (int idx = tid; idx < L * CHB; idx += 128) {
        int t = idx >> 3, j = idx & 7;
        dt_s[t][j] = g_dt[(t0 + t) * DI + d0 + j];
        xc_s[t][j] = __half2float(g_xc2[(t0 + t) * DI + d0 + j]);
    }
    for (int idx = tid; idx < L * S; idx += 128) {
        int t = idx >> 4, s = idx & 15;
        B_s[t][s] = g_dbl[(t0 + t) * 48 + 16 + s];
    }
    __syncthreads();

    const int w = tid >> 5, lane = tid & 31;
    const int j = w * 2 + (lane >> 4);
    const int s = lane & 15;
    const int d = d0 + j;
    const float Av = -__expf(A_log[d * S + s]);
    float h = 0.f, P = 1.f;
#pragma unroll 4
    for (int t = 0; t < L; t++) {
        float dtv = dt_s[t][j];
        float e = __expf(dtv * Av);
        h = e * h + (dtv * xc_s[t][j]) * B_s[t][s];
        P *= e;
    }
    int o = (c * DI + d) * S + s;
    g_P[o] = P;
    g_hl[o] = h;
}

// ---------------- scan pass 2: sequential chunk combine ----------------------
__global__ void scan2_kernel() {
    int id = blockIdx.x * 256 + threadIdx.x;      // 0 .. 8191 = d*16+s
    float h = 0.f;
#pragma unroll 8
    for (int c = 0; c < NC; c++) {
        int o = c * DI * S + id;
        g_hin[o] = h;
        h = g_P[o] * h + g_hl[o];
    }
}

// ---------------- scan pass 3: final scan + gating, fp16 out -----------------
__global__ void scan3_kernel(const float* __restrict__ A_log,
                             const float* __restrict__ Dp) {
    __shared__ float dt_s[L][CHB];
    __shared__ float xc_s[L][CHB];
    __shared__ float B_s[L][S];
    __shared__ float C_s[L][S];
    __shared__ float y_s[L][CHB];
    const int c = blockIdx.x, dg = blockIdx.y;
    const int t0 = c * L, d0 = dg * CHB;
    const int tid = threadIdx.x;

    for (int idx = tid; idx < L * CHB; idx += 128) {
        int t = idx >> 3, j = idx & 7;
        dt_s[t][j] = g_dt[(t0 + t) * DI + d0 + j];
        xc_s[t][j] = __half2float(g_xc2[(t0 + t) * DI + d0 + j]);
    }
    for (int idx = tid; idx < L * S; idx += 128) {
        int t = idx >> 4, s = idx & 15;
        B_s[t][s] = g_dbl[(t0 + t) * 48 + 16 + s];
        C_s[t][s] = g_dbl[(t0 + t) * 48 + 32 + s];
    }
    __syncthreads();

    const int w = tid >> 5, lane = tid & 31;
    const int j = w * 2 + (lane >> 4);
    const int s = lane & 15;
    const int d = d0 + j;
    const float Av = -__expf(A_log[d * S + s]);
    float h = g_hin[(c * DI + d) * S + s];
#pragma unroll 4
    for (int t = 0; t < L; t++) {
        float dtv = dt_s[t][j];
        float e = __expf(dtv * Av);
        h = e * h + (dtv * xc_s[t][j]) * B_s[t][s];
        float yv = h * C_s[t][s];
        yv += __shfl_xor_sync(0xffffffffu, yv, 8);
        yv += __shfl_xor_sync(0xffffffffu, yv, 4);
        yv += __shfl_xor_sync(0xffffffffu, yv, 2);
        yv += __shfl_xor_sync(0xffffffffu, yv, 1);
        if (s == 0) y_s[t][j] = yv;
    }
    __syncthreads();

    for (int idx = tid; idx < L * CHB; idx += 128) {
        int t = idx >> 3, jj = idx & 7;
        int dd = d0 + jj, tt = t0 + t;
        float z = __half2float(g_xz2[tt * 1024 + DI + dd]);
        float sig = 1.f / (1.f + __expf(-z));
        float v = (y_s[t][jj] + Dp[dd] * xc_s[t][jj]) * (z * sig);
        g_y22[tt * DI + dd] = __float2half(v);
    }
}

// ---------------------------------------------------------------------------
extern "C" void kernel_launch(void* const* d_in, const int* in_sizes, int n_in,
                              void* d_out, int out_size) {
    const float* input  = (const float*)d_in[0];
    const float* W_in   = (const float*)d_in[2];
    const float* conv_w = (const float*)d_in[3];
    const float* conv_b = (const float*)d_in[4];
    const float* W_x    = (const float*)d_in[5];
    const float* W_dt   = (const float*)d_in[6];
    const float* b_dt   = (const float*)d_in[7];
    const float* A_log  = (const float*)d_in[8];
    const float* Dp     = (const float*)d_in[9];
    const float* W_out  = (const float*)d_in[10];
    const float* W_lin  = (const float*)d_in[11];
    const float* b_lin  = (const float*)d_in[12];
    const float* ln1_g  = (const float*)d_in[13];
    const float* ln1_b  = (const float*)d_in[14];
    const float* W_exp  = (const float*)d_in[15];
    const float* b_exp  = (const float*)d_in[16];
    const float* W_sq   = (const float*)d_in[17];
    const float* b_sq   = (const float*)d_in[18];
    const float* ln2_g  = (const float*)d_in[19];
    const float* ln2_b  = (const float*)d_in[20];
    float* out = (float*)d_out;

    float *dbl, *h;
    h16 *xz2, *in2, *xc2, *y22, *h2, *ff12, *Win2, *Wx2, *Wexp2, *Wsq2, *Wc2, *Wlin2, *WoutT;
    cudaGetSymbolAddress((void**)&xz2,  g_xz2);
    cudaGetSymbolAddress((void**)&dbl,  g_dbl);
    cudaGetSymbolAddress((void**)&h,    g_h);
    cudaGetSymbolAddress((void**)&in2,  g_in2);
    cudaGetSymbolAddress((void**)&xc2,  g_xc2);
    cudaGetSymbolAddress((void**)&y22,  g_y22);
    cudaGetSymbolAddress((void**)&h2,   g_h2);
    cudaGetSymbolAddress((void**)&ff12, g_ff12);
    cudaGetSymbolAddress((void**)&Win2, g_Win2);
    cudaGetSymbolAddress((void**)&Wx2,  g_Wx2);
    cudaGetSymbolAddress((void**)&Wexp2,g_Wexp2);
    cudaGetSymbolAddress((void**)&Wsq2, g_Wsq2);
    cudaGetSymbolAddress((void**)&Wc2,  g_Wc2);
    cudaGetSymbolAddress((void**)&Wlin2,g_Wlin2);
    cudaGetSymbolAddress((void**)&WoutT,g_WoutT);

    const int SM_128_128 = 3 * (128 + 128) * 36 * 4;   // 110592
    const int SM_64_128  = 3 * (64 + 128) * 36 * 4;    // 82944
    const int SM_64_64   = 3 * (64 + 64) * 36 * 4;     // 55296
    const int SM_LN      = 2 * (64 + 256) * 36 * 4;    // 92160 (2-stage)
    cudaFuncSetAttribute(gemm_f16<128,128,4,2,2>, cudaFuncAttributeMaxDynamicSharedMemorySize, SM_128_128);
    cudaFuncSetAttribute(gemm_f16<128,128,4,2,1>, cudaFuncAttributeMaxDynamicSharedMemorySize, SM_128_128);
    cudaFuncSetAttribute(gemm_f16<64,128,2,4,2>,  cudaFuncAttributeMaxDynamicSharedMemorySize, SM_64_128);
    cudaFuncSetAttribute(gemm_dt,                 cudaFuncAttributeMaxDynamicSharedMemorySize, SM_64_64);
    cudaFuncSetAttribute(gemm_ln,                 cudaFuncAttributeMaxDynamicSharedMemorySize, SM_LN);

    float* out_tail = (out_size >= 2 * T * DM) ? (out + (size_t)T * DM) : nullptr;

    // 1: merged prep (input + all weights)
    prep_kernel<<<2048, 256>>>(input, out_tail, W_in, W_x, W_exp, W_sq, W_lin, W_out);

    // 2 (G0): Wc = Wlin @ Wout  [256,512], K=256, fp16 out
    gemm_f16<64,128,2,4,2><<<dim3(4, 4), 256, SM_64_128>>>(
        Wlin2, WoutT, Wc2, 256, 512, 512, nullptr);

    // 3 (G1): xz = x @ W_in^T  [8192,1024], K=256, fp16 out
    gemm_f16<128,128,4,2,2><<<dim3(8, 64), 256, SM_128_128>>>(
        in2, Win2, xz2, 256, 1024, 1024, nullptr);

    // 4: conv + silu -> xc2 fp16 (fp16 in, 2 channels/thread)
    conv_silu_kernel<<<(T / 8) * 256 / 256, 256>>>(conv_w, conv_b);

    // 5 (G2+dt): dbl = xc @ W_x^T, dt = softplus(dbl16 @ Wdt^T + b)
    gemm_dt<<<dim3(1, 128), 256, SM_64_64>>>(xc2, Wx2, 512, dbl, W_dt, b_dt);

    // 6-8: chunked selective scan + gating -> y22 fp16
    scan1_kernel<<<dim3(NC, DI / CHB), 128>>>(A_log);
    scan2_kernel<<<(DI * S) / 256, 256>>>();
    scan3_kernel<<<dim3(NC, DI / CHB), 128>>>(A_log, Dp);

    // 9 (G4+LN1): h = LN(y2 @ Wc^T + b_lin + input), h2 fp16
    gemm_ln<<<T / 64, 256, SM_LN>>>(
        y22, Wc2, 512, b_lin, input, ln1_g, ln1_b, h, h2);

    // 10 (G5): ff1 = relu(h @ W_exp^T + b_exp) -> ff12 fp16  [8192,512], K=256
    gemm_f16<128,128,4,2,1><<<dim3(4, 64), 256, SM_128_128>>>(
        h2, Wexp2, ff12, 256, 512, 512, b_exp);

    // 11 (G6+LN2): out = LN(ff1 @ W_sq^T + b_sq + h)
    gemm_ln<<<T / 64, 256, SM_LN>>>(
        ff12, Wsq2, 512, b_sq, h, ln2_g, ln2_b, out, nullptr);
}

// round 17
// speedup vs baseline: 1.3092x; 1.0864x over previous
#include <cuda_runtime.h>
#include <cuda_fp16.h>
#include <math.h>

#define T    8192
#define DM   256
#define DI   512
#define S    16
#define NC   64           // chunks
#define L    128          // T/NC
#define CHB  8            // channels per scan block
#define DG   (DI / CHB)   // 64 channel groups

typedef __half h16;

// ---------------- scratch (static device memory; no allocs) ----------------
__device__ h16   g_xz2 [T * 1024];       // in-proj output, fp16
__device__ h16   g_in2 [T * DM];         // input fp16, K=256
__device__ h16   g_xc2 [T * DI];         // xc fp16 (conv+silu output)
__device__ float g_dbl [T * 48];
__device__ float g_dt  [T * DI];
__device__ h16   g_y22 [T * DI];         // gated y fp16, K=512
__device__ float g_h   [T * DM];
__device__ h16   g_h2  [T * DM];         // h fp16, K=256
__device__ h16   g_ff12[T * DI];         // relu(ff1) fp16, K=512
__device__ h16   g_Win2 [1024 * DM];     // weights fp16
__device__ h16   g_Wx2  [64 * DI];       // padded 48->64 rows
__device__ h16   g_Wc2  [DM * DI];
__device__ h16   g_Wexp2[DI * DM];
__device__ h16   g_Wsq2 [DM * DI];
__device__ h16   g_Wlin2[DM * DM];
__device__ h16   g_WoutT[DI * DM];       // Wout^T: [n][k]
__device__ float g_P   [NC * DI * S];
__device__ float g_hl  [NC * DI * S];
__device__ int   g_flag[NC * DG];        // lookback flags (cleared in prep)

__device__ __forceinline__ void ldsm4(unsigned& r0, unsigned& r1,
                                      unsigned& r2, unsigned& r3, unsigned addr) {
    asm volatile("ldmatrix.sync.aligned.m8n8.x4.shared.b16 {%0,%1,%2,%3}, [%4];"
                 : "=r"(r0), "=r"(r1), "=r"(r2), "=r"(r3) : "r"(addr));
}

__device__ __forceinline__ void cp16(unsigned saddr, const void* gaddr) {
    asm volatile("cp.async.ca.shared.global [%0], [%1], 16;"
                 :: "r"(saddr), "l"(gaddr));
}

#define MMA16816(acc, a0, a1, a2, a3, b0, b1)                                   \
    asm volatile(                                                               \
        "mma.sync.aligned.m16n8k16.row.col.f32.f16.f16.f32 "                    \
        "{%0,%1,%2,%3},{%4,%5,%6,%7},{%8,%9},{%0,%1,%2,%3};"                    \
        : "+f"(acc[0]), "+f"(acc[1]), "+f"(acc[2]), "+f"(acc[3])                \
        : "r"(a0), "r"(a1), "r"(a2), "r"(a3), "r"(b0), "r"(b1))

// ---------------- fp16 tensor-core GEMM (64-wide K chunks, 3-stage) ---------
// MODE 0: fp32 out. MODE 1: relu->fp16 out. MODE 2: fp16 out (no relu).
template<int BM, int BN, int WM, int WN, int MODE>
__global__ __launch_bounds__(256, 2)
void gemm_f16(const h16* __restrict__ A, const h16* __restrict__ B,
              void* __restrict__ Cv, int K, int Nld, int Nlog,
              const float* __restrict__ bias) {
    constexpr int MT = BM / WM / 16;
    constexpr int NT = BN / WN / 8;
    constexpr int SAW = 36;                 // words per 64-h16 row (8 h16 pad)
    constexpr int STG = (BM + BN) * SAW;    // words per stage
    extern __shared__ unsigned sm[];        // 3 stages
    const unsigned smemU = (unsigned)__cvta_generic_to_shared(sm);

    const int tid = threadIdx.x;
    const int w = tid >> 5, lane = tid & 31;
    const int g = lane >> 2, t4 = lane & 3;
    const int wm = w % WM, wn = w / WM;
    const int bm = blockIdx.y * BM, bn = blockIdx.x * BN;
    const int m0 = wm * (BM / WM), n0 = wn * (BN / WN);

    const int rA = (lane & 7) + ((lane & 8) ? 8 : 0);
    const int cA = (lane & 16) ? 4 : 0;
    const int rB = (lane & 7) + ((lane & 16) ? 8 : 0);
    const int cB = (lane & 8) ? 4 : 0;
    const unsigned aAddr = smemU + (unsigned)(((m0 + rA) * SAW + cA) * 4);
    const unsigned bAddr = smemU + (unsigned)((BM * SAW + (n0 + rB) * SAW + cB) * 4);

    const int ldr = tid >> 3;
    const int lcw = (tid & 7) * 4;
    const int lce = (tid & 7) * 8;

    float acc[MT][NT][4];
#pragma unroll
    for (int mi = 0; mi < MT; mi++)
#pragma unroll
        for (int ni = 0; ni < NT; ni++)
#pragma unroll
            for (int q = 0; q < 4; q++) acc[mi][ni][q] = 0.f;

    const int nch = K >> 6;

    auto issue = [&](int ch, int st) {
        const unsigned base = smemU + (unsigned)(st * STG * 4);
        const int ke = ch * 64 + lce;
#pragma unroll
        for (int r = ldr; r < BM; r += 32)
            cp16(base + (unsigned)((r * SAW + lcw) * 4),
                 A + (size_t)(bm + r) * K + ke);
#pragma unroll
        for (int r = ldr; r < BN; r += 32)
            cp16(base + (unsigned)((BM * SAW + r * SAW + lcw) * 4),
                 B + (size_t)(bn + r) * K + ke);
        asm volatile("cp.async.commit_group;" ::: "memory");
    };

    issue(0, 0);
    issue(1, 1);

    int st = 0;
    for (int i = 0; i < nch; i++) {
        if (i + 1 < nch)
            asm volatile("cp.async.wait_group 1;" ::: "memory");
        else
            asm volatile("cp.async.wait_group 0;" ::: "memory");
        __syncthreads();
        if (i + 2 < nch) {
            int st2 = st + 2; if (st2 >= 3) st2 -= 3;
            issue(i + 2, st2);
        }
        const unsigned so = (unsigned)(st * STG * 4);
#pragma unroll
        for (int kt = 0; kt < 4; kt++) {
            unsigned af[MT][4];
#pragma unroll
            for (int mi = 0; mi < MT; mi++)
                ldsm4(af[mi][0], af[mi][1], af[mi][2], af[mi][3],
                      aAddr + so + (unsigned)(mi * 16 * SAW * 4 + kt * 32));
            unsigned bfr[NT][2];
#pragma unroll
            for (int p = 0; p < NT / 2; p++) {
                unsigned r0, r1, r2, r3;
                ldsm4(r0, r1, r2, r3,
                      bAddr + so + (unsigned)(p * 16 * SAW * 4 + kt * 32));
                bfr[2 * p][0] = r0; bfr[2 * p][1] = r1;
                bfr[2 * p + 1][0] = r2; bfr[2 * p + 1][1] = r3;
            }
#pragma unroll
            for (int mi = 0; mi < MT; mi++)
#pragma unroll
                for (int ni = 0; ni < NT; ni++)
                    MMA16816(acc[mi][ni], af[mi][0], af[mi][1], af[mi][2], af[mi][3],
                             bfr[ni][0], bfr[ni][1]);
        }
        if (++st >= 3) st = 0;
    }

    // epilogue
#pragma unroll
    for (int mi = 0; mi < MT; mi++) {
        int r0 = bm + m0 + mi * 16 + g;
        int r1 = r0 + 8;
#pragma unroll
        for (int ni = 0; ni < NT; ni++) {
            int c = bn + n0 + ni * 8 + 2 * t4;
            if (c >= Nlog) continue;
            float b0 = bias ? bias[c] : 0.f;
            float b1 = bias ? bias[c + 1] : 0.f;
            float v00 = acc[mi][ni][0] + b0, v01 = acc[mi][ni][1] + b1;
            float v10 = acc[mi][ni][2] + b0, v11 = acc[mi][ni][3] + b1;
            if (MODE == 0) {
                float* C = (float*)Cv;
                *reinterpret_cast<float2*>(C + (size_t)r0 * Nld + c) = make_float2(v00, v01);
                *reinterpret_cast<float2*>(C + (size_t)r1 * Nld + c) = make_float2(v10, v11);
            } else {
                h16* C2 = (h16*)Cv;
                if (MODE == 1) {
                    v00 = fmaxf(v00, 0.f); v01 = fmaxf(v01, 0.f);
                    v10 = fmaxf(v10, 0.f); v11 = fmaxf(v11, 0.f);
                }
                *reinterpret_cast<__half2*>(C2 + (size_t)r0 * Nld + c) =
                    __halves2half2(__float2half(v00), __float2half(v01));
                *reinterpret_cast<__half2*>(C2 + (size_t)r1 * Nld + c) =
                    __halves2half2(__float2half(v10), __float2half(v11));
            }
        }
    }
}

// ---------------- G2 + fused dt projection -----------------------------------
__global__ __launch_bounds__(256, 2)
void gemm_dt(const h16* __restrict__ A, const h16* __restrict__ B, int K,
             float* __restrict__ dblOut,
             const float* __restrict__ Wdt, const float* __restrict__ bdt) {
    constexpr int BM = 64, BN = 64, WM = 2;
    constexpr int MT = 2, NT = 2;
    constexpr int SAW = 36;
    constexpr int STG = (BM + BN) * SAW;
    extern __shared__ unsigned sm[];
    const unsigned smemU = (unsigned)__cvta_generic_to_shared(sm);

    const int tid = threadIdx.x;
    const int w = tid >> 5, lane = tid & 31;
    const int g = lane >> 2, t4 = lane & 3;
    const int wm = w % WM, wn = w / WM;
    const int bm = blockIdx.y * BM;
    const int m0 = wm * 32, n0 = wn * 16;

    const int rA = (lane & 7) + ((lane & 8) ? 8 : 0);
    const int cA = (lane & 16) ? 4 : 0;
    const int rB = (lane & 7) + ((lane & 16) ? 8 : 0);
    const int cB = (lane & 8) ? 4 : 0;
    const unsigned aAddr = smemU + (unsigned)(((m0 + rA) * SAW + cA) * 4);
    const unsigned bAddr = smemU + (unsigned)((BM * SAW + (n0 + rB) * SAW + cB) * 4);

    const int ldr = tid >> 3;
    const int lcw = (tid & 7) * 4;
    const int lce = (tid & 7) * 8;

    float acc[MT][NT][4];
#pragma unroll
    for (int mi = 0; mi < MT; mi++)
#pragma unroll
        for (int ni = 0; ni < NT; ni++)
#pragma unroll
            for (int q = 0; q < 4; q++) acc[mi][ni][q] = 0.f;

    const int nch = K >> 6;

    auto issue = [&](int ch, int st) {
        const unsigned base = smemU + (unsigned)(st * STG * 4);
        const int ke = ch * 64 + lce;
#pragma unroll
        for (int r = ldr; r < BM; r += 32)
            cp16(base + (unsigned)((r * SAW + lcw) * 4),
                 A + (size_t)(bm + r) * K + ke);
#pragma unroll
        for (int r = ldr; r < BN; r += 32)
            cp16(base + (unsigned)((BM * SAW + r * SAW + lcw) * 4),
                 B + (size_t)r * K + ke);
        asm volatile("cp.async.commit_group;" ::: "memory");
    };

    issue(0, 0);
    issue(1, 1);

    int st = 0;
    for (int i = 0; i < nch; i++) {
        if (i + 1 < nch)
            asm volatile("cp.async.wait_group 1;" ::: "memory");
        else
            asm volatile("cp.async.wait_group 0;" ::: "memory");
        __syncthreads();
        if (i + 2 < nch) {
            int st2 = st + 2; if (st2 >= 3) st2 -= 3;
            issue(i + 2, st2);
        }
        const unsigned so = (unsigned)(st * STG * 4);
#pragma unroll
        for (int kt = 0; kt < 4; kt++) {
            unsigned af[MT][4];
#pragma unroll
            for (int mi = 0; mi < MT; mi++)
                ldsm4(af[mi][0], af[mi][1], af[mi][2], af[mi][3],
                      aAddr + so + (unsigned)(mi * 16 * SAW * 4 + kt * 32));
            unsigned bfr[NT][2];
            {
                unsigned r0, r1, r2, r3;
                ldsm4(r0, r1, r2, r3,
                      bAddr + so + (unsigned)(kt * 32));
                bfr[0][0] = r0; bfr[0][1] = r1;
                bfr[1][0] = r2; bfr[1][1] = r3;
            }
#pragma unroll
            for (int mi = 0; mi < MT; mi++)
#pragma unroll
                for (int ni = 0; ni < NT; ni++)
                    MMA16816(acc[mi][ni], af[mi][0], af[mi][1], af[mi][2], af[mi][3],
                             bfr[ni][0], bfr[ni][1]);
        }
        if (++st >= 3) st = 0;
    }

    float* sdt = (float*)sm;                      // [64][17] floats
    __syncthreads();
#pragma unroll
    for (int mi = 0; mi < MT; mi++) {
        int lr0 = m0 + mi * 16 + g;
        int lr1 = lr0 + 8;
        int r0 = bm + lr0, r1 = bm + lr1;
#pragma unroll
        for (int ni = 0; ni < NT; ni++) {
            int c = n0 + ni * 8 + 2 * t4;
            if (c < 48) {
                *reinterpret_cast<float2*>(dblOut + (size_t)r0 * 48 + c) =
                    make_float2(acc[mi][ni][0], acc[mi][ni][1]);
                *reinterpret_cast<float2*>(dblOut + (size_t)r1 * 48 + c) =
                    make_float2(acc[mi][ni][2], acc[mi][ni][3]);
            }
            if (c < 16) {
                sdt[lr0 * 17 + c]     = acc[mi][ni][0];
                sdt[lr0 * 17 + c + 1] = acc[mi][ni][1];
                sdt[lr1 * 17 + c]     = acc[mi][ni][2];
                sdt[lr1 * 17 + c + 1] = acc[mi][ni][3];
            }
        }
    }
    __syncthreads();

#pragma unroll
    for (int half = 0; half < 2; half++) {
        int d = tid + half * 256;
        float wv[16];
#pragma unroll
        for (int k = 0; k < 16; k++) wv[k] = Wdt[d * 16 + k];
        float b = bdt[d];
#pragma unroll 4
        for (int r = 0; r < 64; r++) {
            float s = b;
#pragma unroll
            for (int k = 0; k < 16; k++) s += sdt[r * 17 + k] * wv[k];
            float v = fmaxf(s, 0.f) + __logf(1.f + __expf(-fabsf(s)));
            g_dt[(size_t)(bm + r) * 512 + d] = v;
        }
    }
}

// ---------------- GEMM with fused LayerNorm epilogue (2-stage, occ 2) --------
__global__ __launch_bounds__(256, 2)
void gemm_ln(const h16* __restrict__ A, const h16* __restrict__ B, int K,
             const float* __restrict__ bias, const float* __restrict__ res,
             const float* __restrict__ gam, const float* __restrict__ bet,
             float* __restrict__ out32, h16* __restrict__ out16) {
    constexpr int BM = 64, BN = 256, WM = 2;
    constexpr int MT = 2, NT = 8;
    constexpr int SAW = 36;
    constexpr int STG = (BM + BN) * SAW;
    extern __shared__ unsigned sm[];              // 2 stages
    const unsigned smemU = (unsigned)__cvta_generic_to_shared(sm);

    const int tid = threadIdx.x;
    const int w = tid >> 5, lane = tid & 31;
    const int g = lane >> 2, t4 = lane & 3;
    const int wm = w % WM, wn = w / WM;
    const int bm = blockIdx.x * BM;
    const int m0 = wm * 32, n0 = wn * 64;

    const int rA = (lane & 7) + ((lane & 8) ? 8 : 0);
    const int cA = (lane & 16) ? 4 : 0;
    const int rB = (lane & 7) + ((lane & 16) ? 8 : 0);
    const int cB = (lane & 8) ? 4 : 0;
    const unsigned aAddr = smemU + (unsigned)(((m0 + rA) * SAW + cA) * 4);
    const unsigned bAddr = smemU + (unsigned)((BM * SAW + (n0 + rB) * SAW + cB) * 4);

    const int ldr = tid >> 3;
    const int lcw = (tid & 7) * 4;
    const int lce = (tid & 7) * 8;

    float acc[MT][NT][4];
#pragma unroll
    for (int mi = 0; mi < MT; mi++)
#pragma unroll
        for (int ni = 0; ni < NT; ni++)
#pragma unroll
            for (int q = 0; q < 4; q++) acc[mi][ni][q] = 0.f;

    const int nch = K >> 6;

    auto issue = [&](int ch, int st) {
        const unsigned base = smemU + (unsigned)(st * STG * 4);
        const int ke = ch * 64 + lce;
#pragma unroll
        for (int r = ldr; r < BM; r += 32)
            cp16(base + (unsigned)((r * SAW + lcw) * 4),
                 A + (size_t)(bm + r) * K + ke);
#pragma unroll
        for (int r = ldr; r < BN; r += 32)
            cp16(base + (unsigned)((BM * SAW + r * SAW + lcw) * 4),
                 B + (size_t)r * K + ke);
        asm volatile("cp.async.commit_group;" ::: "memory");
    };

    issue(0, 0);

    for (int i = 0; i < nch; i++) {
        if (i + 1 < nch) {
            issue(i + 1, (i + 1) & 1);
            asm volatile("cp.async.wait_group 1;" ::: "memory");
        } else {
            asm volatile("cp.async.wait_group 0;" ::: "memory");
        }
        __syncthreads();
        const unsigned so = (unsigned)((i & 1) * STG * 4);
#pragma unroll
        for (int kt = 0; kt < 4; kt++) {
            unsigned af[MT][4];
#pragma unroll
            for (int mi = 0; mi < MT; mi++)
                ldsm4(af[mi][0], af[mi][1], af[mi][2], af[mi][3],
                      aAddr + so + (unsigned)(mi * 16 * SAW * 4 + kt * 32));
            unsigned bfr[NT][2];
#pragma unroll
            for (int p = 0; p < NT / 2; p++) {
                unsigned r0, r1, r2, r3;
                ldsm4(r0, r1, r2, r3,
                      bAddr + so + (unsigned)(p * 16 * SAW * 4 + kt * 32));
                bfr[2 * p][0] = r0; bfr[2 * p][1] = r1;
                bfr[2 * p + 1][0] = r2; bfr[2 * p + 1][1] = r3;
            }
#pragma unroll
            for (int mi = 0; mi < MT; mi++)
#pragma unroll
                for (int ni = 0; ni < NT; ni++)
                    MMA16816(acc[mi][ni], af[mi][0], af[mi][1], af[mi][2], af[mi][3],
                             bfr[ni][0], bfr[ni][1]);
        }
        __syncthreads();                           // buffer reuse guard (2-stage)
    }

    // --- fused LN epilogue ---
    float s1[MT][2], s2[MT][2];
#pragma unroll
    for (int mi = 0; mi < MT; mi++) {
        int r0 = bm + m0 + mi * 16 + g;
        int r1 = r0 + 8;
        s1[mi][0] = s1[mi][1] = s2[mi][0] = s2[mi][1] = 0.f;
#pragma unroll
        for (int ni = 0; ni < NT; ni++) {
            int c = n0 + ni * 8 + 2 * t4;
            float b0 = bias[c], b1 = bias[c + 1];
            float2 e0 = *reinterpret_cast<const float2*>(res + (size_t)r0 * DM + c);
            float2 e1 = *reinterpret_cast<const float2*>(res + (size_t)r1 * DM + c);
            acc[mi][ni][0] += b0 + e0.x;
            acc[mi][ni][1] += b1 + e0.y;
            acc[mi][ni][2] += b0 + e1.x;
            acc[mi][ni][3] += b1 + e1.y;
            s1[mi][0] += acc[mi][ni][0] + acc[mi][ni][1];
            s2[mi][0] += acc[mi][ni][0] * acc[mi][ni][0] + acc[mi][ni][1] * acc[mi][ni][1];
            s1[mi][1] += acc[mi][ni][2] + acc[mi][ni][3];
            s2[mi][1] += acc[mi][ni][2] * acc[mi][ni][2] + acc[mi][ni][3] * acc[mi][ni][3];
        }
    }
#pragma unroll
    for (int mi = 0; mi < MT; mi++)
#pragma unroll
        for (int q = 0; q < 2; q++) {
            s1[mi][q] += __shfl_xor_sync(0xffffffffu, s1[mi][q], 1);
            s1[mi][q] += __shfl_xor_sync(0xffffffffu, s1[mi][q], 2);
            s2[mi][q] += __shfl_xor_sync(0xffffffffu, s2[mi][q], 1);
            s2[mi][q] += __shfl_xor_sync(0xffffffffu, s2[mi][q], 2);
        }
    float* sred = (float*)sm;
    __syncthreads();
    if (t4 == 0) {
#pragma unroll
        for (int mi = 0; mi < MT; mi++) {
            int lr = m0 + mi * 16 + g;
            sred[(lr) * 8 + wn]           = s1[mi][0];
            sred[(lr) * 8 + 4 + wn]       = s2[mi][0];
            sred[(lr + 8) * 8 + wn]       = s1[mi][1];
            sred[(lr + 8) * 8 + 4 + wn]   = s2[mi][1];
        }
    }
    __syncthreads();
#pragma unroll
    for (int mi = 0; mi < MT; mi++) {
#pragma unroll
        for (int q = 0; q < 2; q++) {
            int lr = m0 + mi * 16 + g + q * 8;
            float t1 = sred[lr * 8 + 0] + sred[lr * 8 + 1] + sred[lr * 8 + 2] + sred[lr * 8 + 3];
            float t2 = sred[lr * 8 + 4] + sred[lr * 8 + 5] + sred[lr * 8 + 6] + sred[lr * 8 + 7];
            float m = t1 * (1.f / DM);
            float var = t2 * (1.f / DM) - m * m;
            float rstd = rsqrtf(var + 1e-5f);
            int row = bm + lr;
#pragma unroll
            for (int ni = 0; ni < NT; ni++) {
                int c = n0 + ni * 8 + 2 * t4;
                float v0 = (acc[mi][ni][q * 2 + 0] - m) * rstd * gam[c] + bet[c];
                float v1 = (acc[mi][ni][q * 2 + 1] - m) * rstd * gam[c + 1] + bet[c + 1];
                *reinterpret_cast<float2*>(out32 + (size_t)row * DM + c) = make_float2(v0, v1);
                if (out16)
                    *reinterpret_cast<__half2*>(out16 + (size_t)row * DM + c) =
                        __halves2half2(__float2half(v0), __float2half(v1));
            }
        }
    }
}

// ---------------- merged prep: input + weights + flag clear ------------------
__global__ void prep_kernel(const float* __restrict__ X, float* __restrict__ tail,
                            const float* __restrict__ Win,
                            const float* __restrict__ Wx,
                            const float* __restrict__ Wexp,
                            const float* __restrict__ Wsq,
                            const float* __restrict__ Wlin,
                            const float* __restrict__ Wout) {
    const int NF = NC * DG;
    const int N0 = T * DM;
    const int N1 = 1024 * 256, N2 = 64 * 512, N3 = 512 * 256,
              N4 = 256 * 512, N5 = 256 * 256, N6 = 512 * 256;
    const int TOT = NF + N0 + N1 + N2 + N3 + N4 + N5 + N6;
    for (int idx = blockIdx.x * 256 + threadIdx.x; idx < TOT; idx += gridDim.x * 256) {
        int j = idx;
        if (j < NF) { g_flag[j] = 0; continue; }
        j -= NF;
        if (j < N0) {
            float v = X[j];
            g_in2[j] = __float2half(v);
            if (tail) tail[j] = v;
            continue;
        }
        j -= N0;
        if (j < N1) { g_Win2[j] = __float2half(Win[j]); continue; }
        j -= N1;
        if (j < N2) {
            int n = j >> 9, k = j & 511;
            g_Wx2[j] = __float2half((n < 48) ? Wx[n * 512 + k] : 0.f);
            continue;
        }
        j -= N2;
        if (j < N3) { g_Wexp2[j] = __float2half(Wexp[j]); continue; }
        j -= N3;
        if (j < N4) { g_Wsq2[j] = __float2half(Wsq[j]); continue; }
        j -= N4;
        if (j < N5) { g_Wlin2[j] = __float2half(Wlin[j]); continue; }
        j -= N5;
        {
            int n = j >> 8, k = j & 255;
            g_WoutT[j] = __float2half(Wout[k * 512 + n]);
        }
    }
}

// ---------------- depthwise causal conv1d (k=4) + SiLU (fp16, 4 t/thread) ----
__global__ void conv_silu_kernel(const float* __restrict__ cw,
                                 const float* __restrict__ cb) {
    int idx = blockIdx.x * 256 + threadIdx.x;     // (t/4)*256 + d2
    int d = (idx & 255) * 2;
    int t0 = (idx >> 8) * 4;
    float w0a = cw[d * 4 + 0], w1a = cw[d * 4 + 1], w2a = cw[d * 4 + 2], w3a = cw[d * 4 + 3];
    float w0b = cw[d * 4 + 4], w1b = cw[d * 4 + 5], w2b = cw[d * 4 + 6], w3b = cw[d * 4 + 7];
    float ba = cb[d], bb = cb[d + 1];
    float2 xm3 = make_float2(0.f, 0.f), xm2 = xm3, xm1 = xm3;
    if (t0 >= 3) xm3 = __half22float2(*reinterpret_cast<const __half2*>(g_xz2 + (t0 - 3) * 1024 + d));
    if (t0 >= 2) xm2 = __half22float2(*reinterpret_cast<const __half2*>(g_xz2 + (t0 - 2) * 1024 + d));
    if (t0 >= 1) xm1 = __half22float2(*reinterpret_cast<const __half2*>(g_xz2 + (t0 - 1) * 1024 + d));
#pragma unroll
    for (int q = 0; q < 4; q++) {
        int t = t0 + q;
        float2 x0 = __half22float2(*reinterpret_cast<const __half2*>(g_xz2 + t * 1024 + d));
        float accA = ba + w0a * xm3.x + w1a * xm2.x + w2a * xm1.x + w3a * x0.x;
        float accB = bb + w0b * xm3.y + w1b * xm2.y + w2b * xm1.y + w3b * x0.y;
        xm3 = xm2; xm2 = xm1; xm1 = x0;
        float va = accA / (1.f + __expf(-accA));
        float vb = accB / (1.f + __expf(-accB));
        *reinterpret_cast<__half2*>(g_xc2 + t * 512 + d) =
            __halves2half2(__float2half(va), __float2half(vb));
    }
}

// ---------------- single-pass selective scan (decoupled lookback) ------------
__global__ __launch_bounds__(128)
void scan_fused(const float* __restrict__ A_log, const float* __restrict__ Dp) {
    __shared__ float dt_s[L][CHB];
    __shared__ float xc_s[L][CHB];
    __shared__ float B_s[L][S];
    __shared__ float C_s[L][S];
    __shared__ float y_s[L][CHB];
    const int dg = blockIdx.x, c = blockIdx.y;
    const int t0 = c * L, d0 = dg * CHB;
    const int tid = threadIdx.x;

    for (int idx = tid; idx < L * CHB; idx += 128) {
        int t = idx >> 3, j = idx & 7;
        dt_s[t][j] = g_dt[(t0 + t) * DI + d0 + j];
        xc_s[t][j] = __half2float(g_xc2[(t0 + t) * DI + d0 + j]);
    }
    for (int idx = tid; idx < L * S; idx += 128) {
        int t = idx >> 4, s = idx & 15;
        B_s[t][s] = g_dbl[(t0 + t) * 48 + 16 + s];
        C_s[t][s] = g_dbl[(t0 + t) * 48 + 32 + s];
    }
    __syncthreads();

    const int w = tid >> 5, lane = tid & 31;
    const int j = w * 2 + (lane >> 4);
    const int s = lane & 15;
    const int d = d0 + j;
    const float Av = -__expf(A_log[d * S + s]);

    // pass A: local scan (h0 = 0) + decay product
    {
        float h = 0.f, P = 1.f;
#pragma unroll 4
        for (int t = 0; t < L; t++) {
            float dtv = dt_s[t][j];
            float e = __expf(dtv * Av);
            h = e * h + (dtv * xc_s[t][j]) * B_s[t][s];
            P *= e;
        }
        int o = (c * DI + d) * S + s;
        g_P[o] = P;
        g_hl[o] = h;
    }
    __threadfence();
    __syncthreads();
    if (tid == 0) atomicExch(&g_flag[c * DG + dg], 1);

    // wait for all predecessor chunks of this channel group
    float hin = 0.f;
    if (c > 0) {
        for (int cc = tid; cc < c; cc += 128)
            while (atomicAdd(&g_flag[cc * DG + dg], 0) == 0) {}
        __syncthreads();
        __threadfence();
        // fold: same ascending chain as the old scan2 (bit-identical)
        for (int cc = 0; cc < c; cc++) {
            int oo = (cc * DI + d) * S + s;
            hin = g_P[oo] * hin + g_hl[oo];
        }
    }

    // pass B: re-scan with correct h_in, compute y
    float h = hin;
#pragma unroll 4
    for (int t = 0; t < L; t++) {
        float dtv = dt_s[t][j];
        float e = __expf(dtv * Av);
        h = e * h + (dtv * xc_s[t][j]) * B_s[t][s];
        float yv = h * C_s[t][s];
        yv += __shfl_xor_sync(0xffffffffu, yv, 8);
        yv += __shfl_xor_sync(0xffffffffu, yv, 4);
        yv += __shfl_xor_sync(0xffffffffu, yv, 2);
        yv += __shfl_xor_sync(0xffffffffu, yv, 1);
        if (s == 0) y_s[t][j] = yv;
    }
    __syncthreads();

    // fused epilogue: y2 = (y + Dp*xc) * silu(z) -> fp16
    for (int idx = tid; idx < L * CHB; idx += 128) {
        int t = idx >> 3, jj = idx & 7;
        int dd = d0 + jj, tt = t0 + t;
        float z = __half2float(g_xz2[tt * 1024 + DI + dd]);
        float sig = 1.f / (1.f + __expf(-z));
        float v = (y_s[t][jj] + Dp[dd] * xc_s[t][jj]) * (z * sig);
        g_y22[tt * DI + dd] = __float2half(v);
    }
}

// ---------------------------------------------------------------------------
extern "C" void kernel_launch(void* const* d_in, const int* in_sizes, int n_in,
                              void* d_out, int out_size) {
    const float* input  = (const float*)d_in[0];
    const float* W_in   = (const float*)d_in[2];
    const float* conv_w = (const float*)d_in[3];
    const float* conv_b = (const float*)d_in[4];
    const float* W_x    = (const float*)d_in[5];
    const float* W_dt   = (const float*)d_in[6];
    const float* b_dt   = (const float*)d_in[7];
    const float* A_log  = (const float*)d_in[8];
    const float* Dp     = (const float*)d_in[9];
    const float* W_out  = (const float*)d_in[10];
    const float* W_lin  = (const float*)d_in[11];
    const float* b_lin  = (const float*)d_in[12];
    const float* ln1_g  = (const float*)d_in[13];
    const float* ln1_b  = (const float*)d_in[14];
    const float* W_exp  = (const float*)d_in[15];
    const float* b_exp  = (const float*)d_in[16];
    const float* W_sq   = (const float*)d_in[17];
    const float* b_sq   = (const float*)d_in[18];
    const float* ln2_g  = (const float*)d_in[19];
    const float* ln2_b  = (const float*)d_in[20];
    float* out = (float*)d_out;

    float *dbl, *h;
    h16 *xz2, *in2, *xc2, *y22, *h2, *ff12, *Win2, *Wx2, *Wexp2, *Wsq2, *Wc2, *Wlin2, *WoutT;
    cudaGetSymbolAddress((void**)&xz2,  g_xz2);
    cudaGetSymbolAddress((void**)&dbl,  g_dbl);
    cudaGetSymbolAddress((void**)&h,    g_h);
    cudaGetSymbolAddress((void**)&in2,  g_in2);
    cudaGetSymbolAddress((void**)&xc2,  g_xc2);
    cudaGetSymbolAddress((void**)&y22,  g_y22);
    cudaGetSymbolAddress((void**)&h2,   g_h2);
    cudaGetSymbolAddress((void**)&ff12, g_ff12);
    cudaGetSymbolAddress((void**)&Win2, g_Win2);
    cudaGetSymbolAddress((void**)&Wx2,  g_Wx2);
    cudaGetSymbolAddress((void**)&Wexp2,g_Wexp2);
    cudaGetSymbolAddress((void**)&Wsq2, g_Wsq2);
    cudaGetSymbolAddress((void**)&Wc2,  g_Wc2);
    cudaGetSymbolAddress((void**)&Wlin2,g_Wlin2);
    cudaGetSymbolAddress((void**)&WoutT,g_WoutT);

    const int SM_128_128 = 3 * (128 + 128) * 36 * 4;   // 110592
    const int SM_64_128  = 3 * (64 + 128) * 36 * 4;    // 82944
    const int SM_64_64   = 3 * (64 + 64) * 36 * 4;     // 55296
    const int SM_LN      = 2 * (64 + 256) * 36 * 4;    // 92160 (2-stage)
    cudaFuncSetAttribute(gemm_f16<128,128,4,2,2>, cudaFuncAttributeMaxDynamicSharedMemorySize, SM_128_128);
    cudaFuncSetAttribute(gemm_f16<128,128,4,2,1>, cudaFuncAttributeMaxDynamicSharedMemorySize, SM_128_128);
    cudaFuncSetAttribute(gemm_f16<64,128,2,4,2>,  cudaFuncAttributeMaxDynamicSharedMemorySize, SM_64_128);
    cudaFuncSetAttribute(gemm_dt,                 cudaFuncAttributeMaxDynamicSharedMemorySize, SM_64_64);
    cudaFuncSetAttribute(gemm_ln,                 cudaFuncAttributeMaxDynamicSharedMemorySize, SM_LN);

    float* out_tail = (out_size >= 2 * T * DM) ? (out + (size_t)T * DM) : nullptr;

    // 1: merged prep (flags + input + all weights)
    prep_kernel<<<2048, 256>>>(input, out_tail, W_in, W_x, W_exp, W_sq, W_lin, W_out);

    // 2 (G0): Wc = Wlin @ Wout  [256,512], K=256, fp16 out
    gemm_f16<64,128,2,4,2><<<dim3(4, 4), 256, SM_64_128>>>(
        Wlin2, WoutT, Wc2, 256, 512, 512, nullptr);

    // 3 (G1): xz = x @ W_in^T  [8192,1024], K=256, fp16 out
    gemm_f16<128,128,4,2,2><<<dim3(8, 64), 256, SM_128_128>>>(
        in2, Win2, xz2, 256, 1024, 1024, nullptr);

    // 4: conv + silu -> xc2 fp16 (4 t/thread)
    conv_silu_kernel<<<(T / 4) * 256 / 256, 256>>>(conv_w, conv_b);

    // 5 (G2+dt): dbl = xc @ W_x^T, dt = softplus(dbl16 @ Wdt^T + b)
    gemm_dt<<<dim3(1, 128), 256, SM_64_64>>>(xc2, Wx2, 512, dbl, W_dt, b_dt);

    // 6: single-pass selective scan + gating -> y22 fp16
    scan_fused<<<dim3(DG, NC), 128>>>(A_log, Dp);

    // 7 (G4+LN1): h = LN(y2 @ Wc^T + b_lin + input), h2 fp16
    gemm_ln<<<T / 64, 256, SM_LN>>>(
        y22, Wc2, 512, b_lin, input, ln1_g, ln1_b, h, h2);

    // 8 (G5): ff1 = relu(h @ W_exp^T + b_exp) -> ff12 fp16  [8192,512], K=256
    gemm_f16<128,128,4,2,1><<<dim3(4, 64), 256, SM_128_128>>>(
        h2, Wexp2, ff12, 256, 512, 512, b_exp);

    // 9 (G6+LN2): out = LN(ff1 @ W_sq^T + b_sq + h)
    gemm_ln<<<T / 64, 256, SM_LN>>>(
        ff12, Wsq2, 512, b_sq, h, ln2_g, ln2_b, out, nullptr);
}